// round 1
// baseline (speedup 1.0000x reference)
#include <cuda_runtime.h>
#include <cuda_bf16.h>
#include <math_constants.h>

// ---------------------------------------------------------------------------
// MultiHeadAttention: out = proj( causal_softmax( QK^T/sqrt(d) ) V ) with
// fused QKV GEMM. B=2, S=2048, H=16, D=64, E=1024.
//
// Pipeline:
//   1) g_qkv = x @ W_attn + b_attn            (4096 x 3072)   SGEMM
//   2) g_att = flash_attention(g_qkv)         (4096 x 1024)   fp32 flash
//   3) d_out = g_att @ W_proj + b_proj        (4096 x 1024)   SGEMM
// ---------------------------------------------------------------------------

#define S_LEN   2048
#define N_EMBD  1024
#define E3      3072
#define N_HEADS 16
#define HEAD_D  64
#define M_ROWS  4096   // B * S

__device__ float g_qkv[(size_t)M_ROWS * E3];     // 48 MB scratch
__device__ float g_att[(size_t)M_ROWS * N_EMBD]; // 16 MB scratch

// ---------------------------------------------------------------------------
// SGEMM: C = A(MxK) @ W(KxN) + bias.  BM=BN=128, BK=8, 256 threads, 8x8/thread
// ---------------------------------------------------------------------------
__global__ __launch_bounds__(256, 2)
void sgemm_bias(const float* __restrict__ A, const float* __restrict__ W,
                const float* __restrict__ bias, float* __restrict__ C,
                int M, int N, int K)
{
    const int BM = 128, BN = 128, BK = 8;
    __shared__ float As[BK][BM + 4];  // +4 pad: conflict-free transpose STS
    __shared__ float Bs[BK][BN];

    int t  = threadIdx.x;
    int tx = t & 15, ty = t >> 4;
    int row0 = blockIdx.y * BM, col0 = blockIdx.x * BN;

    int arow = t >> 1;          // 0..127
    int acol = (t & 1) * 4;     // 0 or 4
    int brow = t >> 5;          // 0..7
    int bcol = (t & 31) * 4;    // 0..124

    const float* Aptr = A + (size_t)(row0 + arow) * K + acol;
    const float* Wptr = W + (size_t)brow * N + col0 + bcol;

    float acc[8][8];
#pragma unroll
    for (int i = 0; i < 8; i++)
#pragma unroll
        for (int j = 0; j < 8; j++) acc[i][j] = 0.f;

    float4 pa = *(const float4*)Aptr;
    float4 pb = *(const float4*)Wptr;

    int nk = K / BK;
    for (int kb = 0; kb < nk; kb++) {
        As[acol + 0][arow] = pa.x;
        As[acol + 1][arow] = pa.y;
        As[acol + 2][arow] = pa.z;
        As[acol + 3][arow] = pa.w;
        *(float4*)&Bs[brow][bcol] = pb;
        __syncthreads();

        if (kb + 1 < nk) {
            pa = *(const float4*)(Aptr + (kb + 1) * BK);
            pb = *(const float4*)(Wptr + (size_t)(kb + 1) * BK * N);
        }

#pragma unroll
        for (int k = 0; k < BK; k++) {
            float a[8], b[8];
            *(float4*)&a[0] = *(const float4*)&As[k][ty * 8];
            *(float4*)&a[4] = *(const float4*)&As[k][ty * 8 + 4];
            *(float4*)&b[0] = *(const float4*)&Bs[k][tx * 8];
            *(float4*)&b[4] = *(const float4*)&Bs[k][tx * 8 + 4];
#pragma unroll
            for (int i = 0; i < 8; i++)
#pragma unroll
                for (int j = 0; j < 8; j++)
                    acc[i][j] += a[i] * b[j];
        }
        __syncthreads();
    }

    // epilogue: add bias, vectorized stores
#pragma unroll
    for (int i = 0; i < 8; i++) {
        int row = row0 + ty * 8 + i;
        float* cp = C + (size_t)row * N + col0 + tx * 8;
        const float* bp = bias + col0 + tx * 8;
        float4 r0, r1;
        r0.x = acc[i][0] + bp[0]; r0.y = acc[i][1] + bp[1];
        r0.z = acc[i][2] + bp[2]; r0.w = acc[i][3] + bp[3];
        r1.x = acc[i][4] + bp[4]; r1.y = acc[i][5] + bp[5];
        r1.z = acc[i][6] + bp[6]; r1.w = acc[i][7] + bp[7];
        *(float4*)cp       = r0;
        *(float4*)(cp + 4) = r1;
    }
}

// ---------------------------------------------------------------------------
// Flash attention, fp32, causal. 64x64 tiles, 256 threads, 4x4 micro-tiles.
// Q,K stored d-major (transposed) in SMEM -> score loop is a pure outer
// product with float4 loads over the row index (broadcast q, conflict-free k).
// P stored transposed so PV has identical access shape.
// Dynamic SMEM: 4 * 64*64 * 4B = 65536 B.
// ---------------------------------------------------------------------------
__global__ __launch_bounds__(256)
void flash_attn(const float* __restrict__ qkv, float* __restrict__ out)
{
    extern __shared__ float sm[];
    float* Qt = sm;            // Qt[d*64 + r]
    float* Kt = sm + 4096;     // Kt[d*64 + c]
    float* Vs = sm + 8192;     // Vs[c*64 + d]
    float* Pt = sm + 12288;    // Pt[c*64 + r]

    int qt = blockIdx.x;               // q tile, 0..31
    int bh = blockIdx.y;               // 0..31
    int b = bh >> 4, h = bh & 15;
    int t  = threadIdx.x;
    int tx = t & 15, ty = t >> 4;
    int r0 = ty * 4, c0 = tx * 4;
    int qbase = qt * 64;
    const float scale = 0.125f;        // 1/sqrt(64)

    // load Q tile transposed, pre-scaled
    {
        int r   = t >> 2;
        int seg = (t & 3) << 4;
        const float* src = qkv + (size_t)(b * S_LEN + qbase + r) * E3 + h * 64 + seg;
#pragma unroll
        for (int u = 0; u < 4; u++) {
            float4 f = *(const float4*)(src + u * 4);
            int d = seg + u * 4;
            Qt[(d + 0) * 64 + r] = f.x * scale;
            Qt[(d + 1) * 64 + r] = f.y * scale;
            Qt[(d + 2) * 64 + r] = f.z * scale;
            Qt[(d + 3) * 64 + r] = f.w * scale;
        }
    }

    float m_i[4], l_i[4], o[4][4];
#pragma unroll
    for (int i = 0; i < 4; i++) {
        m_i[i] = -CUDART_INF_F;
        l_i[i] = 0.f;
#pragma unroll
        for (int j = 0; j < 4; j++) o[i][j] = 0.f;
    }

    int ntiles = qt + 1;  // causal
    for (int kt = 0; kt < ntiles; kt++) {
        __syncthreads();  // previous PV done before overwriting Kt/Vs
        {
            int c   = t >> 2;
            int seg = (t & 3) << 4;
            const float* kp = qkv + (size_t)(b * S_LEN + kt * 64 + c) * E3
                              + 1024 + h * 64 + seg;
            const float* vp = kp + 1024;
#pragma unroll
            for (int u = 0; u < 4; u++) {
                int d = seg + u * 4;
                float4 f = *(const float4*)(kp + u * 4);
                Kt[(d + 0) * 64 + c] = f.x;
                Kt[(d + 1) * 64 + c] = f.y;
                Kt[(d + 2) * 64 + c] = f.z;
                Kt[(d + 3) * 64 + c] = f.w;
                *(float4*)&Vs[c * 64 + d] = *(const float4*)(vp + u * 4);
            }
        }
        __syncthreads();

        // ---- S = Q K^T (outer product over d) ----
        float s[4][4];
#pragma unroll
        for (int i = 0; i < 4; i++)
#pragma unroll
            for (int j = 0; j < 4; j++) s[i][j] = 0.f;

#pragma unroll 8
        for (int d = 0; d < 64; d++) {
            float q4[4], k4[4];
            *(float4*)q4 = *(const float4*)&Qt[d * 64 + r0];
            *(float4*)k4 = *(const float4*)&Kt[d * 64 + c0];
#pragma unroll
            for (int i = 0; i < 4; i++)
#pragma unroll
                for (int j = 0; j < 4; j++)
                    s[i][j] += q4[i] * k4[j];
        }

        // ---- causal mask on the diagonal tile ----
        if (kt == qt) {
#pragma unroll
            for (int i = 0; i < 4; i++)
#pragma unroll
                for (int j = 0; j < 4; j++)
                    if (c0 + j > r0 + i) s[i][j] = -CUDART_INF_F;
        }

        // ---- online softmax update ----
#pragma unroll
        for (int i = 0; i < 4; i++) {
            float mt = fmaxf(fmaxf(s[i][0], s[i][1]), fmaxf(s[i][2], s[i][3]));
            mt = fmaxf(mt, __shfl_xor_sync(0xffffffffu, mt, 8));
            mt = fmaxf(mt, __shfl_xor_sync(0xffffffffu, mt, 4));
            mt = fmaxf(mt, __shfl_xor_sync(0xffffffffu, mt, 2));
            mt = fmaxf(mt, __shfl_xor_sync(0xffffffffu, mt, 1));
            float mn    = fmaxf(m_i[i], mt);
            float alpha = __expf(m_i[i] - mn);
            m_i[i] = mn;
            float rs = 0.f;
#pragma unroll
            for (int j = 0; j < 4; j++) {
                float p = __expf(s[i][j] - mn);
                s[i][j] = p;
                rs += p;
            }
            rs += __shfl_xor_sync(0xffffffffu, rs, 8);
            rs += __shfl_xor_sync(0xffffffffu, rs, 4);
            rs += __shfl_xor_sync(0xffffffffu, rs, 2);
            rs += __shfl_xor_sync(0xffffffffu, rs, 1);
            l_i[i] = alpha * l_i[i] + rs;
#pragma unroll
            for (int j = 0; j < 4; j++) o[i][j] *= alpha;
        }

        // ---- write P transposed ----
#pragma unroll
        for (int j = 0; j < 4; j++)
#pragma unroll
            for (int i = 0; i < 4; i++)
                Pt[(c0 + j) * 64 + r0 + i] = s[i][j];
        __syncthreads();

        // ---- O += P V ----
#pragma unroll 8
        for (int c = 0; c < 64; c++) {
            float p4[4], v4[4];
            *(float4*)p4 = *(const float4*)&Pt[c * 64 + r0];
            *(float4*)v4 = *(const float4*)&Vs[c * 64 + c0];
#pragma unroll
            for (int i = 0; i < 4; i++)
#pragma unroll
                for (int j = 0; j < 4; j++)
                    o[i][j] += p4[i] * v4[j];
        }
    }

    // ---- normalize + write (b, s, h*64+d) ----
#pragma unroll
    for (int i = 0; i < 4; i++) {
        float inv = 1.f / l_i[i];
        float4 res;
        res.x = o[i][0] * inv;
        res.y = o[i][1] * inv;
        res.z = o[i][2] * inv;
        res.w = o[i][3] * inv;
        *(float4*)(out + (size_t)(b * S_LEN + qbase + r0 + i) * N_EMBD
                   + h * 64 + c0) = res;
    }
}

// ---------------------------------------------------------------------------
extern "C" void kernel_launch(void* const* d_in, const int* in_sizes, int n_in,
                              void* d_out, int out_size)
{
    const float* x      = (const float*)d_in[0];
    const float* W_attn = (const float*)d_in[1];
    const float* b_attn = (const float*)d_in[2];
    const float* W_proj = (const float*)d_in[3];
    const float* b_proj = (const float*)d_in[4];
    float* out = (float*)d_out;

    float *qkv, *att;
    cudaGetSymbolAddress((void**)&qkv, g_qkv);
    cudaGetSymbolAddress((void**)&att, g_att);

    // 64 KB dynamic SMEM opt-in for the flash kernel (idempotent, capture-safe)
    cudaFuncSetAttribute(flash_attn,
                         cudaFuncAttributeMaxDynamicSharedMemorySize, 65536);

    // 1) QKV projection: (4096 x 1024) @ (1024 x 3072) + bias
    dim3 g1(E3 / 128, M_ROWS / 128);
    sgemm_bias<<<g1, 256>>>(x, W_attn, b_attn, qkv, M_ROWS, E3, N_EMBD);

    // 2) causal flash attention
    dim3 g2(S_LEN / 64, 2 * N_HEADS);
    flash_attn<<<g2, 256, 65536>>>(qkv, att);

    // 3) output projection: (4096 x 1024) @ (1024 x 1024) + bias
    dim3 g3(N_EMBD / 128, M_ROWS / 128);
    sgemm_bias<<<g3, 256>>>(att, W_proj, b_proj, out, M_ROWS, N_EMBD, N_EMBD);
}

// round 3
// speedup vs baseline: 1.3653x; 1.3653x over previous
#include <cuda_runtime.h>
#include <cuda_bf16.h>
#include <math_constants.h>
#include <cstdint>

// ---------------------------------------------------------------------------
// MultiHeadAttention, B=2,S=2048,H=16,D=64,E=1024.
//   1) qkv = x @ W_attn + b_attn     mma.sync bf16x3 GEMM (4096x3072, K=1024)
//   2) att = flash(qkv)              fp32 flash
//   3) out = att @ W_proj + b_proj   mma.sync bf16x3 GEMM (4096x1024, K=1024)
// fp32 operands split hi/lo bf16; C = Ah*Bh + Ah*Bl + Al*Bh (fp32 accum).
// NOTE: tcgen05 is NOT available (harness builds compute_103, not 103a) —
// HMMA via mma.sync is the tensor path here.
// ---------------------------------------------------------------------------

#define S_LEN   2048
#define N_EMBD  1024
#define E3      3072
#define N_HEADS 16
#define M_ROWS  4096

__device__ float g_qkv[(size_t)M_ROWS * E3];
__device__ float g_att[(size_t)M_ROWS * N_EMBD];
__device__ __nv_bfloat16 g_xhi[(size_t)M_ROWS * N_EMBD];
__device__ __nv_bfloat16 g_xlo[(size_t)M_ROWS * N_EMBD];
__device__ __nv_bfloat16 g_ahi[(size_t)M_ROWS * N_EMBD];
__device__ __nv_bfloat16 g_alo[(size_t)M_ROWS * N_EMBD];
__device__ __nv_bfloat16 g_wahi[(size_t)E3 * N_EMBD];     // W_attn^T [3072][1024]
__device__ __nv_bfloat16 g_walo[(size_t)E3 * N_EMBD];
__device__ __nv_bfloat16 g_wphi[(size_t)N_EMBD * N_EMBD]; // W_proj^T [1024][1024]
__device__ __nv_bfloat16 g_wplo[(size_t)N_EMBD * N_EMBD];

// ------------------------- helpers ------------------------------------------
__device__ __forceinline__ uint32_t smem_u32(const void* p) {
    uint32_t a;
    asm("{ .reg .u64 t; cvta.to.shared.u64 t, %1; cvt.u32.u64 %0, t; }"
        : "=r"(a) : "l"(p));
    return a;
}
__device__ __forceinline__ void cp16(uint32_t dst, const void* src) {
    asm volatile("cp.async.cg.shared.global [%0], [%1], 16;" :: "r"(dst), "l"(src));
}
#define CP_COMMIT() asm volatile("cp.async.commit_group;" ::: "memory")
#define CP_WAIT1()  asm volatile("cp.async.wait_group 1;"  ::: "memory")

__device__ __forceinline__ void ldsm4(uint32_t* r, uint32_t addr) {
    asm volatile("ldmatrix.sync.aligned.m8n8.x4.shared.b16 {%0,%1,%2,%3}, [%4];"
                 : "=r"(r[0]), "=r"(r[1]), "=r"(r[2]), "=r"(r[3]) : "r"(addr));
}
__device__ __forceinline__ void mma16816(float* d, const uint32_t* a, const uint32_t* b) {
    asm volatile(
        "mma.sync.aligned.m16n8k16.row.col.f32.bf16.bf16.f32 "
        "{%0,%1,%2,%3}, {%4,%5,%6,%7}, {%8,%9}, {%0,%1,%2,%3};"
        : "+f"(d[0]), "+f"(d[1]), "+f"(d[2]), "+f"(d[3])
        : "r"(a[0]), "r"(a[1]), "r"(a[2]), "r"(a[3]), "r"(b[0]), "r"(b[1]));
}

// ---------------------------------------------------------------------------
// split fp32 -> bf16 hi/lo
// ---------------------------------------------------------------------------
__global__ void cvt_hilo(const float* __restrict__ in, __nv_bfloat16* __restrict__ hi,
                         __nv_bfloat16* __restrict__ lo, int n4)
{
    int i = blockIdx.x * blockDim.x + threadIdx.x;
    if (i >= n4) return;
    float4 v = ((const float4*)in)[i];
    __nv_bfloat16 h0 = __float2bfloat16(v.x), h1 = __float2bfloat16(v.y);
    __nv_bfloat16 h2 = __float2bfloat16(v.z), h3 = __float2bfloat16(v.w);
    ushort4 hv, lv;
    hv.x = __bfloat16_as_ushort(h0); hv.y = __bfloat16_as_ushort(h1);
    hv.z = __bfloat16_as_ushort(h2); hv.w = __bfloat16_as_ushort(h3);
    lv.x = __bfloat16_as_ushort(__float2bfloat16(v.x - __bfloat162float(h0)));
    lv.y = __bfloat16_as_ushort(__float2bfloat16(v.y - __bfloat162float(h1)));
    lv.z = __bfloat16_as_ushort(__float2bfloat16(v.z - __bfloat162float(h2)));
    lv.w = __bfloat16_as_ushort(__float2bfloat16(v.w - __bfloat162float(h3)));
    ((ushort4*)hi)[i] = hv;
    ((ushort4*)lo)[i] = lv;
}

// transpose W[K][N] -> T[N][K] with hi/lo split
__global__ void cvt_t_hilo(const float* __restrict__ W, __nv_bfloat16* __restrict__ Thi,
                           __nv_bfloat16* __restrict__ Tlo, int K, int N)
{
    __shared__ float tile[32][33];
    int k0 = blockIdx.y * 32, n0 = blockIdx.x * 32;
    int tx = threadIdx.x, ty = threadIdx.y;
#pragma unroll
    for (int i = ty; i < 32; i += 8)
        tile[i][tx] = W[(size_t)(k0 + i) * N + n0 + tx];
    __syncthreads();
#pragma unroll
    for (int i = ty; i < 32; i += 8) {
        float v = tile[tx][i];
        __nv_bfloat16 h = __float2bfloat16(v);
        __nv_bfloat16 l = __float2bfloat16(v - __bfloat162float(h));
        size_t o = (size_t)(n0 + i) * K + k0 + tx;
        Thi[o] = h; Tlo[o] = l;
    }
}

// ---------------------------------------------------------------------------
// HMMA bf16x3 GEMM: C[M,N] = A[M,K] @ B[N,K]^T + bias.
// CTA tile 128x128, BK=32 bf16, 8 warps (warp tile 64x32), 2-stage cp.async.
// SMEM per stage: 4 matrices (Ah,Al,Bh,Bl) x 128 rows x 80B (32 bf16 + pad).
// ---------------------------------------------------------------------------
#define ROWB     80            // padded row bytes (conflict-free ldmatrix)
#define MATB     (128 * ROWB)  // 10240
#define STAGEB   (4 * MATB)    // 40960
#define GSMEM    (2 * STAGEB)  // 81920

__global__ __launch_bounds__(256)
void gemm_mma(const __nv_bfloat16* __restrict__ Ahi, const __nv_bfloat16* __restrict__ Alo,
              const __nv_bfloat16* __restrict__ Bhi, const __nv_bfloat16* __restrict__ Blo,
              const float* __restrict__ bias, float* __restrict__ C,
              int M, int N, int K)
{
    extern __shared__ char smem[];
    uint32_t sb = smem_u32(smem);
    int t = threadIdx.x, wid = t >> 5, lid = t & 31;
    int m0 = blockIdx.y * 128, n0 = blockIdx.x * 128;
    int wm = wid & 1, wn = wid >> 1;

    const __nv_bfloat16* gp[4] = {
        Ahi + (size_t)m0 * K, Alo + (size_t)m0 * K,
        Bhi + (size_t)n0 * K, Blo + (size_t)n0 * K };

    const int chunk = t & 3;      // 16B chunk in row
    const int rbase = t >> 2;     // 0..63

    float acc[4][4][4];
#pragma unroll
    for (int i = 0; i < 4; i++)
#pragma unroll
        for (int j = 0; j < 4; j++)
#pragma unroll
            for (int v = 0; v < 4; v++) acc[i][j][v] = 0.f;

    int nkt = K / 32;

    // prologue load stage 0
    {
        uint32_t st = sb;
#pragma unroll
        for (int mat = 0; mat < 4; mat++)
#pragma unroll
            for (int h = 0; h < 2; h++) {
                int row = rbase + h * 64;
                cp16(st + mat * MATB + row * ROWB + chunk * 16,
                     gp[mat] + (size_t)row * K + chunk * 8);
            }
    }
    CP_COMMIT();

    for (int kt = 0; kt < nkt; kt++) {
        if (kt + 1 < nkt) {
            uint32_t st = sb + ((kt + 1) & 1) * STAGEB;
            int koff = (kt + 1) * 32;
#pragma unroll
            for (int mat = 0; mat < 4; mat++)
#pragma unroll
                for (int h = 0; h < 2; h++) {
                    int row = rbase + h * 64;
                    cp16(st + mat * MATB + row * ROWB + chunk * 16,
                         gp[mat] + (size_t)row * K + koff + chunk * 8);
                }
        }
        CP_COMMIT();
        CP_WAIT1();
        __syncthreads();

        uint32_t st = sb + (kt & 1) * STAGEB;
        uint32_t aRow = st + (wm * 64) * ROWB;            // Ah base for this warp
        uint32_t bRow = st + 2 * MATB + (wn * 32) * ROWB; // Bh base for this warp

#pragma unroll
        for (int k16 = 0; k16 < 2; k16++) {
            int kb = k16 * 32;  // byte offset of this k16 within the row
            uint32_t ah[4][4], al[4][4], bh[2][4], bl[2][4];
            // A fragments: 4 m16 tiles, hi & lo
            uint32_t aoff = (uint32_t)(lid & 15) * ROWB + kb + (lid >> 4) * 16;
#pragma unroll
            for (int mt = 0; mt < 4; mt++) {
                uint32_t ad = aRow + mt * 16 * ROWB + aoff;
                ldsm4(ah[mt], ad);
                ldsm4(al[mt], ad + MATB);
            }
            // B fragments: 2 pairs of n8 tiles, hi & lo
            uint32_t brow = ((lid >> 4) & 1) * 8 + (lid & 7);
            uint32_t boff = brow * ROWB + kb + ((lid >> 3) & 1) * 16;
#pragma unroll
            for (int p = 0; p < 2; p++) {
                uint32_t bd = bRow + p * 16 * ROWB + boff;
                ldsm4(bh[p], bd);
                ldsm4(bl[p], bd + MATB);
            }
#pragma unroll
            for (int mt = 0; mt < 4; mt++)
#pragma unroll
                for (int p = 0; p < 2; p++) {
                    mma16816(acc[mt][2 * p],     ah[mt], &bh[p][0]);
                    mma16816(acc[mt][2 * p + 1], ah[mt], &bh[p][2]);
                    mma16816(acc[mt][2 * p],     ah[mt], &bl[p][0]);
                    mma16816(acc[mt][2 * p + 1], ah[mt], &bl[p][2]);
                    mma16816(acc[mt][2 * p],     al[mt], &bh[p][0]);
                    mma16816(acc[mt][2 * p + 1], al[mt], &bh[p][2]);
                }
        }
        __syncthreads();
    }

    // epilogue: add bias, store. lane covers (row l/4 [+8], col 2*(l%4)+{0,1})
    int rA = m0 + wm * 64 + (lid >> 2);
    int cA = n0 + wn * 32 + 2 * (lid & 3);
#pragma unroll
    for (int mt = 0; mt < 4; mt++) {
        int r = rA + mt * 16;
#pragma unroll
        for (int nt = 0; nt < 4; nt++) {
            int c = cA + nt * 8;
            float b0 = bias[c], b1 = bias[c + 1];
            float2 v0 = { acc[mt][nt][0] + b0, acc[mt][nt][1] + b1 };
            float2 v1 = { acc[mt][nt][2] + b0, acc[mt][nt][3] + b1 };
            *(float2*)(C + (size_t)r * N + c)       = v0;
            *(float2*)(C + (size_t)(r + 8) * N + c) = v1;
        }
    }
}

// ---------------------------------------------------------------------------
// Flash attention, fp32, causal (unchanged).
// ---------------------------------------------------------------------------
__global__ __launch_bounds__(256)
void flash_attn(const float* __restrict__ qkv, float* __restrict__ out)
{
    extern __shared__ float sm[];
    float* Qt = sm;
    float* Kt = sm + 4096;
    float* Vs = sm + 8192;
    float* Pt = sm + 12288;

    int qt = blockIdx.x;
    int bh = blockIdx.y;
    int b = bh >> 4, h = bh & 15;
    int t  = threadIdx.x;
    int tx = t & 15, ty = t >> 4;
    int r0 = ty * 4, c0 = tx * 4;
    int qbase = qt * 64;
    const float scale = 0.125f;

    {
        int r   = t >> 2;
        int seg = (t & 3) << 4;
        const float* src = qkv + (size_t)(b * S_LEN + qbase + r) * E3 + h * 64 + seg;
#pragma unroll
        for (int u = 0; u < 4; u++) {
            float4 f = *(const float4*)(src + u * 4);
            int d = seg + u * 4;
            Qt[(d + 0) * 64 + r] = f.x * scale;
            Qt[(d + 1) * 64 + r] = f.y * scale;
            Qt[(d + 2) * 64 + r] = f.z * scale;
            Qt[(d + 3) * 64 + r] = f.w * scale;
        }
    }

    float m_i[4], l_i[4], o[4][4];
#pragma unroll
    for (int i = 0; i < 4; i++) {
        m_i[i] = -CUDART_INF_F;
        l_i[i] = 0.f;
#pragma unroll
        for (int j = 0; j < 4; j++) o[i][j] = 0.f;
    }

    int ntiles = qt + 1;
    for (int kt = 0; kt < ntiles; kt++) {
        __syncthreads();
        {
            int c   = t >> 2;
            int seg = (t & 3) << 4;
            const float* kp = qkv + (size_t)(b * S_LEN + kt * 64 + c) * E3
                              + 1024 + h * 64 + seg;
            const float* vp = kp + 1024;
#pragma unroll
            for (int u = 0; u < 4; u++) {
                int d = seg + u * 4;
                float4 f = *(const float4*)(kp + u * 4);
                Kt[(d + 0) * 64 + c] = f.x;
                Kt[(d + 1) * 64 + c] = f.y;
                Kt[(d + 2) * 64 + c] = f.z;
                Kt[(d + 3) * 64 + c] = f.w;
                *(float4*)&Vs[c * 64 + d] = *(const float4*)(vp + u * 4);
            }
        }
        __syncthreads();

        float s[4][4];
#pragma unroll
        for (int i = 0; i < 4; i++)
#pragma unroll
            for (int j = 0; j < 4; j++) s[i][j] = 0.f;

#pragma unroll 8
        for (int d = 0; d < 64; d++) {
            float q4[4], k4[4];
            *(float4*)q4 = *(const float4*)&Qt[d * 64 + r0];
            *(float4*)k4 = *(const float4*)&Kt[d * 64 + c0];
#pragma unroll
            for (int i = 0; i < 4; i++)
#pragma unroll
                for (int j = 0; j < 4; j++)
                    s[i][j] += q4[i] * k4[j];
        }

        if (kt == qt) {
#pragma unroll
            for (int i = 0; i < 4; i++)
#pragma unroll
                for (int j = 0; j < 4; j++)
                    if (c0 + j > r0 + i) s[i][j] = -CUDART_INF_F;
        }

#pragma unroll
        for (int i = 0; i < 4; i++) {
            float mt = fmaxf(fmaxf(s[i][0], s[i][1]), fmaxf(s[i][2], s[i][3]));
            mt = fmaxf(mt, __shfl_xor_sync(0xffffffffu, mt, 8));
            mt = fmaxf(mt, __shfl_xor_sync(0xffffffffu, mt, 4));
            mt = fmaxf(mt, __shfl_xor_sync(0xffffffffu, mt, 2));
            mt = fmaxf(mt, __shfl_xor_sync(0xffffffffu, mt, 1));
            float mn    = fmaxf(m_i[i], mt);
            float alpha = __expf(m_i[i] - mn);
            m_i[i] = mn;
            float rs = 0.f;
#pragma unroll
            for (int j = 0; j < 4; j++) {
                float p = __expf(s[i][j] - mn);
                s[i][j] = p;
                rs += p;
            }
            rs += __shfl_xor_sync(0xffffffffu, rs, 8);
            rs += __shfl_xor_sync(0xffffffffu, rs, 4);
            rs += __shfl_xor_sync(0xffffffffu, rs, 2);
            rs += __shfl_xor_sync(0xffffffffu, rs, 1);
            l_i[i] = alpha * l_i[i] + rs;
#pragma unroll
            for (int j = 0; j < 4; j++) o[i][j] *= alpha;
        }

#pragma unroll
        for (int j = 0; j < 4; j++)
#pragma unroll
            for (int i = 0; i < 4; i++)
                Pt[(c0 + j) * 64 + r0 + i] = s[i][j];
        __syncthreads();

#pragma unroll 8
        for (int c = 0; c < 64; c++) {
            float p4[4], v4[4];
            *(float4*)p4 = *(const float4*)&Pt[c * 64 + r0];
            *(float4*)v4 = *(const float4*)&Vs[c * 64 + c0];
#pragma unroll
            for (int i = 0; i < 4; i++)
#pragma unroll
                for (int j = 0; j < 4; j++)
                    o[i][j] += p4[i] * v4[j];
        }
    }

#pragma unroll
    for (int i = 0; i < 4; i++) {
        float inv = 1.f / l_i[i];
        float4 res;
        res.x = o[i][0] * inv;
        res.y = o[i][1] * inv;
        res.z = o[i][2] * inv;
        res.w = o[i][3] * inv;
        *(float4*)(out + (size_t)(b * S_LEN + qbase + r0 + i) * N_EMBD
                   + h * 64 + c0) = res;
    }
}

// ---------------------------------------------------------------------------
extern "C" void kernel_launch(void* const* d_in, const int* in_sizes, int n_in,
                              void* d_out, int out_size)
{
    const float* x      = (const float*)d_in[0];
    const float* W_attn = (const float*)d_in[1];
    const float* b_attn = (const float*)d_in[2];
    const float* W_proj = (const float*)d_in[3];
    const float* b_proj = (const float*)d_in[4];
    float* out = (float*)d_out;

    float *qkv, *att;
    cudaGetSymbolAddress((void**)&qkv, g_qkv);
    cudaGetSymbolAddress((void**)&att, g_att);
    __nv_bfloat16 *xhi, *xlo, *ahi, *alo, *wahi, *walo, *wphi, *wplo;
    cudaGetSymbolAddress((void**)&xhi, g_xhi);
    cudaGetSymbolAddress((void**)&xlo, g_xlo);
    cudaGetSymbolAddress((void**)&ahi, g_ahi);
    cudaGetSymbolAddress((void**)&alo, g_alo);
    cudaGetSymbolAddress((void**)&wahi, g_wahi);
    cudaGetSymbolAddress((void**)&walo, g_walo);
    cudaGetSymbolAddress((void**)&wphi, g_wphi);
    cudaGetSymbolAddress((void**)&wplo, g_wplo);

    cudaFuncSetAttribute(flash_attn,
                         cudaFuncAttributeMaxDynamicSharedMemorySize, 65536);
    cudaFuncSetAttribute(gemm_mma,
                         cudaFuncAttributeMaxDynamicSharedMemorySize, GSMEM);

    // split inputs / weights
    cvt_hilo<<<(M_ROWS * N_EMBD / 4 + 255) / 256, 256>>>(x, xhi, xlo, M_ROWS * N_EMBD / 4);
    cvt_t_hilo<<<dim3(E3 / 32, N_EMBD / 32), dim3(32, 8)>>>(W_attn, wahi, walo, N_EMBD, E3);
    cvt_t_hilo<<<dim3(N_EMBD / 32, N_EMBD / 32), dim3(32, 8)>>>(W_proj, wphi, wplo, N_EMBD, N_EMBD);

    // 1) QKV projection (tensor cores)
    gemm_mma<<<dim3(E3 / 128, M_ROWS / 128), 256, GSMEM>>>(
        xhi, xlo, wahi, walo, b_attn, qkv, M_ROWS, E3, N_EMBD);

    // 2) causal flash attention (fp32)
    flash_attn<<<dim3(S_LEN / 64, 2 * N_HEADS), 256, 65536>>>(qkv, att);

    // 3) output projection (tensor cores)
    cvt_hilo<<<(M_ROWS * N_EMBD / 4 + 255) / 256, 256>>>(att, ahi, alo, M_ROWS * N_EMBD / 4);
    gemm_mma<<<dim3(N_EMBD / 128, M_ROWS / 128), 256, GSMEM>>>(
        ahi, alo, wphi, wplo, b_proj, out, M_ROWS, N_EMBD, N_EMBD);
}

// round 4
// speedup vs baseline: 2.5507x; 1.8683x over previous
#include <cuda_runtime.h>
#include <cuda_bf16.h>
#include <math_constants.h>
#include <cstdint>

// ---------------------------------------------------------------------------
// MultiHeadAttention, B=2,S=2048,H=16,D=64,E=1024. All GEMMs + attention on
// HMMA (mma.sync bf16, fp32 accum) with hi/lo bf16 3-term split precision.
//   1) qkv(hi,lo) = split( x @ W_attn + b_attn )   [fused epilogue]
//   2) att(hi,lo) = split( flash(qkv) )            [tensor-core flash]
//   3) out        = att @ W_proj + b_proj          [fp32 epilogue]
// ---------------------------------------------------------------------------

#define S_LEN   2048
#define N_EMBD  1024
#define E3      3072
#define N_HEADS 16
#define M_ROWS  4096

__device__ __nv_bfloat16 g_xhi[(size_t)M_ROWS * N_EMBD];
__device__ __nv_bfloat16 g_xlo[(size_t)M_ROWS * N_EMBD];
__device__ __nv_bfloat16 g_qkvh[(size_t)M_ROWS * E3];
__device__ __nv_bfloat16 g_qkvl[(size_t)M_ROWS * E3];
__device__ __nv_bfloat16 g_atth[(size_t)M_ROWS * N_EMBD];
__device__ __nv_bfloat16 g_attl[(size_t)M_ROWS * N_EMBD];
__device__ __nv_bfloat16 g_wahi[(size_t)E3 * N_EMBD];     // W_attn^T [3072][1024]
__device__ __nv_bfloat16 g_walo[(size_t)E3 * N_EMBD];
__device__ __nv_bfloat16 g_wphi[(size_t)N_EMBD * N_EMBD]; // W_proj^T
__device__ __nv_bfloat16 g_wplo[(size_t)N_EMBD * N_EMBD];

// ------------------------- helpers ------------------------------------------
__device__ __forceinline__ uint32_t smem_u32(const void* p) {
    uint32_t a;
    asm("{ .reg .u64 t; cvta.to.shared.u64 t, %1; cvt.u32.u64 %0, t; }"
        : "=r"(a) : "l"(p));
    return a;
}
__device__ __forceinline__ void cp16(uint32_t dst, const void* src) {
    asm volatile("cp.async.cg.shared.global [%0], [%1], 16;" :: "r"(dst), "l"(src));
}
#define CP_COMMIT() asm volatile("cp.async.commit_group;" ::: "memory")
#define CP_WAIT1()  asm volatile("cp.async.wait_group 1;"  ::: "memory")
#define CP_WAIT2()  asm volatile("cp.async.wait_group 2;"  ::: "memory")

__device__ __forceinline__ void ldsm4(uint32_t* r, uint32_t addr) {
    asm volatile("ldmatrix.sync.aligned.m8n8.x4.shared.b16 {%0,%1,%2,%3}, [%4];"
                 : "=r"(r[0]), "=r"(r[1]), "=r"(r[2]), "=r"(r[3]) : "r"(addr));
}
__device__ __forceinline__ void ldsm4t(uint32_t* r, uint32_t addr) {
    asm volatile("ldmatrix.sync.aligned.m8n8.x4.trans.shared.b16 {%0,%1,%2,%3}, [%4];"
                 : "=r"(r[0]), "=r"(r[1]), "=r"(r[2]), "=r"(r[3]) : "r"(addr));
}
__device__ __forceinline__ void mma16816(float* d, const uint32_t* a, const uint32_t* b) {
    asm volatile(
        "mma.sync.aligned.m16n8k16.row.col.f32.bf16.bf16.f32 "
        "{%0,%1,%2,%3}, {%4,%5,%6,%7}, {%8,%9}, {%0,%1,%2,%3};"
        : "+f"(d[0]), "+f"(d[1]), "+f"(d[2]), "+f"(d[3])
        : "r"(a[0]), "r"(a[1]), "r"(a[2]), "r"(a[3]), "r"(b[0]), "r"(b[1]));
}
// split two fp32 into packed bf16x2 hi and lo
__device__ __forceinline__ void split2(float a, float b, uint32_t& hi, uint32_t& lo) {
    __nv_bfloat16 ha = __float2bfloat16(a), hb = __float2bfloat16(b);
    hi = (uint32_t)__bfloat16_as_ushort(ha) | ((uint32_t)__bfloat16_as_ushort(hb) << 16);
    __nv_bfloat16 la = __float2bfloat16(a - __bfloat162float(ha));
    __nv_bfloat16 lb = __float2bfloat16(b - __bfloat162float(hb));
    lo = (uint32_t)__bfloat16_as_ushort(la) | ((uint32_t)__bfloat16_as_ushort(lb) << 16);
}

// ---------------------------------------------------------------------------
// elementwise fp32 -> bf16 hi/lo split (for x)
// ---------------------------------------------------------------------------
__global__ void cvt_hilo(const float* __restrict__ in, __nv_bfloat16* __restrict__ hi,
                         __nv_bfloat16* __restrict__ lo, int n4)
{
    int i = blockIdx.x * blockDim.x + threadIdx.x;
    if (i >= n4) return;
    float4 v = ((const float4*)in)[i];
    uint32_t h0, l0, h1, l1;
    split2(v.x, v.y, h0, l0);
    split2(v.z, v.w, h1, l1);
    uint2 hv = {h0, h1}, lv = {l0, l1};
    ((uint2*)hi)[i] = hv;
    ((uint2*)lo)[i] = lv;
}

// transpose W[K][N] -> T[N][K] with hi/lo split
__global__ void cvt_t_hilo(const float* __restrict__ W, __nv_bfloat16* __restrict__ Thi,
                           __nv_bfloat16* __restrict__ Tlo, int K, int N)
{
    __shared__ float tile[32][33];
    int k0 = blockIdx.y * 32, n0 = blockIdx.x * 32;
    int tx = threadIdx.x, ty = threadIdx.y;
#pragma unroll
    for (int i = ty; i < 32; i += 8)
        tile[i][tx] = W[(size_t)(k0 + i) * N + n0 + tx];
    __syncthreads();
#pragma unroll
    for (int i = ty; i < 32; i += 8) {
        float v = tile[tx][i];
        __nv_bfloat16 h = __float2bfloat16(v);
        __nv_bfloat16 l = __float2bfloat16(v - __bfloat162float(h));
        size_t o = (size_t)(n0 + i) * K + k0 + tx;
        Thi[o] = h; Tlo[o] = l;
    }
}

// ---------------------------------------------------------------------------
// HMMA bf16x3 GEMM: 128x128 CTA tile, BK=32, 8 warps (64x32), 3-stage cp.async.
// HILO=true: write bf16 hi/lo outputs; else fp32.
// ---------------------------------------------------------------------------
#define ROWB     80
#define MATB     (128 * ROWB)
#define STAGEB   (4 * MATB)      // 40960
#define GSMEM    (3 * STAGEB)    // 122880

template <bool HILO>
__global__ __launch_bounds__(256)
void gemm_mma(const __nv_bfloat16* __restrict__ Ahi, const __nv_bfloat16* __restrict__ Alo,
              const __nv_bfloat16* __restrict__ Bhi, const __nv_bfloat16* __restrict__ Blo,
              const float* __restrict__ bias, float* __restrict__ Cf,
              __nv_bfloat16* __restrict__ Ch, __nv_bfloat16* __restrict__ Cl,
              int M, int N, int K)
{
    extern __shared__ char smem[];
    uint32_t sb = smem_u32(smem);
    int t = threadIdx.x, wid = t >> 5, lid = t & 31;
    int m0 = blockIdx.y * 128, n0 = blockIdx.x * 128;
    int wm = wid & 1, wn = wid >> 1;

    const __nv_bfloat16* gp[4] = {
        Ahi + (size_t)m0 * K, Alo + (size_t)m0 * K,
        Bhi + (size_t)n0 * K, Blo + (size_t)n0 * K };

    const int chunk = t & 3;
    const int rbase = t >> 2;

    float acc[4][4][4];
#pragma unroll
    for (int i = 0; i < 4; i++)
#pragma unroll
        for (int j = 0; j < 4; j++)
#pragma unroll
            for (int v = 0; v < 4; v++) acc[i][j][v] = 0.f;

    int nkt = K / 32;

    // prologue: stages 0,1
#pragma unroll
    for (int s = 0; s < 2; s++) {
        uint32_t st = sb + s * STAGEB;
        int koff = s * 32;
#pragma unroll
        for (int mat = 0; mat < 4; mat++)
#pragma unroll
            for (int h = 0; h < 2; h++) {
                int row = rbase + h * 64;
                cp16(st + mat * MATB + row * ROWB + chunk * 16,
                     gp[mat] + (size_t)row * K + koff + chunk * 8);
            }
        CP_COMMIT();
    }

    int s2 = 2;  // stage slot for tile kt+2
    for (int kt = 0; kt < nkt; kt++) {
        if (kt + 2 < nkt) {
            uint32_t st = sb + s2 * STAGEB;
            int koff = (kt + 2) * 32;
#pragma unroll
            for (int mat = 0; mat < 4; mat++)
#pragma unroll
                for (int h = 0; h < 2; h++) {
                    int row = rbase + h * 64;
                    cp16(st + mat * MATB + row * ROWB + chunk * 16,
                         gp[mat] + (size_t)row * K + koff + chunk * 8);
                }
        }
        CP_COMMIT();
        CP_WAIT2();
        __syncthreads();

        uint32_t st = sb + (kt - (kt / 3) * 3) * STAGEB;
        uint32_t aRow = st + (wm * 64) * ROWB;
        uint32_t bRow = st + 2 * MATB + (wn * 32) * ROWB;

#pragma unroll
        for (int k16 = 0; k16 < 2; k16++) {
            int kb = k16 * 32;
            uint32_t ah[4][4], al[4][4], bh[2][4], bl[2][4];
            uint32_t aoff = (uint32_t)(lid & 15) * ROWB + kb + (lid >> 4) * 16;
#pragma unroll
            for (int mt = 0; mt < 4; mt++) {
                uint32_t ad = aRow + mt * 16 * ROWB + aoff;
                ldsm4(ah[mt], ad);
                ldsm4(al[mt], ad + MATB);
            }
            uint32_t brow = ((lid >> 4) & 1) * 8 + (lid & 7);
            uint32_t boff = brow * ROWB + kb + ((lid >> 3) & 1) * 16;
#pragma unroll
            for (int p = 0; p < 2; p++) {
                uint32_t bd = bRow + p * 16 * ROWB + boff;
                ldsm4(bh[p], bd);
                ldsm4(bl[p], bd + MATB);
            }
#pragma unroll
            for (int mt = 0; mt < 4; mt++)
#pragma unroll
                for (int p = 0; p < 2; p++) {
                    mma16816(acc[mt][2 * p],     ah[mt], &bh[p][0]);
                    mma16816(acc[mt][2 * p + 1], ah[mt], &bh[p][2]);
                    mma16816(acc[mt][2 * p],     ah[mt], &bl[p][0]);
                    mma16816(acc[mt][2 * p + 1], ah[mt], &bl[p][2]);
                    mma16816(acc[mt][2 * p],     al[mt], &bh[p][0]);
                    mma16816(acc[mt][2 * p + 1], al[mt], &bh[p][2]);
                }
        }
        __syncthreads();
        s2 = (s2 == 2) ? 0 : s2 + 1;
    }

    int rA = m0 + wm * 64 + (lid >> 2);
    int cA = n0 + wn * 32 + 2 * (lid & 3);
#pragma unroll
    for (int mt = 0; mt < 4; mt++) {
        int r = rA + mt * 16;
#pragma unroll
        for (int nt = 0; nt < 4; nt++) {
            int c = cA + nt * 8;
            float b0 = bias[c], b1 = bias[c + 1];
            float v00 = acc[mt][nt][0] + b0, v01 = acc[mt][nt][1] + b1;
            float v10 = acc[mt][nt][2] + b0, v11 = acc[mt][nt][3] + b1;
            if (HILO) {
                uint32_t h, l;
                split2(v00, v01, h, l);
                *(uint32_t*)(Ch + (size_t)r * N + c) = h;
                *(uint32_t*)(Cl + (size_t)r * N + c) = l;
                split2(v10, v11, h, l);
                *(uint32_t*)(Ch + (size_t)(r + 8) * N + c) = h;
                *(uint32_t*)(Cl + (size_t)(r + 8) * N + c) = l;
            } else {
                float2 w0 = {v00, v01}, w1 = {v10, v11};
                *(float2*)(Cf + (size_t)r * N + c)       = w0;
                *(float2*)(Cf + (size_t)(r + 8) * N + c) = w1;
            }
        }
    }
}

// ---------------------------------------------------------------------------
// Tensor-core causal flash attention. Per CTA: one (b,h), 64 q-rows.
// 4 warps x 16 rows. bf16 hi/lo 3-term for QK^T and PV. Softmax base-2 fp32.
// SMEM: Q hi/lo (2x9216) + 2 KV stages (each K hi/lo + V hi/lo, 4x9216).
// ---------------------------------------------------------------------------
#define FROWB   144
#define FMATB   (64 * FROWB)         // 9216
#define FSTAGE  (4 * FMATB)          // 36864
#define FSMEM   (2 * FMATB + 2 * FSTAGE)  // 92160
#define SCALE_L2E 0.18033688011112042f    // 1/sqrt(64) * log2(e)

__global__ __launch_bounds__(128)
void flash_mma(const __nv_bfloat16* __restrict__ qkvh,
               const __nv_bfloat16* __restrict__ qkvl,
               __nv_bfloat16* __restrict__ atth,
               __nv_bfloat16* __restrict__ attl)
{
    extern __shared__ char smem[];
    uint32_t sb = smem_u32(smem);
    int t = threadIdx.x, wid = t >> 5, lid = t & 31;
    int bh = blockIdx.x;
    int b = bh >> 4, hh = bh & 15;
    int qt = (int)gridDim.y - 1 - blockIdx.y;   // heavy tiles first
    int qbase = qt * 64;
    int tok0 = b * S_LEN;

    const uint32_t QH = sb, QL = sb + FMATB;
    const int lrow  = t >> 1;
    const int lcol0 = (t & 1) * 4;

    // prologue: Q tile + KV stage 0
    {
        size_t rq = (size_t)(tok0 + qbase + lrow) * E3 + hh * 64;
#pragma unroll
        for (int u = 0; u < 4; u++) {
            int ch = lcol0 + u;
            cp16(QH + lrow * FROWB + ch * 16, qkvh + rq + ch * 8);
            cp16(QL + lrow * FROWB + ch * 16, qkvl + rq + ch * 8);
        }
        size_t rk = (size_t)(tok0 + lrow) * E3 + 1024 + hh * 64;
        uint32_t st = sb + 2 * FMATB;
#pragma unroll
        for (int u = 0; u < 4; u++) {
            int ch = lcol0 + u;
            uint32_t d = lrow * FROWB + ch * 16;
            cp16(st + d,             qkvh + rk + ch * 8);         // KH
            cp16(st + FMATB + d,     qkvl + rk + ch * 8);         // KL
            cp16(st + 2 * FMATB + d, qkvh + rk + 1024 + ch * 8);  // VH
            cp16(st + 3 * FMATB + d, qkvl + rk + 1024 + ch * 8);  // VL
        }
    }
    CP_COMMIT();

    // lane-derived constants
    const uint32_t aoff_base = (uint32_t)(lid & 15) * FROWB + (lid >> 4) * 16
                               + (uint32_t)wid * 16 * FROWB;
    const uint32_t brow = ((lid >> 4) & 1) * 8 + (lid & 7);
    const uint32_t boff = brow * FROWB + ((lid >> 3) & 1) * 16;
    const uint32_t vrow = ((lid >> 3) & 1) * 8 + (lid & 7);
    const uint32_t voff = vrow * FROWB + ((lid >> 4) & 1) * 16;

    uint32_t qh[4][4], ql[4][4];
    float o[8][4];
#pragma unroll
    for (int n = 0; n < 8; n++)
#pragma unroll
        for (int v = 0; v < 4; v++) o[n][v] = 0.f;
    float m_lo = -CUDART_INF_F, m_hi = -CUDART_INF_F, l_lo = 0.f, l_hi = 0.f;

    const int rlo = lid >> 2;           // within warp tile
    const int myrow_lo = wid * 16 + rlo;
    const int mycol0 = 2 * (lid & 3);

    for (int kt = 0; kt <= qt; kt++) {
        // prefetch next KV stage
        if (kt + 1 <= qt) {
            uint32_t st = sb + 2 * FMATB + ((kt + 1) & 1) * FSTAGE;
            size_t rk = (size_t)(tok0 + (kt + 1) * 64 + lrow) * E3 + 1024 + hh * 64;
#pragma unroll
            for (int u = 0; u < 4; u++) {
                int ch = lcol0 + u;
                uint32_t d = lrow * FROWB + ch * 16;
                cp16(st + d,             qkvh + rk + ch * 8);
                cp16(st + FMATB + d,     qkvl + rk + ch * 8);
                cp16(st + 2 * FMATB + d, qkvh + rk + 1024 + ch * 8);
                cp16(st + 3 * FMATB + d, qkvl + rk + 1024 + ch * 8);
            }
        }
        CP_COMMIT();
        CP_WAIT1();
        __syncthreads();

        if (kt == 0) {   // Q now resident: build persistent A fragments
#pragma unroll
            for (int ks = 0; ks < 4; ks++) {
                uint32_t ad = QH + aoff_base + ks * 32;
                ldsm4(qh[ks], ad);
                ldsm4(ql[ks], ad + FMATB);
            }
        }

        uint32_t st = sb + 2 * FMATB + (kt & 1) * FSTAGE;

        // ---- S = Q K^T ----
        float s[8][4];
#pragma unroll
        for (int n = 0; n < 8; n++)
#pragma unroll
            for (int v = 0; v < 4; v++) s[n][v] = 0.f;

#pragma unroll
        for (int ks = 0; ks < 4; ks++) {
#pragma unroll
            for (int p = 0; p < 4; p++) {
                uint32_t ka = st + p * 16 * FROWB + boff + ks * 32;
                uint32_t kh4[4], kl4[4];
                ldsm4(kh4, ka);
                ldsm4(kl4, ka + FMATB);
                mma16816(s[2 * p],     qh[ks], &kh4[0]);
                mma16816(s[2 * p + 1], qh[ks], &kh4[2]);
                mma16816(s[2 * p],     qh[ks], &kl4[0]);
                mma16816(s[2 * p + 1], qh[ks], &kl4[2]);
                mma16816(s[2 * p],     ql[ks], &kh4[0]);
                mma16816(s[2 * p + 1], ql[ks], &kh4[2]);
            }
        }

        // scale to log2 units
#pragma unroll
        for (int n = 0; n < 8; n++)
#pragma unroll
            for (int v = 0; v < 4; v++) s[n][v] *= SCALE_L2E;

        // causal mask (diagonal tile only; tiles are 64-aligned)
        if (kt == qt) {
#pragma unroll
            for (int n = 0; n < 8; n++) {
                int c0 = n * 8 + mycol0;
                if (c0 > myrow_lo)     s[n][0] = -CUDART_INF_F;
                if (c0 + 1 > myrow_lo) s[n][1] = -CUDART_INF_F;
                if (c0 > myrow_lo + 8)     s[n][2] = -CUDART_INF_F;
                if (c0 + 1 > myrow_lo + 8) s[n][3] = -CUDART_INF_F;
            }
        }

        // ---- online softmax ----
        float mt_lo = -CUDART_INF_F, mt_hi = -CUDART_INF_F;
#pragma unroll
        for (int n = 0; n < 8; n++) {
            mt_lo = fmaxf(mt_lo, fmaxf(s[n][0], s[n][1]));
            mt_hi = fmaxf(mt_hi, fmaxf(s[n][2], s[n][3]));
        }
        mt_lo = fmaxf(mt_lo, __shfl_xor_sync(0xffffffffu, mt_lo, 1));
        mt_lo = fmaxf(mt_lo, __shfl_xor_sync(0xffffffffu, mt_lo, 2));
        mt_hi = fmaxf(mt_hi, __shfl_xor_sync(0xffffffffu, mt_hi, 1));
        mt_hi = fmaxf(mt_hi, __shfl_xor_sync(0xffffffffu, mt_hi, 2));

        float mn_lo = fmaxf(m_lo, mt_lo), mn_hi = fmaxf(m_hi, mt_hi);
        float a_lo = exp2f(m_lo - mn_lo), a_hi = exp2f(m_hi - mn_hi);
        m_lo = mn_lo; m_hi = mn_hi;

        float rs_lo = 0.f, rs_hi = 0.f;
#pragma unroll
        for (int n = 0; n < 8; n++) {
            s[n][0] = exp2f(s[n][0] - mn_lo);
            s[n][1] = exp2f(s[n][1] - mn_lo);
            s[n][2] = exp2f(s[n][2] - mn_hi);
            s[n][3] = exp2f(s[n][3] - mn_hi);
            rs_lo += s[n][0] + s[n][1];
            rs_hi += s[n][2] + s[n][3];
        }
        rs_lo += __shfl_xor_sync(0xffffffffu, rs_lo, 1);
        rs_lo += __shfl_xor_sync(0xffffffffu, rs_lo, 2);
        rs_hi += __shfl_xor_sync(0xffffffffu, rs_hi, 1);
        rs_hi += __shfl_xor_sync(0xffffffffu, rs_hi, 2);
        l_lo = a_lo * l_lo + rs_lo;
        l_hi = a_hi * l_hi + rs_hi;
#pragma unroll
        for (int n = 0; n < 8; n++) {
            o[n][0] *= a_lo; o[n][1] *= a_lo;
            o[n][2] *= a_hi; o[n][3] *= a_hi;
        }

        // ---- O += P V  (P from S fragments, V^T via ldmatrix.trans) ----
        uint32_t vbase = st + 2 * FMATB;
#pragma unroll
        for (int ks = 0; ks < 4; ks++) {
            uint32_t ph[4], pl[4];
            split2(s[2 * ks][0],     s[2 * ks][1],     ph[0], pl[0]);
            split2(s[2 * ks][2],     s[2 * ks][3],     ph[1], pl[1]);
            split2(s[2 * ks + 1][0], s[2 * ks + 1][1], ph[2], pl[2]);
            split2(s[2 * ks + 1][2], s[2 * ks + 1][3], ph[3], pl[3]);
#pragma unroll
            for (int p = 0; p < 4; p++) {
                uint32_t va = vbase + ks * 16 * FROWB + voff + p * 32;
                uint32_t vh4[4], vl4[4];
                ldsm4t(vh4, va);
                ldsm4t(vl4, va + FMATB);
                mma16816(o[2 * p],     ph, &vh4[0]);
                mma16816(o[2 * p + 1], ph, &vh4[2]);
                mma16816(o[2 * p],     ph, &vl4[0]);
                mma16816(o[2 * p + 1], ph, &vl4[2]);
                mma16816(o[2 * p],     pl, &vh4[0]);
                mma16816(o[2 * p + 1], pl, &vh4[2]);
            }
        }
        __syncthreads();   // all warps done with this stage before overwrite
    }

    // ---- epilogue: normalize, split hi/lo, store ----
    float inv_lo = 1.f / l_lo, inv_hi = 1.f / l_hi;
    int tok_lo = tok0 + qbase + wid * 16 + rlo;
    int tok_hi = tok_lo + 8;
#pragma unroll
    for (int n = 0; n < 8; n++) {
        int c = hh * 64 + n * 8 + mycol0;
        uint32_t h, l;
        split2(o[n][0] * inv_lo, o[n][1] * inv_lo, h, l);
        *(uint32_t*)(atth + (size_t)tok_lo * N_EMBD + c) = h;
        *(uint32_t*)(attl + (size_t)tok_lo * N_EMBD + c) = l;
        split2(o[n][2] * inv_hi, o[n][3] * inv_hi, h, l);
        *(uint32_t*)(atth + (size_t)tok_hi * N_EMBD + c) = h;
        *(uint32_t*)(attl + (size_t)tok_hi * N_EMBD + c) = l;
    }
}

// ---------------------------------------------------------------------------
extern "C" void kernel_launch(void* const* d_in, const int* in_sizes, int n_in,
                              void* d_out, int out_size)
{
    const float* x      = (const float*)d_in[0];
    const float* W_attn = (const float*)d_in[1];
    const float* b_attn = (const float*)d_in[2];
    const float* W_proj = (const float*)d_in[3];
    const float* b_proj = (const float*)d_in[4];
    float* out = (float*)d_out;

    __nv_bfloat16 *xhi, *xlo, *qkvh, *qkvl, *atth, *attl, *wahi, *walo, *wphi, *wplo;
    cudaGetSymbolAddress((void**)&xhi, g_xhi);
    cudaGetSymbolAddress((void**)&xlo, g_xlo);
    cudaGetSymbolAddress((void**)&qkvh, g_qkvh);
    cudaGetSymbolAddress((void**)&qkvl, g_qkvl);
    cudaGetSymbolAddress((void**)&atth, g_atth);
    cudaGetSymbolAddress((void**)&attl, g_attl);
    cudaGetSymbolAddress((void**)&wahi, g_wahi);
    cudaGetSymbolAddress((void**)&walo, g_walo);
    cudaGetSymbolAddress((void**)&wphi, g_wphi);
    cudaGetSymbolAddress((void**)&wplo, g_wplo);

    cudaFuncSetAttribute(gemm_mma<true>,
                         cudaFuncAttributeMaxDynamicSharedMemorySize, GSMEM);
    cudaFuncSetAttribute(gemm_mma<false>,
                         cudaFuncAttributeMaxDynamicSharedMemorySize, GSMEM);
    cudaFuncSetAttribute(flash_mma,
                         cudaFuncAttributeMaxDynamicSharedMemorySize, FSMEM);

    // operand preparation
    cvt_hilo<<<(M_ROWS * N_EMBD / 4 + 255) / 256, 256>>>(x, xhi, xlo, M_ROWS * N_EMBD / 4);
    cvt_t_hilo<<<dim3(E3 / 32, N_EMBD / 32), dim3(32, 8)>>>(W_attn, wahi, walo, N_EMBD, E3);
    cvt_t_hilo<<<dim3(N_EMBD / 32, N_EMBD / 32), dim3(32, 8)>>>(W_proj, wphi, wplo, N_EMBD, N_EMBD);

    // 1) QKV projection -> bf16 hi/lo directly
    gemm_mma<true><<<dim3(E3 / 128, M_ROWS / 128), 256, GSMEM>>>(
        xhi, xlo, wahi, walo, b_attn, nullptr, qkvh, qkvl, M_ROWS, E3, N_EMBD);

    // 2) tensor-core causal flash attention -> att hi/lo
    flash_mma<<<dim3(2 * N_HEADS, S_LEN / 64), 128, FSMEM>>>(qkvh, qkvl, atth, attl);

    // 3) output projection -> fp32
    gemm_mma<false><<<dim3(N_EMBD / 128, M_ROWS / 128), 256, GSMEM>>>(
        atth, attl, wphi, wplo, b_proj, out, nullptr, nullptr, M_ROWS, N_EMBD, N_EMBD);
}

// round 5
// speedup vs baseline: 2.9757x; 1.1666x over previous
#include <cuda_runtime.h>
#include <cuda_bf16.h>
#include <math_constants.h>
#include <cstdint>

// ---------------------------------------------------------------------------
// MultiHeadAttention, B=2,S=2048,H=16,D=64,E=1024. All GEMMs + attention on
// HMMA (mma.sync bf16, fp32 accum) with hi/lo bf16 3-term split precision.
//   1) qkv(hi,lo) = split( x @ W_attn + b_attn )   [fused epilogue]
//   2) att(hi,lo) = split( flash(qkv) )            [tensor-core flash]
//   3) out        = att @ W_proj + b_proj          [fp32 epilogue]
// GEMM mainloop: BK=64, 3 stages, ONE barrier per ktile (sync-frequency was
// the round-4 bottleneck: tensor% pinned ~44% by 2 barriers per BK=32 tile).
// ---------------------------------------------------------------------------

#define S_LEN   2048
#define N_EMBD  1024
#define E3      3072
#define N_HEADS 16
#define M_ROWS  4096

__device__ __nv_bfloat16 g_xhi[(size_t)M_ROWS * N_EMBD];
__device__ __nv_bfloat16 g_xlo[(size_t)M_ROWS * N_EMBD];
__device__ __nv_bfloat16 g_qkvh[(size_t)M_ROWS * E3];
__device__ __nv_bfloat16 g_qkvl[(size_t)M_ROWS * E3];
__device__ __nv_bfloat16 g_atth[(size_t)M_ROWS * N_EMBD];
__device__ __nv_bfloat16 g_attl[(size_t)M_ROWS * N_EMBD];
__device__ __nv_bfloat16 g_wahi[(size_t)E3 * N_EMBD];     // W_attn^T [3072][1024]
__device__ __nv_bfloat16 g_walo[(size_t)E3 * N_EMBD];
__device__ __nv_bfloat16 g_wphi[(size_t)N_EMBD * N_EMBD]; // W_proj^T
__device__ __nv_bfloat16 g_wplo[(size_t)N_EMBD * N_EMBD];

// ------------------------- helpers ------------------------------------------
__device__ __forceinline__ uint32_t smem_u32(const void* p) {
    uint32_t a;
    asm("{ .reg .u64 t; cvta.to.shared.u64 t, %1; cvt.u32.u64 %0, t; }"
        : "=r"(a) : "l"(p));
    return a;
}
__device__ __forceinline__ void cp16(uint32_t dst, const void* src) {
    asm volatile("cp.async.cg.shared.global [%0], [%1], 16;" :: "r"(dst), "l"(src));
}
#define CP_COMMIT() asm volatile("cp.async.commit_group;" ::: "memory")
#define CP_WAIT1()  asm volatile("cp.async.wait_group 1;"  ::: "memory")

__device__ __forceinline__ void ldsm4(uint32_t* r, uint32_t addr) {
    asm volatile("ldmatrix.sync.aligned.m8n8.x4.shared.b16 {%0,%1,%2,%3}, [%4];"
                 : "=r"(r[0]), "=r"(r[1]), "=r"(r[2]), "=r"(r[3]) : "r"(addr));
}
__device__ __forceinline__ void ldsm4t(uint32_t* r, uint32_t addr) {
    asm volatile("ldmatrix.sync.aligned.m8n8.x4.trans.shared.b16 {%0,%1,%2,%3}, [%4];"
                 : "=r"(r[0]), "=r"(r[1]), "=r"(r[2]), "=r"(r[3]) : "r"(addr));
}
__device__ __forceinline__ void mma16816(float* d, const uint32_t* a, const uint32_t* b) {
    asm volatile(
        "mma.sync.aligned.m16n8k16.row.col.f32.bf16.bf16.f32 "
        "{%0,%1,%2,%3}, {%4,%5,%6,%7}, {%8,%9}, {%0,%1,%2,%3};"
        : "+f"(d[0]), "+f"(d[1]), "+f"(d[2]), "+f"(d[3])
        : "r"(a[0]), "r"(a[1]), "r"(a[2]), "r"(a[3]), "r"(b[0]), "r"(b[1]));
}
// fast split: truncation hi (exact residual lo). hi: {lo16(a-trunc), ...} packed.
__device__ __forceinline__ void split2(float a, float b, uint32_t& hi, uint32_t& lo) {
    uint32_t ua = __float_as_uint(a) & 0xFFFF0000u;
    uint32_t ub = __float_as_uint(b) & 0xFFFF0000u;
    hi = __byte_perm(ua, ub, 0x7632);           // {b.hi16, a.hi16} -> a low, b high
    float la = a - __uint_as_float(ua);
    float lb = b - __uint_as_float(ub);
    asm("cvt.rn.bf16x2.f32 %0, %1, %2;" : "=r"(lo) : "f"(lb), "f"(la));
}

// ---------------------------------------------------------------------------
// elementwise fp32 -> bf16 hi/lo split (for x)
// ---------------------------------------------------------------------------
__global__ void cvt_hilo(const float* __restrict__ in, __nv_bfloat16* __restrict__ hi,
                         __nv_bfloat16* __restrict__ lo, int n4)
{
    int i = blockIdx.x * blockDim.x + threadIdx.x;
    if (i >= n4) return;
    float4 v = ((const float4*)in)[i];
    uint32_t h0, l0, h1, l1;
    split2(v.x, v.y, h0, l0);
    split2(v.z, v.w, h1, l1);
    uint2 hv = {h0, h1}, lv = {l0, l1};
    ((uint2*)hi)[i] = hv;
    ((uint2*)lo)[i] = lv;
}

// transpose W[K][N] -> T[N][K] with hi/lo split
__global__ void cvt_t_hilo(const float* __restrict__ W, __nv_bfloat16* __restrict__ Thi,
                           __nv_bfloat16* __restrict__ Tlo, int K, int N)
{
    __shared__ float tile[32][33];
    int k0 = blockIdx.y * 32, n0 = blockIdx.x * 32;
    int tx = threadIdx.x, ty = threadIdx.y;
#pragma unroll
    for (int i = ty; i < 32; i += 8)
        tile[i][tx] = W[(size_t)(k0 + i) * N + n0 + tx];
    __syncthreads();
#pragma unroll
    for (int i = ty; i < 32; i += 8) {
        float v = tile[tx][i];
        uint32_t uh = __float_as_uint(v) & 0xFFFF0000u;
        float l = v - __uint_as_float(uh);
        size_t o = (size_t)(n0 + i) * K + k0 + tx;
        Thi[o] = __ushort_as_bfloat16((unsigned short)(uh >> 16));
        Tlo[o] = __float2bfloat16(l);
    }
}

// ---------------------------------------------------------------------------
// HMMA bf16x3 GEMM: 128x128 CTA tile, BK=64, 8 warps (64x32), 3-stage
// cp.async, ONE __syncthreads per ktile (loads issued post-barrier).
// ---------------------------------------------------------------------------
#define ROWB     144             // 64 bf16 = 128B + 16B pad (conflict-free)
#define MATB     (128 * ROWB)    // 18432
#define STAGEB   (4 * MATB)      // 73728
#define GSMEM    (3 * STAGEB)    // 221184 (< 227KB opt-in)

template <bool HILO>
__global__ __launch_bounds__(256)
void gemm_mma(const __nv_bfloat16* __restrict__ Ahi, const __nv_bfloat16* __restrict__ Alo,
              const __nv_bfloat16* __restrict__ Bhi, const __nv_bfloat16* __restrict__ Blo,
              const float* __restrict__ bias, float* __restrict__ Cf,
              __nv_bfloat16* __restrict__ Ch, __nv_bfloat16* __restrict__ Cl,
              int M, int N, int K)
{
    extern __shared__ char smem[];
    uint32_t sb = smem_u32(smem);
    int t = threadIdx.x, wid = t >> 5, lid = t & 31;
    int m0 = blockIdx.y * 128, n0 = blockIdx.x * 128;
    int wm = wid & 1, wn = wid >> 1;

    const __nv_bfloat16* gp[4] = {
        Ahi + (size_t)m0 * K, Alo + (size_t)m0 * K,
        Bhi + (size_t)n0 * K, Blo + (size_t)n0 * K };

    const int chunk = t & 7;      // 16B chunk within 128B row payload
    const int rb    = t >> 3;     // 0..31

    float acc[4][4][4];
#pragma unroll
    for (int i = 0; i < 4; i++)
#pragma unroll
        for (int j = 0; j < 4; j++)
#pragma unroll
            for (int v = 0; v < 4; v++) acc[i][j][v] = 0.f;

    int nkt = K / 64;  // 16

    // prologue: stages 0,1
#pragma unroll
    for (int s = 0; s < 2; s++) {
        uint32_t st = sb + s * STAGEB;
        int koff = s * 64;
#pragma unroll
        for (int mat = 0; mat < 4; mat++)
#pragma unroll
            for (int h = 0; h < 4; h++) {
                int row = rb + h * 32;
                cp16(st + mat * MATB + row * ROWB + chunk * 16,
                     gp[mat] + (size_t)row * K + koff + chunk * 8);
            }
        CP_COMMIT();
    }

    int rd = 0, wr = 2;   // read / write stage indices
    for (int kt = 0; kt < nkt; kt++) {
        CP_WAIT1();
        __syncthreads();

        uint32_t st = sb + rd * STAGEB;
        uint32_t aRow = st + (wm * 64) * ROWB;
        uint32_t bRow = st + 2 * MATB + (wn * 32) * ROWB;

#pragma unroll
        for (int k16 = 0; k16 < 4; k16++) {
            int kb = k16 * 32;
            uint32_t ah[4][4], al[4][4], bh[2][4], bl[2][4];
            uint32_t aoff = (uint32_t)(lid & 15) * ROWB + kb + (lid >> 4) * 16;
#pragma unroll
            for (int mt = 0; mt < 4; mt++) {
                uint32_t ad = aRow + mt * 16 * ROWB + aoff;
                ldsm4(ah[mt], ad);
                ldsm4(al[mt], ad + MATB);
            }
            uint32_t brow = ((lid >> 4) & 1) * 8 + (lid & 7);
            uint32_t boff = brow * ROWB + kb + ((lid >> 3) & 1) * 16;
#pragma unroll
            for (int p = 0; p < 2; p++) {
                uint32_t bd = bRow + p * 16 * ROWB + boff;
                ldsm4(bh[p], bd);
                ldsm4(bl[p], bd + MATB);
            }
#pragma unroll
            for (int mt = 0; mt < 4; mt++)
#pragma unroll
                for (int p = 0; p < 2; p++) {
                    mma16816(acc[mt][2 * p],     ah[mt], &bh[p][0]);
                    mma16816(acc[mt][2 * p + 1], ah[mt], &bh[p][2]);
                    mma16816(acc[mt][2 * p],     ah[mt], &bl[p][0]);
                    mma16816(acc[mt][2 * p + 1], ah[mt], &bl[p][2]);
                    mma16816(acc[mt][2 * p],     al[mt], &bh[p][0]);
                    mma16816(acc[mt][2 * p + 1], al[mt], &bh[p][2]);
                }
        }

        // issue loads for stage kt+2 (safe: everyone crossed this iter's sync,
        // so stage (kt+2)%3 == (kt-1)%3 is fully consumed)
        if (kt + 2 < nkt) {
            uint32_t st2 = sb + wr * STAGEB;
            int koff = (kt + 2) * 64;
#pragma unroll
            for (int mat = 0; mat < 4; mat++)
#pragma unroll
                for (int h = 0; h < 4; h++) {
                    int row = rb + h * 32;
                    cp16(st2 + mat * MATB + row * ROWB + chunk * 16,
                         gp[mat] + (size_t)row * K + koff + chunk * 8);
                }
        }
        CP_COMMIT();
        rd = (rd == 2) ? 0 : rd + 1;
        wr = (wr == 2) ? 0 : wr + 1;
    }

    int rA = m0 + wm * 64 + (lid >> 2);
    int cA = n0 + wn * 32 + 2 * (lid & 3);
#pragma unroll
    for (int mt = 0; mt < 4; mt++) {
        int r = rA + mt * 16;
#pragma unroll
        for (int nt = 0; nt < 4; nt++) {
            int c = cA + nt * 8;
            float b0 = bias[c], b1 = bias[c + 1];
            float v00 = acc[mt][nt][0] + b0, v01 = acc[mt][nt][1] + b1;
            float v10 = acc[mt][nt][2] + b0, v11 = acc[mt][nt][3] + b1;
            if (HILO) {
                uint32_t h, l;
                split2(v00, v01, h, l);
                *(uint32_t*)(Ch + (size_t)r * N + c) = h;
                *(uint32_t*)(Cl + (size_t)r * N + c) = l;
                split2(v10, v11, h, l);
                *(uint32_t*)(Ch + (size_t)(r + 8) * N + c) = h;
                *(uint32_t*)(Cl + (size_t)(r + 8) * N + c) = l;
            } else {
                float2 w0 = {v00, v01}, w1 = {v10, v11};
                *(float2*)(Cf + (size_t)r * N + c)       = w0;
                *(float2*)(Cf + (size_t)(r + 8) * N + c) = w1;
            }
        }
    }
}

// ---------------------------------------------------------------------------
// Tensor-core causal flash attention. Per CTA: one (b,h), 64 q-rows.
// 4 warps x 16 rows. bf16 hi/lo 3-term for QK^T and PV. Softmax base-2 fp32.
// ---------------------------------------------------------------------------
#define FROWB   144
#define FMATB   (64 * FROWB)         // 9216
#define FSTAGE  (4 * FMATB)          // 36864
#define FSMEM   (2 * FMATB + 2 * FSTAGE)  // 92160
#define SCALE_L2E 0.18033688011112042f    // 1/sqrt(64) * log2(e)

__global__ __launch_bounds__(128)
void flash_mma(const __nv_bfloat16* __restrict__ qkvh,
               const __nv_bfloat16* __restrict__ qkvl,
               __nv_bfloat16* __restrict__ atth,
               __nv_bfloat16* __restrict__ attl)
{
    extern __shared__ char smem[];
    uint32_t sb = smem_u32(smem);
    int t = threadIdx.x, wid = t >> 5, lid = t & 31;
    int bh = blockIdx.x;
    int b = bh >> 4, hh = bh & 15;
    int qt = (int)gridDim.y - 1 - blockIdx.y;   // heavy tiles first
    int qbase = qt * 64;
    int tok0 = b * S_LEN;

    const uint32_t QH = sb, QL = sb + FMATB;
    const int lrow  = t >> 1;
    const int lcol0 = (t & 1) * 4;

    // prologue: Q tile + KV stage 0
    {
        size_t rq = (size_t)(tok0 + qbase + lrow) * E3 + hh * 64;
#pragma unroll
        for (int u = 0; u < 4; u++) {
            int ch = lcol0 + u;
            cp16(QH + lrow * FROWB + ch * 16, qkvh + rq + ch * 8);
            cp16(QL + lrow * FROWB + ch * 16, qkvl + rq + ch * 8);
        }
        size_t rk = (size_t)(tok0 + lrow) * E3 + 1024 + hh * 64;
        uint32_t st = sb + 2 * FMATB;
#pragma unroll
        for (int u = 0; u < 4; u++) {
            int ch = lcol0 + u;
            uint32_t d = lrow * FROWB + ch * 16;
            cp16(st + d,             qkvh + rk + ch * 8);         // KH
            cp16(st + FMATB + d,     qkvl + rk + ch * 8);         // KL
            cp16(st + 2 * FMATB + d, qkvh + rk + 1024 + ch * 8);  // VH
            cp16(st + 3 * FMATB + d, qkvl + rk + 1024 + ch * 8);  // VL
        }
    }
    CP_COMMIT();

    const uint32_t aoff_base = (uint32_t)(lid & 15) * FROWB + (lid >> 4) * 16
                               + (uint32_t)wid * 16 * FROWB;
    const uint32_t brow = ((lid >> 4) & 1) * 8 + (lid & 7);
    const uint32_t boff = brow * FROWB + ((lid >> 3) & 1) * 16;
    const uint32_t vrow = ((lid >> 3) & 1) * 8 + (lid & 7);
    const uint32_t voff = vrow * FROWB + ((lid >> 4) & 1) * 16;

    uint32_t qh[4][4], ql[4][4];
    float o[8][4];
#pragma unroll
    for (int n = 0; n < 8; n++)
#pragma unroll
        for (int v = 0; v < 4; v++) o[n][v] = 0.f;
    float m_lo = -CUDART_INF_F, m_hi = -CUDART_INF_F, l_lo = 0.f, l_hi = 0.f;

    const int rlo = lid >> 2;
    const int myrow_lo = wid * 16 + rlo;
    const int mycol0 = 2 * (lid & 3);

    for (int kt = 0; kt <= qt; kt++) {
        if (kt + 1 <= qt) {
            uint32_t st = sb + 2 * FMATB + ((kt + 1) & 1) * FSTAGE;
            size_t rk = (size_t)(tok0 + (kt + 1) * 64 + lrow) * E3 + 1024 + hh * 64;
#pragma unroll
            for (int u = 0; u < 4; u++) {
                int ch = lcol0 + u;
                uint32_t d = lrow * FROWB + ch * 16;
                cp16(st + d,             qkvh + rk + ch * 8);
                cp16(st + FMATB + d,     qkvl + rk + ch * 8);
                cp16(st + 2 * FMATB + d, qkvh + rk + 1024 + ch * 8);
                cp16(st + 3 * FMATB + d, qkvl + rk + 1024 + ch * 8);
            }
        }
        CP_COMMIT();
        CP_WAIT1();
        __syncthreads();

        if (kt == 0) {
#pragma unroll
            for (int ks = 0; ks < 4; ks++) {
                uint32_t ad = QH + aoff_base + ks * 32;
                ldsm4(qh[ks], ad);
                ldsm4(ql[ks], ad + FMATB);
            }
        }

        uint32_t st = sb + 2 * FMATB + (kt & 1) * FSTAGE;

        // ---- S = Q K^T ----
        float s[8][4];
#pragma unroll
        for (int n = 0; n < 8; n++)
#pragma unroll
            for (int v = 0; v < 4; v++) s[n][v] = 0.f;

#pragma unroll
        for (int ks = 0; ks < 4; ks++) {
#pragma unroll
            for (int p = 0; p < 4; p++) {
                uint32_t ka = st + p * 16 * FROWB + boff + ks * 32;
                uint32_t kh4[4], kl4[4];
                ldsm4(kh4, ka);
                ldsm4(kl4, ka + FMATB);
                mma16816(s[2 * p],     qh[ks], &kh4[0]);
                mma16816(s[2 * p + 1], qh[ks], &kh4[2]);
                mma16816(s[2 * p],     qh[ks], &kl4[0]);
                mma16816(s[2 * p + 1], qh[ks], &kl4[2]);
                mma16816(s[2 * p],     ql[ks], &kh4[0]);
                mma16816(s[2 * p + 1], ql[ks], &kh4[2]);
            }
        }

#pragma unroll
        for (int n = 0; n < 8; n++)
#pragma unroll
            for (int v = 0; v < 4; v++) s[n][v] *= SCALE_L2E;

        if (kt == qt) {
#pragma unroll
            for (int n = 0; n < 8; n++) {
                int c0 = n * 8 + mycol0;
                if (c0 > myrow_lo)     s[n][0] = -CUDART_INF_F;
                if (c0 + 1 > myrow_lo) s[n][1] = -CUDART_INF_F;
                if (c0 > myrow_lo + 8)     s[n][2] = -CUDART_INF_F;
                if (c0 + 1 > myrow_lo + 8) s[n][3] = -CUDART_INF_F;
            }
        }

        // ---- online softmax ----
        float mt_lo = -CUDART_INF_F, mt_hi = -CUDART_INF_F;
#pragma unroll
        for (int n = 0; n < 8; n++) {
            mt_lo = fmaxf(mt_lo, fmaxf(s[n][0], s[n][1]));
            mt_hi = fmaxf(mt_hi, fmaxf(s[n][2], s[n][3]));
        }
        mt_lo = fmaxf(mt_lo, __shfl_xor_sync(0xffffffffu, mt_lo, 1));
        mt_lo = fmaxf(mt_lo, __shfl_xor_sync(0xffffffffu, mt_lo, 2));
        mt_hi = fmaxf(mt_hi, __shfl_xor_sync(0xffffffffu, mt_hi, 1));
        mt_hi = fmaxf(mt_hi, __shfl_xor_sync(0xffffffffu, mt_hi, 2));

        float mn_lo = fmaxf(m_lo, mt_lo), mn_hi = fmaxf(m_hi, mt_hi);
        float a_lo = exp2f(m_lo - mn_lo), a_hi = exp2f(m_hi - mn_hi);
        m_lo = mn_lo; m_hi = mn_hi;

        float rs_lo = 0.f, rs_hi = 0.f;
#pragma unroll
        for (int n = 0; n < 8; n++) {
            s[n][0] = exp2f(s[n][0] - mn_lo);
            s[n][1] = exp2f(s[n][1] - mn_lo);
            s[n][2] = exp2f(s[n][2] - mn_hi);
            s[n][3] = exp2f(s[n][3] - mn_hi);
            rs_lo += s[n][0] + s[n][1];
            rs_hi += s[n][2] + s[n][3];
        }
        rs_lo += __shfl_xor_sync(0xffffffffu, rs_lo, 1);
        rs_lo += __shfl_xor_sync(0xffffffffu, rs_lo, 2);
        rs_hi += __shfl_xor_sync(0xffffffffu, rs_hi, 1);
        rs_hi += __shfl_xor_sync(0xffffffffu, rs_hi, 2);
        l_lo = a_lo * l_lo + rs_lo;
        l_hi = a_hi * l_hi + rs_hi;
#pragma unroll
        for (int n = 0; n < 8; n++) {
            o[n][0] *= a_lo; o[n][1] *= a_lo;
            o[n][2] *= a_hi; o[n][3] *= a_hi;
        }

        // ---- O += P V ----
        uint32_t vbase = st + 2 * FMATB;
#pragma unroll
        for (int ks = 0; ks < 4; ks++) {
            uint32_t ph[4], pl[4];
            split2(s[2 * ks][0],     s[2 * ks][1],     ph[0], pl[0]);
            split2(s[2 * ks][2],     s[2 * ks][3],     ph[1], pl[1]);
            split2(s[2 * ks + 1][0], s[2 * ks + 1][1], ph[2], pl[2]);
            split2(s[2 * ks + 1][2], s[2 * ks + 1][3], ph[3], pl[3]);
#pragma unroll
            for (int p = 0; p < 4; p++) {
                uint32_t va = vbase + ks * 16 * FROWB + voff + p * 32;
                uint32_t vh4[4], vl4[4];
                ldsm4t(vh4, va);
                ldsm4t(vl4, va + FMATB);
                mma16816(o[2 * p],     ph, &vh4[0]);
                mma16816(o[2 * p + 1], ph, &vh4[2]);
                mma16816(o[2 * p],     ph, &vl4[0]);
                mma16816(o[2 * p + 1], ph, &vl4[2]);
                mma16816(o[2 * p],     pl, &vh4[0]);
                mma16816(o[2 * p + 1], pl, &vh4[2]);
            }
        }
        __syncthreads();
    }

    // ---- epilogue ----
    float inv_lo = 1.f / l_lo, inv_hi = 1.f / l_hi;
    int tok_lo = tok0 + qbase + wid * 16 + rlo;
    int tok_hi = tok_lo + 8;
#pragma unroll
    for (int n = 0; n < 8; n++) {
        int c = hh * 64 + n * 8 + mycol0;
        uint32_t h, l;
        split2(o[n][0] * inv_lo, o[n][1] * inv_lo, h, l);
        *(uint32_t*)(atth + (size_t)tok_lo * N_EMBD + c) = h;
        *(uint32_t*)(attl + (size_t)tok_lo * N_EMBD + c) = l;
        split2(o[n][2] * inv_hi, o[n][3] * inv_hi, h, l);
        *(uint32_t*)(atth + (size_t)tok_hi * N_EMBD + c) = h;
        *(uint32_t*)(attl + (size_t)tok_hi * N_EMBD + c) = l;
    }
}

// ---------------------------------------------------------------------------
extern "C" void kernel_launch(void* const* d_in, const int* in_sizes, int n_in,
                              void* d_out, int out_size)
{
    const float* x      = (const float*)d_in[0];
    const float* W_attn = (const float*)d_in[1];
    const float* b_attn = (const float*)d_in[2];
    const float* W_proj = (const float*)d_in[3];
    const float* b_proj = (const float*)d_in[4];
    float* out = (float*)d_out;

    __nv_bfloat16 *xhi, *xlo, *qkvh, *qkvl, *atth, *attl, *wahi, *walo, *wphi, *wplo;
    cudaGetSymbolAddress((void**)&xhi, g_xhi);
    cudaGetSymbolAddress((void**)&xlo, g_xlo);
    cudaGetSymbolAddress((void**)&qkvh, g_qkvh);
    cudaGetSymbolAddress((void**)&qkvl, g_qkvl);
    cudaGetSymbolAddress((void**)&atth, g_atth);
    cudaGetSymbolAddress((void**)&attl, g_attl);
    cudaGetSymbolAddress((void**)&wahi, g_wahi);
    cudaGetSymbolAddress((void**)&walo, g_walo);
    cudaGetSymbolAddress((void**)&wphi, g_wphi);
    cudaGetSymbolAddress((void**)&wplo, g_wplo);

    cudaFuncSetAttribute(gemm_mma<true>,
                         cudaFuncAttributeMaxDynamicSharedMemorySize, GSMEM);
    cudaFuncSetAttribute(gemm_mma<false>,
                         cudaFuncAttributeMaxDynamicSharedMemorySize, GSMEM);
    cudaFuncSetAttribute(flash_mma,
                         cudaFuncAttributeMaxDynamicSharedMemorySize, FSMEM);

    cvt_hilo<<<(M_ROWS * N_EMBD / 4 + 255) / 256, 256>>>(x, xhi, xlo, M_ROWS * N_EMBD / 4);
    cvt_t_hilo<<<dim3(E3 / 32, N_EMBD / 32), dim3(32, 8)>>>(W_attn, wahi, walo, N_EMBD, E3);
    cvt_t_hilo<<<dim3(N_EMBD / 32, N_EMBD / 32), dim3(32, 8)>>>(W_proj, wphi, wplo, N_EMBD, N_EMBD);

    gemm_mma<true><<<dim3(E3 / 128, M_ROWS / 128), 256, GSMEM>>>(
        xhi, xlo, wahi, walo, b_attn, nullptr, qkvh, qkvl, M_ROWS, E3, N_EMBD);

    flash_mma<<<dim3(2 * N_HEADS, S_LEN / 64), 128, FSMEM>>>(qkvh, qkvl, atth, attl);

    gemm_mma<false><<<dim3(N_EMBD / 128, M_ROWS / 128), 256, GSMEM>>>(
        atth, attl, wphi, wplo, b_proj, out, nullptr, nullptr, M_ROWS, N_EMBD, N_EMBD);
}

// round 6
// speedup vs baseline: 3.2608x; 1.0958x over previous
#include <cuda_runtime.h>
#include <cuda_bf16.h>
#include <math_constants.h>
#include <cstdint>

// ---------------------------------------------------------------------------
// MultiHeadAttention, B=2,S=2048,H=16,D=64,E=1024. HMMA everywhere with
// bf16 hi/lo 3-term split precision.
//   1) qkv(hi,lo) = split( x @ W_attn + b_attn )
//   2) att(hi,lo) = split( flash(qkv) )   [128-row Q tiles, 8 warps]
//   3) out        = att @ W_proj + b_proj
// GEMM mainloop: BK=64, 3 stages, 1 barrier/ktile, term-major MMA order
// (kills accumulator RAW chains — round-5 limiter at 2 warps/SMSP).
// ---------------------------------------------------------------------------

#define S_LEN   2048
#define N_EMBD  1024
#define E3      3072
#define N_HEADS 16
#define M_ROWS  4096

__device__ __nv_bfloat16 g_xhi[(size_t)M_ROWS * N_EMBD];
__device__ __nv_bfloat16 g_xlo[(size_t)M_ROWS * N_EMBD];
__device__ __nv_bfloat16 g_qkvh[(size_t)M_ROWS * E3];
__device__ __nv_bfloat16 g_qkvl[(size_t)M_ROWS * E3];
__device__ __nv_bfloat16 g_atth[(size_t)M_ROWS * N_EMBD];
__device__ __nv_bfloat16 g_attl[(size_t)M_ROWS * N_EMBD];
__device__ __nv_bfloat16 g_wahi[(size_t)E3 * N_EMBD];
__device__ __nv_bfloat16 g_walo[(size_t)E3 * N_EMBD];
__device__ __nv_bfloat16 g_wphi[(size_t)N_EMBD * N_EMBD];
__device__ __nv_bfloat16 g_wplo[(size_t)N_EMBD * N_EMBD];

// ------------------------- helpers ------------------------------------------
__device__ __forceinline__ uint32_t smem_u32(const void* p) {
    uint32_t a;
    asm("{ .reg .u64 t; cvta.to.shared.u64 t, %1; cvt.u32.u64 %0, t; }"
        : "=r"(a) : "l"(p));
    return a;
}
__device__ __forceinline__ void cp16(uint32_t dst, const void* src) {
    asm volatile("cp.async.cg.shared.global [%0], [%1], 16;" :: "r"(dst), "l"(src));
}
#define CP_COMMIT() asm volatile("cp.async.commit_group;" ::: "memory")
#define CP_WAIT1()  asm volatile("cp.async.wait_group 1;"  ::: "memory")

__device__ __forceinline__ void ldsm4(uint32_t* r, uint32_t addr) {
    asm volatile("ldmatrix.sync.aligned.m8n8.x4.shared.b16 {%0,%1,%2,%3}, [%4];"
                 : "=r"(r[0]), "=r"(r[1]), "=r"(r[2]), "=r"(r[3]) : "r"(addr));
}
__device__ __forceinline__ void ldsm4t(uint32_t* r, uint32_t addr) {
    asm volatile("ldmatrix.sync.aligned.m8n8.x4.trans.shared.b16 {%0,%1,%2,%3}, [%4];"
                 : "=r"(r[0]), "=r"(r[1]), "=r"(r[2]), "=r"(r[3]) : "r"(addr));
}
__device__ __forceinline__ void mma16816(float* d, const uint32_t* a, const uint32_t* b) {
    asm volatile(
        "mma.sync.aligned.m16n8k16.row.col.f32.bf16.bf16.f32 "
        "{%0,%1,%2,%3}, {%4,%5,%6,%7}, {%8,%9}, {%0,%1,%2,%3};"
        : "+f"(d[0]), "+f"(d[1]), "+f"(d[2]), "+f"(d[3])
        : "r"(a[0]), "r"(a[1]), "r"(a[2]), "r"(a[3]), "r"(b[0]), "r"(b[1]));
}
// fast split: truncation hi + exact residual lo
__device__ __forceinline__ void split2(float a, float b, uint32_t& hi, uint32_t& lo) {
    uint32_t ua = __float_as_uint(a) & 0xFFFF0000u;
    uint32_t ub = __float_as_uint(b) & 0xFFFF0000u;
    hi = __byte_perm(ua, ub, 0x7632);
    float la = a - __uint_as_float(ua);
    float lb = b - __uint_as_float(ub);
    asm("cvt.rn.bf16x2.f32 %0, %1, %2;" : "=r"(lo) : "f"(lb), "f"(la));
}

// ---------------------------------------------------------------------------
__global__ void cvt_hilo(const float* __restrict__ in, __nv_bfloat16* __restrict__ hi,
                         __nv_bfloat16* __restrict__ lo, int n4)
{
    int i = blockIdx.x * blockDim.x + threadIdx.x;
    if (i >= n4) return;
    float4 v = ((const float4*)in)[i];
    uint32_t h0, l0, h1, l1;
    split2(v.x, v.y, h0, l0);
    split2(v.z, v.w, h1, l1);
    uint2 hv = {h0, h1}, lv = {l0, l1};
    ((uint2*)hi)[i] = hv;
    ((uint2*)lo)[i] = lv;
}

__global__ void cvt_t_hilo(const float* __restrict__ W, __nv_bfloat16* __restrict__ Thi,
                           __nv_bfloat16* __restrict__ Tlo, int K, int N)
{
    __shared__ float tile[32][33];
    int k0 = blockIdx.y * 32, n0 = blockIdx.x * 32;
    int tx = threadIdx.x, ty = threadIdx.y;
#pragma unroll
    for (int i = ty; i < 32; i += 8)
        tile[i][tx] = W[(size_t)(k0 + i) * N + n0 + tx];
    __syncthreads();
#pragma unroll
    for (int i = ty; i < 32; i += 8) {
        float v = tile[tx][i];
        uint32_t uh = __float_as_uint(v) & 0xFFFF0000u;
        float l = v - __uint_as_float(uh);
        size_t o = (size_t)(n0 + i) * K + k0 + tx;
        Thi[o] = __ushort_as_bfloat16((unsigned short)(uh >> 16));
        Tlo[o] = __float2bfloat16(l);
    }
}

// ---------------------------------------------------------------------------
// HMMA bf16x3 GEMM: 128x128 CTA, BK=64, 8 warps, 3 stages, 1 barrier/ktile.
// Term-major MMA ordering: each acc written once per 16-MMA pass.
// ---------------------------------------------------------------------------
#define ROWB     144
#define MATB     (128 * ROWB)
#define STAGEB   (4 * MATB)
#define GSMEM    (3 * STAGEB)    // 221184

template <bool HILO>
__global__ __launch_bounds__(256)
void gemm_mma(const __nv_bfloat16* __restrict__ Ahi, const __nv_bfloat16* __restrict__ Alo,
              const __nv_bfloat16* __restrict__ Bhi, const __nv_bfloat16* __restrict__ Blo,
              const float* __restrict__ bias, float* __restrict__ Cf,
              __nv_bfloat16* __restrict__ Ch, __nv_bfloat16* __restrict__ Cl,
              int M, int N, int K)
{
    extern __shared__ char smem[];
    uint32_t sb = smem_u32(smem);
    int t = threadIdx.x, wid = t >> 5, lid = t & 31;
    int m0 = blockIdx.y * 128, n0 = blockIdx.x * 128;
    int wm = wid & 1, wn = wid >> 1;

    const __nv_bfloat16* gp[4] = {
        Ahi + (size_t)m0 * K, Alo + (size_t)m0 * K,
        Bhi + (size_t)n0 * K, Blo + (size_t)n0 * K };

    const int chunk = t & 7;
    const int rb    = t >> 3;

    float acc[4][4][4];
#pragma unroll
    for (int i = 0; i < 4; i++)
#pragma unroll
        for (int j = 0; j < 4; j++)
#pragma unroll
            for (int v = 0; v < 4; v++) acc[i][j][v] = 0.f;

    int nkt = K / 64;

#pragma unroll
    for (int s = 0; s < 2; s++) {
        uint32_t st = sb + s * STAGEB;
        int koff = s * 64;
#pragma unroll
        for (int mat = 0; mat < 4; mat++)
#pragma unroll
            for (int h = 0; h < 4; h++) {
                int row = rb + h * 32;
                cp16(st + mat * MATB + row * ROWB + chunk * 16,
                     gp[mat] + (size_t)row * K + koff + chunk * 8);
            }
        CP_COMMIT();
    }

    int rd = 0, wr = 2;
    for (int kt = 0; kt < nkt; kt++) {
        CP_WAIT1();
        __syncthreads();

        uint32_t st = sb + rd * STAGEB;
        uint32_t aRow = st + (wm * 64) * ROWB;
        uint32_t bRow = st + 2 * MATB + (wn * 32) * ROWB;

#pragma unroll
        for (int k16 = 0; k16 < 4; k16++) {
            int kb = k16 * 32;
            uint32_t ah[4][4], al[4][4], bh[2][4], bl[2][4];
            uint32_t aoff = (uint32_t)(lid & 15) * ROWB + kb + (lid >> 4) * 16;
#pragma unroll
            for (int mt = 0; mt < 4; mt++) {
                uint32_t ad = aRow + mt * 16 * ROWB + aoff;
                ldsm4(ah[mt], ad);
                ldsm4(al[mt], ad + MATB);
            }
            uint32_t brow = ((lid >> 4) & 1) * 8 + (lid & 7);
            uint32_t boff = brow * ROWB + kb + ((lid >> 3) & 1) * 16;
#pragma unroll
            for (int p = 0; p < 2; p++) {
                uint32_t bd = bRow + p * 16 * ROWB + boff;
                ldsm4(bh[p], bd);
                ldsm4(bl[p], bd + MATB);
            }
            // term-major passes: each acc touched once per 16-MMA pass
#pragma unroll
            for (int mt = 0; mt < 4; mt++) {
                mma16816(acc[mt][0], ah[mt], &bh[0][0]);
                mma16816(acc[mt][1], ah[mt], &bh[0][2]);
                mma16816(acc[mt][2], ah[mt], &bh[1][0]);
                mma16816(acc[mt][3], ah[mt], &bh[1][2]);
            }
#pragma unroll
            for (int mt = 0; mt < 4; mt++) {
                mma16816(acc[mt][0], ah[mt], &bl[0][0]);
                mma16816(acc[mt][1], ah[mt], &bl[0][2]);
                mma16816(acc[mt][2], ah[mt], &bl[1][0]);
                mma16816(acc[mt][3], ah[mt], &bl[1][2]);
            }
#pragma unroll
            for (int mt = 0; mt < 4; mt++) {
                mma16816(acc[mt][0], al[mt], &bh[0][0]);
                mma16816(acc[mt][1], al[mt], &bh[0][2]);
                mma16816(acc[mt][2], al[mt], &bh[1][0]);
                mma16816(acc[mt][3], al[mt], &bh[1][2]);
            }
        }

        if (kt + 2 < nkt) {
            uint32_t st2 = sb + wr * STAGEB;
            int koff = (kt + 2) * 64;
#pragma unroll
            for (int mat = 0; mat < 4; mat++)
#pragma unroll
                for (int h = 0; h < 4; h++) {
                    int row = rb + h * 32;
                    cp16(st2 + mat * MATB + row * ROWB + chunk * 16,
                         gp[mat] + (size_t)row * K + koff + chunk * 8);
                }
        }
        CP_COMMIT();
        rd = (rd == 2) ? 0 : rd + 1;
        wr = (wr == 2) ? 0 : wr + 1;
    }

    int rA = m0 + wm * 64 + (lid >> 2);
    int cA = n0 + wn * 32 + 2 * (lid & 3);
#pragma unroll
    for (int mt = 0; mt < 4; mt++) {
        int r = rA + mt * 16;
#pragma unroll
        for (int nt = 0; nt < 4; nt++) {
            int c = cA + nt * 8;
            float b0 = bias[c], b1 = bias[c + 1];
            float v00 = acc[mt][nt][0] + b0, v01 = acc[mt][nt][1] + b1;
            float v10 = acc[mt][nt][2] + b0, v11 = acc[mt][nt][3] + b1;
            if (HILO) {
                uint32_t h, l;
                split2(v00, v01, h, l);
                *(uint32_t*)(Ch + (size_t)r * N + c) = h;
                *(uint32_t*)(Cl + (size_t)r * N + c) = l;
                split2(v10, v11, h, l);
                *(uint32_t*)(Ch + (size_t)(r + 8) * N + c) = h;
                *(uint32_t*)(Cl + (size_t)(r + 8) * N + c) = l;
            } else {
                float2 w0 = {v00, v01}, w1 = {v10, v11};
                *(float2*)(Cf + (size_t)r * N + c)       = w0;
                *(float2*)(Cf + (size_t)(r + 8) * N + c) = w1;
            }
        }
    }
}

// ---------------------------------------------------------------------------
// Tensor-core causal flash attention. Per CTA: one (b,h), 128 q-rows,
// 8 warps x 16 rows, 64-token K tiles, 2-stage KV pipeline.
// ---------------------------------------------------------------------------
#define FROWB   144
#define QMATB   (128 * FROWB)        // 18432
#define FMATB   (64 * FROWB)         // 9216
#define FSTAGE  (4 * FMATB)          // 36864
#define FSMEM   (2 * QMATB + 2 * FSTAGE)  // 110592
#define SCALE_L2E 0.18033688011112042f

__global__ __launch_bounds__(256)
void flash_mma(const __nv_bfloat16* __restrict__ qkvh,
               const __nv_bfloat16* __restrict__ qkvl,
               __nv_bfloat16* __restrict__ atth,
               __nv_bfloat16* __restrict__ attl)
{
    extern __shared__ char smem[];
    uint32_t sb = smem_u32(smem);
    int t = threadIdx.x, wid = t >> 5, lid = t & 31;
    int bh = blockIdx.x;
    int b = bh >> 4, hh = bh & 15;
    int qt = (int)gridDim.y - 1 - blockIdx.y;   // heavy tiles first
    int qbase = qt * 128;
    int tok0 = b * S_LEN;

    const uint32_t QH = sb, QL = sb + QMATB;
    const uint32_t KV0 = sb + 2 * QMATB;

    // Q loaders: 2 threads/row
    const int qlrow  = t >> 1;
    const int qlcol0 = (t & 1) * 4;
    // KV loaders: 4 threads/row
    const int klrow  = t >> 2;
    const int klcol0 = (t & 3) * 2;

    // prologue: Q tile + KV stage 0
    {
        size_t rq = (size_t)(tok0 + qbase + qlrow) * E3 + hh * 64;
#pragma unroll
        for (int u = 0; u < 4; u++) {
            int ch = qlcol0 + u;
            cp16(QH + qlrow * FROWB + ch * 16, qkvh + rq + ch * 8);
            cp16(QL + qlrow * FROWB + ch * 16, qkvl + rq + ch * 8);
        }
        size_t rk = (size_t)(tok0 + klrow) * E3 + 1024 + hh * 64;
#pragma unroll
        for (int u = 0; u < 2; u++) {
            int ch = klcol0 + u;
            uint32_t d = klrow * FROWB + ch * 16;
            cp16(KV0 + d,             qkvh + rk + ch * 8);
            cp16(KV0 + FMATB + d,     qkvl + rk + ch * 8);
            cp16(KV0 + 2 * FMATB + d, qkvh + rk + 1024 + ch * 8);
            cp16(KV0 + 3 * FMATB + d, qkvl + rk + 1024 + ch * 8);
        }
    }
    CP_COMMIT();

    const uint32_t aoff_base = (uint32_t)(lid & 15) * FROWB + (lid >> 4) * 16
                               + (uint32_t)wid * 16 * FROWB;
    const uint32_t brow = ((lid >> 4) & 1) * 8 + (lid & 7);
    const uint32_t boff = brow * FROWB + ((lid >> 3) & 1) * 16;
    const uint32_t vrow = ((lid >> 3) & 1) * 8 + (lid & 7);
    const uint32_t voff = vrow * FROWB + ((lid >> 4) & 1) * 16;

    uint32_t qh[4][4], ql[4][4];
    float o[8][4];
#pragma unroll
    for (int n = 0; n < 8; n++)
#pragma unroll
        for (int v = 0; v < 4; v++) o[n][v] = 0.f;
    float m_lo = -CUDART_INF_F, m_hi = -CUDART_INF_F, l_lo = 0.f, l_hi = 0.f;

    const int rlo = lid >> 2;
    const int rloc = 16 * (wid & 3) + rlo;      // row within warp's 64-block
    const int mycol0 = 2 * (lid & 3);
    const int kt_d = 2 * qt + (wid >> 2);       // this warp's diagonal tile
    const int ntiles = 2 * qt + 2;

    for (int kt = 0; kt < ntiles; kt++) {
        if (kt + 1 < ntiles) {
            uint32_t st = KV0 + ((kt + 1) & 1) * FSTAGE;
            size_t rk = (size_t)(tok0 + (kt + 1) * 64 + klrow) * E3 + 1024 + hh * 64;
#pragma unroll
            for (int u = 0; u < 2; u++) {
                int ch = klcol0 + u;
                uint32_t d = klrow * FROWB + ch * 16;
                cp16(st + d,             qkvh + rk + ch * 8);
                cp16(st + FMATB + d,     qkvl + rk + ch * 8);
                cp16(st + 2 * FMATB + d, qkvh + rk + 1024 + ch * 8);
                cp16(st + 3 * FMATB + d, qkvl + rk + 1024 + ch * 8);
            }
        }
        CP_COMMIT();
        CP_WAIT1();
        __syncthreads();

        if (kt == 0) {
#pragma unroll
            for (int ks = 0; ks < 4; ks++) {
                uint32_t ad = QH + aoff_base + ks * 32;
                ldsm4(qh[ks], ad);
                ldsm4(ql[ks], ad + QMATB);
            }
        }

        if (kt <= kt_d) {
            uint32_t st = KV0 + (kt & 1) * FSTAGE;

            // ---- S = Q K^T (pairs of n-tiles -> 4 live acc targets) ----
            float s[8][4];
#pragma unroll
            for (int n = 0; n < 8; n++)
#pragma unroll
                for (int v = 0; v < 4; v++) s[n][v] = 0.f;

#pragma unroll
            for (int ks = 0; ks < 4; ks++) {
#pragma unroll
                for (int pp = 0; pp < 2; pp++) {
                    int p0 = pp * 2;
                    uint32_t ka0 = st + p0 * 16 * FROWB + boff + ks * 32;
                    uint32_t ka1 = ka0 + 16 * FROWB;
                    uint32_t kh0[4], kl0[4], kh1[4], kl1[4];
                    ldsm4(kh0, ka0);
                    ldsm4(kl0, ka0 + FMATB);
                    ldsm4(kh1, ka1);
                    ldsm4(kl1, ka1 + FMATB);
                    mma16816(s[2 * p0],     qh[ks], &kh0[0]);
                    mma16816(s[2 * p0 + 1], qh[ks], &kh0[2]);
                    mma16816(s[2 * p0 + 2], qh[ks], &kh1[0]);
                    mma16816(s[2 * p0 + 3], qh[ks], &kh1[2]);
                    mma16816(s[2 * p0],     qh[ks], &kl0[0]);
                    mma16816(s[2 * p0 + 1], qh[ks], &kl0[2]);
                    mma16816(s[2 * p0 + 2], qh[ks], &kl1[0]);
                    mma16816(s[2 * p0 + 3], qh[ks], &kl1[2]);
                    mma16816(s[2 * p0],     ql[ks], &kh0[0]);
                    mma16816(s[2 * p0 + 1], ql[ks], &kh0[2]);
                    mma16816(s[2 * p0 + 2], ql[ks], &kh1[0]);
                    mma16816(s[2 * p0 + 3], ql[ks], &kh1[2]);
                }
            }

#pragma unroll
            for (int n = 0; n < 8; n++)
#pragma unroll
                for (int v = 0; v < 4; v++) s[n][v] *= SCALE_L2E;

            if (kt == kt_d) {
#pragma unroll
                for (int n = 0; n < 8; n++) {
                    int c0 = n * 8 + mycol0;
                    if (c0 > rloc)     s[n][0] = -CUDART_INF_F;
                    if (c0 + 1 > rloc) s[n][1] = -CUDART_INF_F;
                    if (c0 > rloc + 8)     s[n][2] = -CUDART_INF_F;
                    if (c0 + 1 > rloc + 8) s[n][3] = -CUDART_INF_F;
                }
            }

            // ---- online softmax ----
            float mt_lo = -CUDART_INF_F, mt_hi = -CUDART_INF_F;
#pragma unroll
            for (int n = 0; n < 8; n++) {
                mt_lo = fmaxf(mt_lo, fmaxf(s[n][0], s[n][1]));
                mt_hi = fmaxf(mt_hi, fmaxf(s[n][2], s[n][3]));
            }
            mt_lo = fmaxf(mt_lo, __shfl_xor_sync(0xffffffffu, mt_lo, 1));
            mt_lo = fmaxf(mt_lo, __shfl_xor_sync(0xffffffffu, mt_lo, 2));
            mt_hi = fmaxf(mt_hi, __shfl_xor_sync(0xffffffffu, mt_hi, 1));
            mt_hi = fmaxf(mt_hi, __shfl_xor_sync(0xffffffffu, mt_hi, 2));

            float mn_lo = fmaxf(m_lo, mt_lo), mn_hi = fmaxf(m_hi, mt_hi);
            float a_lo = exp2f(m_lo - mn_lo), a_hi = exp2f(m_hi - mn_hi);
            m_lo = mn_lo; m_hi = mn_hi;

            float rs_lo = 0.f, rs_hi = 0.f;
#pragma unroll
            for (int n = 0; n < 8; n++) {
                s[n][0] = exp2f(s[n][0] - mn_lo);
                s[n][1] = exp2f(s[n][1] - mn_lo);
                s[n][2] = exp2f(s[n][2] - mn_hi);
                s[n][3] = exp2f(s[n][3] - mn_hi);
                rs_lo += s[n][0] + s[n][1];
                rs_hi += s[n][2] + s[n][3];
            }
            rs_lo += __shfl_xor_sync(0xffffffffu, rs_lo, 1);
            rs_lo += __shfl_xor_sync(0xffffffffu, rs_lo, 2);
            rs_hi += __shfl_xor_sync(0xffffffffu, rs_hi, 1);
            rs_hi += __shfl_xor_sync(0xffffffffu, rs_hi, 2);
            l_lo = a_lo * l_lo + rs_lo;
            l_hi = a_hi * l_hi + rs_hi;
#pragma unroll
            for (int n = 0; n < 8; n++) {
                o[n][0] *= a_lo; o[n][1] *= a_lo;
                o[n][2] *= a_hi; o[n][3] *= a_hi;
            }

            // ---- O += P V (pairs of d-tiles) ----
            uint32_t vbase = st + 2 * FMATB;
#pragma unroll
            for (int ks = 0; ks < 4; ks++) {
                uint32_t ph[4], pl[4];
                split2(s[2 * ks][0],     s[2 * ks][1],     ph[0], pl[0]);
                split2(s[2 * ks][2],     s[2 * ks][3],     ph[1], pl[1]);
                split2(s[2 * ks + 1][0], s[2 * ks + 1][1], ph[2], pl[2]);
                split2(s[2 * ks + 1][2], s[2 * ks + 1][3], ph[3], pl[3]);
#pragma unroll
                for (int pp = 0; pp < 2; pp++) {
                    int p0 = pp * 2;
                    uint32_t va0 = vbase + ks * 16 * FROWB + voff + p0 * 32;
                    uint32_t va1 = va0 + 32;
                    uint32_t vh0[4], vl0[4], vh1[4], vl1[4];
                    ldsm4t(vh0, va0);
                    ldsm4t(vl0, va0 + FMATB);
                    ldsm4t(vh1, va1);
                    ldsm4t(vl1, va1 + FMATB);
                    mma16816(o[2 * p0],     ph, &vh0[0]);
                    mma16816(o[2 * p0 + 1], ph, &vh0[2]);
                    mma16816(o[2 * p0 + 2], ph, &vh1[0]);
                    mma16816(o[2 * p0 + 3], ph, &vh1[2]);
                    mma16816(o[2 * p0],     ph, &vl0[0]);
                    mma16816(o[2 * p0 + 1], ph, &vl0[2]);
                    mma16816(o[2 * p0 + 2], ph, &vl1[0]);
                    mma16816(o[2 * p0 + 3], ph, &vl1[2]);
                    mma16816(o[2 * p0],     pl, &vh0[0]);
                    mma16816(o[2 * p0 + 1], pl, &vh0[2]);
                    mma16816(o[2 * p0 + 2], pl, &vh1[0]);
                    mma16816(o[2 * p0 + 3], pl, &vh1[2]);
                }
            }
        }
        __syncthreads();
    }

    // ---- epilogue ----
    float inv_lo = 1.f / l_lo, inv_hi = 1.f / l_hi;
    int tok_lo = tok0 + qbase + wid * 16 + rlo;
    int tok_hi = tok_lo + 8;
#pragma unroll
    for (int n = 0; n < 8; n++) {
        int c = hh * 64 + n * 8 + mycol0;
        uint32_t h, l;
        split2(o[n][0] * inv_lo, o[n][1] * inv_lo, h, l);
        *(uint32_t*)(atth + (size_t)tok_lo * N_EMBD + c) = h;
        *(uint32_t*)(attl + (size_t)tok_lo * N_EMBD + c) = l;
        split2(o[n][2] * inv_hi, o[n][3] * inv_hi, h, l);
        *(uint32_t*)(atth + (size_t)tok_hi * N_EMBD + c) = h;
        *(uint32_t*)(attl + (size_t)tok_hi * N_EMBD + c) = l;
    }
}

// ---------------------------------------------------------------------------
extern "C" void kernel_launch(void* const* d_in, const int* in_sizes, int n_in,
                              void* d_out, int out_size)
{
    const float* x      = (const float*)d_in[0];
    const float* W_attn = (const float*)d_in[1];
    const float* b_attn = (const float*)d_in[2];
    const float* W_proj = (const float*)d_in[3];
    const float* b_proj = (const float*)d_in[4];
    float* out = (float*)d_out;

    __nv_bfloat16 *xhi, *xlo, *qkvh, *qkvl, *atth, *attl, *wahi, *walo, *wphi, *wplo;
    cudaGetSymbolAddress((void**)&xhi, g_xhi);
    cudaGetSymbolAddress((void**)&xlo, g_xlo);
    cudaGetSymbolAddress((void**)&qkvh, g_qkvh);
    cudaGetSymbolAddress((void**)&qkvl, g_qkvl);
    cudaGetSymbolAddress((void**)&atth, g_atth);
    cudaGetSymbolAddress((void**)&attl, g_attl);
    cudaGetSymbolAddress((void**)&wahi, g_wahi);
    cudaGetSymbolAddress((void**)&walo, g_walo);
    cudaGetSymbolAddress((void**)&wphi, g_wphi);
    cudaGetSymbolAddress((void**)&wplo, g_wplo);

    cudaFuncSetAttribute(gemm_mma<true>,
                         cudaFuncAttributeMaxDynamicSharedMemorySize, GSMEM);
    cudaFuncSetAttribute(gemm_mma<false>,
                         cudaFuncAttributeMaxDynamicSharedMemorySize, GSMEM);
    cudaFuncSetAttribute(flash_mma,
                         cudaFuncAttributeMaxDynamicSharedMemorySize, FSMEM);

    cvt_hilo<<<(M_ROWS * N_EMBD / 4 + 255) / 256, 256>>>(x, xhi, xlo, M_ROWS * N_EMBD / 4);
    cvt_t_hilo<<<dim3(E3 / 32, N_EMBD / 32), dim3(32, 8)>>>(W_attn, wahi, walo, N_EMBD, E3);
    cvt_t_hilo<<<dim3(N_EMBD / 32, N_EMBD / 32), dim3(32, 8)>>>(W_proj, wphi, wplo, N_EMBD, N_EMBD);

    gemm_mma<true><<<dim3(E3 / 128, M_ROWS / 128), 256, GSMEM>>>(
        xhi, xlo, wahi, walo, b_attn, nullptr, qkvh, qkvl, M_ROWS, E3, N_EMBD);

    flash_mma<<<dim3(2 * N_HEADS, S_LEN / 128), 256, FSMEM>>>(qkvh, qkvl, atth, attl);

    gemm_mma<false><<<dim3(N_EMBD / 128, M_ROWS / 128), 256, GSMEM>>>(
        atth, attl, wphi, wplo, b_proj, out, nullptr, nullptr, M_ROWS, N_EMBD, N_EMBD);
}

// round 7
// speedup vs baseline: 3.5116x; 1.0769x over previous
#include <cuda_runtime.h>
#include <cuda_bf16.h>
#include <math_constants.h>
#include <cstdint>

// ---------------------------------------------------------------------------
// MultiHeadAttention, B=2,S=2048,H=16,D=64,E=1024. HMMA everywhere with
// bf16 hi/lo 3-term split precision.
//   1) qkv(hi,lo) = split( x @ W_attn + b_attn )
//   2) att(hi,lo) = split( flash(qkv) )   [128-row Q tiles, 8 warps]
//   3) out        = att @ W_proj + b_proj
// GEMM: BK=32, XOR-swizzled smem (no padding) -> 96KB/CTA -> 2 CTAs/SM
// (round-6 limiter: 2 warps/SMSP cannot hide LDSM latency + barriers).
// ---------------------------------------------------------------------------

#define S_LEN   2048
#define N_EMBD  1024
#define E3      3072
#define N_HEADS 16
#define M_ROWS  4096

__device__ __nv_bfloat16 g_xhi[(size_t)M_ROWS * N_EMBD];
__device__ __nv_bfloat16 g_xlo[(size_t)M_ROWS * N_EMBD];
__device__ __nv_bfloat16 g_qkvh[(size_t)M_ROWS * E3];
__device__ __nv_bfloat16 g_qkvl[(size_t)M_ROWS * E3];
__device__ __nv_bfloat16 g_atth[(size_t)M_ROWS * N_EMBD];
__device__ __nv_bfloat16 g_attl[(size_t)M_ROWS * N_EMBD];
__device__ __nv_bfloat16 g_wahi[(size_t)E3 * N_EMBD];
__device__ __nv_bfloat16 g_walo[(size_t)E3 * N_EMBD];
__device__ __nv_bfloat16 g_wphi[(size_t)N_EMBD * N_EMBD];
__device__ __nv_bfloat16 g_wplo[(size_t)N_EMBD * N_EMBD];

// ------------------------- helpers ------------------------------------------
__device__ __forceinline__ uint32_t smem_u32(const void* p) {
    uint32_t a;
    asm("{ .reg .u64 t; cvta.to.shared.u64 t, %1; cvt.u32.u64 %0, t; }"
        : "=r"(a) : "l"(p));
    return a;
}
__device__ __forceinline__ void cp16(uint32_t dst, const void* src) {
    asm volatile("cp.async.cg.shared.global [%0], [%1], 16;" :: "r"(dst), "l"(src));
}
#define CP_COMMIT() asm volatile("cp.async.commit_group;" ::: "memory")
#define CP_WAIT1()  asm volatile("cp.async.wait_group 1;"  ::: "memory")

__device__ __forceinline__ void ldsm4(uint32_t* r, uint32_t addr) {
    asm volatile("ldmatrix.sync.aligned.m8n8.x4.shared.b16 {%0,%1,%2,%3}, [%4];"
                 : "=r"(r[0]), "=r"(r[1]), "=r"(r[2]), "=r"(r[3]) : "r"(addr));
}
__device__ __forceinline__ void ldsm4t(uint32_t* r, uint32_t addr) {
    asm volatile("ldmatrix.sync.aligned.m8n8.x4.trans.shared.b16 {%0,%1,%2,%3}, [%4];"
                 : "=r"(r[0]), "=r"(r[1]), "=r"(r[2]), "=r"(r[3]) : "r"(addr));
}
__device__ __forceinline__ void mma16816(float* d, const uint32_t* a, const uint32_t* b) {
    asm volatile(
        "mma.sync.aligned.m16n8k16.row.col.f32.bf16.bf16.f32 "
        "{%0,%1,%2,%3}, {%4,%5,%6,%7}, {%8,%9}, {%0,%1,%2,%3};"
        : "+f"(d[0]), "+f"(d[1]), "+f"(d[2]), "+f"(d[3])
        : "r"(a[0]), "r"(a[1]), "r"(a[2]), "r"(a[3]), "r"(b[0]), "r"(b[1]));
}
// fast split: truncation hi + exact residual lo
__device__ __forceinline__ void split2(float a, float b, uint32_t& hi, uint32_t& lo) {
    uint32_t ua = __float_as_uint(a) & 0xFFFF0000u;
    uint32_t ub = __float_as_uint(b) & 0xFFFF0000u;
    hi = __byte_perm(ua, ub, 0x7632);
    float la = a - __uint_as_float(ua);
    float lb = b - __uint_as_float(ub);
    asm("cvt.rn.bf16x2.f32 %0, %1, %2;" : "=r"(lo) : "f"(lb), "f"(la));
}

// ---------------------------------------------------------------------------
__global__ void cvt_hilo(const float* __restrict__ in, __nv_bfloat16* __restrict__ hi,
                         __nv_bfloat16* __restrict__ lo, int n4)
{
    int i = blockIdx.x * blockDim.x + threadIdx.x;
    if (i >= n4) return;
    float4 v = ((const float4*)in)[i];
    uint32_t h0, l0, h1, l1;
    split2(v.x, v.y, h0, l0);
    split2(v.z, v.w, h1, l1);
    uint2 hv = {h0, h1}, lv = {l0, l1};
    ((uint2*)hi)[i] = hv;
    ((uint2*)lo)[i] = lv;
}

__global__ void cvt_t_hilo(const float* __restrict__ W, __nv_bfloat16* __restrict__ Thi,
                           __nv_bfloat16* __restrict__ Tlo, int K, int N)
{
    __shared__ float tile[32][33];
    int k0 = blockIdx.y * 32, n0 = blockIdx.x * 32;
    int tx = threadIdx.x, ty = threadIdx.y;
#pragma unroll
    for (int i = ty; i < 32; i += 8)
        tile[i][tx] = W[(size_t)(k0 + i) * N + n0 + tx];
    __syncthreads();
#pragma unroll
    for (int i = ty; i < 32; i += 8) {
        float v = tile[tx][i];
        uint32_t uh = __float_as_uint(v) & 0xFFFF0000u;
        float l = v - __uint_as_float(uh);
        size_t o = (size_t)(n0 + i) * K + k0 + tx;
        Thi[o] = __ushort_as_bfloat16((unsigned short)(uh >> 16));
        Tlo[o] = __float2bfloat16(l);
    }
}

// ---------------------------------------------------------------------------
// HMMA bf16x3 GEMM: 128x128 CTA, BK=32, 8 warps (64x32), 3 stages,
// XOR-swizzled 64B rows (no pad), 1 barrier/ktile, 2 CTAs/SM.
// Swizzle: 16B chunk c at row r lives at chunk c ^ ((r>>1)&3).
// ---------------------------------------------------------------------------
#define MATB   8192              // 128 rows * 64B
#define STAGEB (4 * MATB)        // 32768
#define GSMEM  (3 * STAGEB)      // 98304

template <bool HILO>
__global__ __launch_bounds__(256, 2)
void gemm_mma(const __nv_bfloat16* __restrict__ Ahi, const __nv_bfloat16* __restrict__ Alo,
              const __nv_bfloat16* __restrict__ Bhi, const __nv_bfloat16* __restrict__ Blo,
              const float* __restrict__ bias, float* __restrict__ Cf,
              __nv_bfloat16* __restrict__ Ch, __nv_bfloat16* __restrict__ Cl,
              int M, int N, int K)
{
    extern __shared__ char smem[];
    uint32_t sb = smem_u32(smem);
    int t = threadIdx.x, wid = t >> 5, lid = t & 31;
    int m0 = blockIdx.y * 128, n0 = blockIdx.x * 128;
    int wm = wid & 1, wn = wid >> 1;

    const __nv_bfloat16* gp[4] = {
        Ahi + (size_t)m0 * K, Alo + (size_t)m0 * K,
        Bhi + (size_t)n0 * K, Blo + (size_t)n0 * K };

    // loader lanes: chunk lc (16B) in 64B row, rows lr and lr+64
    const int lc = t & 3;
    const int lr = t >> 2;
    const uint32_t wofs0 = lr * 64 + ((lc ^ ((lr >> 1) & 3)) << 4);
    const uint32_t wofs1 = (lr + 64) * 64 + ((lc ^ (((lr + 64) >> 1) & 3)) << 4);

    float acc[4][4][4];
#pragma unroll
    for (int i = 0; i < 4; i++)
#pragma unroll
        for (int j = 0; j < 4; j++)
#pragma unroll
            for (int v = 0; v < 4; v++) acc[i][j][v] = 0.f;

    int nkt = K / 32;

    // prologue: stages 0,1
#pragma unroll
    for (int s = 0; s < 2; s++) {
        uint32_t st = sb + s * STAGEB;
        int koff = s * 32;
#pragma unroll
        for (int mat = 0; mat < 4; mat++) {
            cp16(st + mat * MATB + wofs0, gp[mat] + (size_t)lr * K + koff + lc * 8);
            cp16(st + mat * MATB + wofs1, gp[mat] + (size_t)(lr + 64) * K + koff + lc * 8);
        }
        CP_COMMIT();
    }

    // fragment lane constants
    const int arow = lid & 15, asel = lid >> 4;
    const int axor = (arow >> 1) & 3;
    const int browl = ((lid >> 4) & 1) * 8 + (lid & 7);
    const int bsel = (lid >> 3) & 1;
    const int bxor = (browl >> 1) & 3;

    int rd = 0, wr = 2;
    for (int kt = 0; kt < nkt; kt++) {
        CP_WAIT1();
        __syncthreads();

        uint32_t st = sb + rd * STAGEB;

#pragma unroll
        for (int kb = 0; kb < 2; kb++) {
            uint32_t ah[4][4], al[4][4];
#pragma unroll
            for (int mt = 0; mt < 4; mt++) {
                uint32_t ad = st + (uint32_t)(wm * 64 + mt * 16 + arow) * 64
                              + (uint32_t)(((kb * 2 + asel) ^ axor) << 4);
                ldsm4(ah[mt], ad);
                ldsm4(al[mt], ad + MATB);
            }
#pragma unroll
            for (int p = 0; p < 2; p++) {
                uint32_t bd = st + 2 * MATB
                              + (uint32_t)(wn * 32 + p * 16 + browl) * 64
                              + (uint32_t)(((kb * 2 + bsel) ^ bxor) << 4);
                uint32_t bh[4], bl[4];
                ldsm4(bh, bd);
                ldsm4(bl, bd + MATB);
#pragma unroll
                for (int mt = 0; mt < 4; mt++) {
                    mma16816(acc[mt][2 * p],     ah[mt], &bh[0]);
                    mma16816(acc[mt][2 * p + 1], ah[mt], &bh[2]);
                }
#pragma unroll
                for (int mt = 0; mt < 4; mt++) {
                    mma16816(acc[mt][2 * p],     ah[mt], &bl[0]);
                    mma16816(acc[mt][2 * p + 1], ah[mt], &bl[2]);
                }
#pragma unroll
                for (int mt = 0; mt < 4; mt++) {
                    mma16816(acc[mt][2 * p],     al[mt], &bh[0]);
                    mma16816(acc[mt][2 * p + 1], al[mt], &bh[2]);
                }
            }
        }

        // issue loads for ktile kt+2 (stage wr == (kt-1)%3, drained by this
        // iteration's barrier)
        if (kt + 2 < nkt) {
            uint32_t st2 = sb + wr * STAGEB;
            int koff = (kt + 2) * 32;
#pragma unroll
            for (int mat = 0; mat < 4; mat++) {
                cp16(st2 + mat * MATB + wofs0, gp[mat] + (size_t)lr * K + koff + lc * 8);
                cp16(st2 + mat * MATB + wofs1, gp[mat] + (size_t)(lr + 64) * K + koff + lc * 8);
            }
        }
        CP_COMMIT();
        rd = (rd == 2) ? 0 : rd + 1;
        wr = (wr == 2) ? 0 : wr + 1;
    }

    int rA = m0 + wm * 64 + (lid >> 2);
    int cA = n0 + wn * 32 + 2 * (lid & 3);
#pragma unroll
    for (int mt = 0; mt < 4; mt++) {
        int r = rA + mt * 16;
#pragma unroll
        for (int nt = 0; nt < 4; nt++) {
            int c = cA + nt * 8;
            float b0 = bias[c], b1 = bias[c + 1];
            float v00 = acc[mt][nt][0] + b0, v01 = acc[mt][nt][1] + b1;
            float v10 = acc[mt][nt][2] + b0, v11 = acc[mt][nt][3] + b1;
            if (HILO) {
                uint32_t h, l;
                split2(v00, v01, h, l);
                *(uint32_t*)(Ch + (size_t)r * N + c) = h;
                *(uint32_t*)(Cl + (size_t)r * N + c) = l;
                split2(v10, v11, h, l);
                *(uint32_t*)(Ch + (size_t)(r + 8) * N + c) = h;
                *(uint32_t*)(Cl + (size_t)(r + 8) * N + c) = l;
            } else {
                float2 w0 = {v00, v01}, w1 = {v10, v11};
                *(float2*)(Cf + (size_t)r * N + c)       = w0;
                *(float2*)(Cf + (size_t)(r + 8) * N + c) = w1;
            }
        }
    }
}

// ---------------------------------------------------------------------------
// Tensor-core causal flash attention (unchanged from round 6).
// Per CTA: one (b,h), 128 q-rows, 8 warps x 16 rows, 64-token K tiles.
// ---------------------------------------------------------------------------
#define FROWB   144
#define QMATB   (128 * FROWB)
#define FMATB   (64 * FROWB)
#define FSTAGE  (4 * FMATB)
#define FSMEM   (2 * QMATB + 2 * FSTAGE)  // 110592
#define SCALE_L2E 0.18033688011112042f

__global__ __launch_bounds__(256)
void flash_mma(const __nv_bfloat16* __restrict__ qkvh,
               const __nv_bfloat16* __restrict__ qkvl,
               __nv_bfloat16* __restrict__ atth,
               __nv_bfloat16* __restrict__ attl)
{
    extern __shared__ char smem[];
    uint32_t sb = smem_u32(smem);
    int t = threadIdx.x, wid = t >> 5, lid = t & 31;
    int bh = blockIdx.x;
    int b = bh >> 4, hh = bh & 15;
    int qt = (int)gridDim.y - 1 - blockIdx.y;
    int qbase = qt * 128;
    int tok0 = b * S_LEN;

    const uint32_t QH = sb, QL = sb + QMATB;
    const uint32_t KV0 = sb + 2 * QMATB;

    const int qlrow  = t >> 1;
    const int qlcol0 = (t & 1) * 4;
    const int klrow  = t >> 2;
    const int klcol0 = (t & 3) * 2;

    {
        size_t rq = (size_t)(tok0 + qbase + qlrow) * E3 + hh * 64;
#pragma unroll
        for (int u = 0; u < 4; u++) {
            int ch = qlcol0 + u;
            cp16(QH + qlrow * FROWB + ch * 16, qkvh + rq + ch * 8);
            cp16(QL + qlrow * FROWB + ch * 16, qkvl + rq + ch * 8);
        }
        size_t rk = (size_t)(tok0 + klrow) * E3 + 1024 + hh * 64;
#pragma unroll
        for (int u = 0; u < 2; u++) {
            int ch = klcol0 + u;
            uint32_t d = klrow * FROWB + ch * 16;
            cp16(KV0 + d,             qkvh + rk + ch * 8);
            cp16(KV0 + FMATB + d,     qkvl + rk + ch * 8);
            cp16(KV0 + 2 * FMATB + d, qkvh + rk + 1024 + ch * 8);
            cp16(KV0 + 3 * FMATB + d, qkvl + rk + 1024 + ch * 8);
        }
    }
    CP_COMMIT();

    const uint32_t aoff_base = (uint32_t)(lid & 15) * FROWB + (lid >> 4) * 16
                               + (uint32_t)wid * 16 * FROWB;
    const uint32_t brow = ((lid >> 4) & 1) * 8 + (lid & 7);
    const uint32_t boff = brow * FROWB + ((lid >> 3) & 1) * 16;
    const uint32_t vrow = ((lid >> 3) & 1) * 8 + (lid & 7);
    const uint32_t voff = vrow * FROWB + ((lid >> 4) & 1) * 16;

    uint32_t qh[4][4], ql[4][4];
    float o[8][4];
#pragma unroll
    for (int n = 0; n < 8; n++)
#pragma unroll
        for (int v = 0; v < 4; v++) o[n][v] = 0.f;
    float m_lo = -CUDART_INF_F, m_hi = -CUDART_INF_F, l_lo = 0.f, l_hi = 0.f;

    const int rlo = lid >> 2;
    const int rloc = 16 * (wid & 3) + rlo;
    const int mycol0 = 2 * (lid & 3);
    const int kt_d = 2 * qt + (wid >> 2);
    const int ntiles = 2 * qt + 2;

    for (int kt = 0; kt < ntiles; kt++) {
        if (kt + 1 < ntiles) {
            uint32_t st = KV0 + ((kt + 1) & 1) * FSTAGE;
            size_t rk = (size_t)(tok0 + (kt + 1) * 64 + klrow) * E3 + 1024 + hh * 64;
#pragma unroll
            for (int u = 0; u < 2; u++) {
                int ch = klcol0 + u;
                uint32_t d = klrow * FROWB + ch * 16;
                cp16(st + d,             qkvh + rk + ch * 8);
                cp16(st + FMATB + d,     qkvl + rk + ch * 8);
                cp16(st + 2 * FMATB + d, qkvh + rk + 1024 + ch * 8);
                cp16(st + 3 * FMATB + d, qkvl + rk + 1024 + ch * 8);
            }
        }
        CP_COMMIT();
        CP_WAIT1();
        __syncthreads();

        if (kt == 0) {
#pragma unroll
            for (int ks = 0; ks < 4; ks++) {
                uint32_t ad = QH + aoff_base + ks * 32;
                ldsm4(qh[ks], ad);
                ldsm4(ql[ks], ad + QMATB);
            }
        }

        if (kt <= kt_d) {
            uint32_t st = KV0 + (kt & 1) * FSTAGE;

            float s[8][4];
#pragma unroll
            for (int n = 0; n < 8; n++)
#pragma unroll
                for (int v = 0; v < 4; v++) s[n][v] = 0.f;

#pragma unroll
            for (int ks = 0; ks < 4; ks++) {
#pragma unroll
                for (int pp = 0; pp < 2; pp++) {
                    int p0 = pp * 2;
                    uint32_t ka0 = st + p0 * 16 * FROWB + boff + ks * 32;
                    uint32_t ka1 = ka0 + 16 * FROWB;
                    uint32_t kh0[4], kl0[4], kh1[4], kl1[4];
                    ldsm4(kh0, ka0);
                    ldsm4(kl0, ka0 + FMATB);
                    ldsm4(kh1, ka1);
                    ldsm4(kl1, ka1 + FMATB);
                    mma16816(s[2 * p0],     qh[ks], &kh0[0]);
                    mma16816(s[2 * p0 + 1], qh[ks], &kh0[2]);
                    mma16816(s[2 * p0 + 2], qh[ks], &kh1[0]);
                    mma16816(s[2 * p0 + 3], qh[ks], &kh1[2]);
                    mma16816(s[2 * p0],     qh[ks], &kl0[0]);
                    mma16816(s[2 * p0 + 1], qh[ks], &kl0[2]);
                    mma16816(s[2 * p0 + 2], qh[ks], &kl1[0]);
                    mma16816(s[2 * p0 + 3], qh[ks], &kl1[2]);
                    mma16816(s[2 * p0],     ql[ks], &kh0[0]);
                    mma16816(s[2 * p0 + 1], ql[ks], &kh0[2]);
                    mma16816(s[2 * p0 + 2], ql[ks], &kh1[0]);
                    mma16816(s[2 * p0 + 3], ql[ks], &kh1[2]);
                }
            }

#pragma unroll
            for (int n = 0; n < 8; n++)
#pragma unroll
                for (int v = 0; v < 4; v++) s[n][v] *= SCALE_L2E;

            if (kt == kt_d) {
#pragma unroll
                for (int n = 0; n < 8; n++) {
                    int c0 = n * 8 + mycol0;
                    if (c0 > rloc)     s[n][0] = -CUDART_INF_F;
                    if (c0 + 1 > rloc) s[n][1] = -CUDART_INF_F;
                    if (c0 > rloc + 8)     s[n][2] = -CUDART_INF_F;
                    if (c0 + 1 > rloc + 8) s[n][3] = -CUDART_INF_F;
                }
            }

            float mt_lo = -CUDART_INF_F, mt_hi = -CUDART_INF_F;
#pragma unroll
            for (int n = 0; n < 8; n++) {
                mt_lo = fmaxf(mt_lo, fmaxf(s[n][0], s[n][1]));
                mt_hi = fmaxf(mt_hi, fmaxf(s[n][2], s[n][3]));
            }
            mt_lo = fmaxf(mt_lo, __shfl_xor_sync(0xffffffffu, mt_lo, 1));
            mt_lo = fmaxf(mt_lo, __shfl_xor_sync(0xffffffffu, mt_lo, 2));
            mt_hi = fmaxf(mt_hi, __shfl_xor_sync(0xffffffffu, mt_hi, 1));
            mt_hi = fmaxf(mt_hi, __shfl_xor_sync(0xffffffffu, mt_hi, 2));

            float mn_lo = fmaxf(m_lo, mt_lo), mn_hi = fmaxf(m_hi, mt_hi);
            float a_lo = exp2f(m_lo - mn_lo), a_hi = exp2f(m_hi - mn_hi);
            m_lo = mn_lo; m_hi = mn_hi;

            float rs_lo = 0.f, rs_hi = 0.f;
#pragma unroll
            for (int n = 0; n < 8; n++) {
                s[n][0] = exp2f(s[n][0] - mn_lo);
                s[n][1] = exp2f(s[n][1] - mn_lo);
                s[n][2] = exp2f(s[n][2] - mn_hi);
                s[n][3] = exp2f(s[n][3] - mn_hi);
                rs_lo += s[n][0] + s[n][1];
                rs_hi += s[n][2] + s[n][3];
            }
            rs_lo += __shfl_xor_sync(0xffffffffu, rs_lo, 1);
            rs_lo += __shfl_xor_sync(0xffffffffu, rs_lo, 2);
            rs_hi += __shfl_xor_sync(0xffffffffu, rs_hi, 1);
            rs_hi += __shfl_xor_sync(0xffffffffu, rs_hi, 2);
            l_lo = a_lo * l_lo + rs_lo;
            l_hi = a_hi * l_hi + rs_hi;
#pragma unroll
            for (int n = 0; n < 8; n++) {
                o[n][0] *= a_lo; o[n][1] *= a_lo;
                o[n][2] *= a_hi; o[n][3] *= a_hi;
            }

            uint32_t vbase = st + 2 * FMATB;
#pragma unroll
            for (int ks = 0; ks < 4; ks++) {
                uint32_t ph[4], pl[4];
                split2(s[2 * ks][0],     s[2 * ks][1],     ph[0], pl[0]);
                split2(s[2 * ks][2],     s[2 * ks][3],     ph[1], pl[1]);
                split2(s[2 * ks + 1][0], s[2 * ks + 1][1], ph[2], pl[2]);
                split2(s[2 * ks + 1][2], s[2 * ks + 1][3], ph[3], pl[3]);
#pragma unroll
                for (int pp = 0; pp < 2; pp++) {
                    int p0 = pp * 2;
                    uint32_t va0 = vbase + ks * 16 * FROWB + voff + p0 * 32;
                    uint32_t va1 = va0 + 32;
                    uint32_t vh0[4], vl0[4], vh1[4], vl1[4];
                    ldsm4t(vh0, va0);
                    ldsm4t(vl0, va0 + FMATB);
                    ldsm4t(vh1, va1);
                    ldsm4t(vl1, va1 + FMATB);
                    mma16816(o[2 * p0],     ph, &vh0[0]);
                    mma16816(o[2 * p0 + 1], ph, &vh0[2]);
                    mma16816(o[2 * p0 + 2], ph, &vh1[0]);
                    mma16816(o[2 * p0 + 3], ph, &vh1[2]);
                    mma16816(o[2 * p0],     ph, &vl0[0]);
                    mma16816(o[2 * p0 + 1], ph, &vl0[2]);
                    mma16816(o[2 * p0 + 2], ph, &vl1[0]);
                    mma16816(o[2 * p0 + 3], ph, &vl1[2]);
                    mma16816(o[2 * p0],     pl, &vh0[0]);
                    mma16816(o[2 * p0 + 1], pl, &vh0[2]);
                    mma16816(o[2 * p0 + 2], pl, &vh1[0]);
                    mma16816(o[2 * p0 + 3], pl, &vh1[2]);
                }
            }
        }
        __syncthreads();
    }

    float inv_lo = 1.f / l_lo, inv_hi = 1.f / l_hi;
    int tok_lo = tok0 + qbase + wid * 16 + rlo;
    int tok_hi = tok_lo + 8;
#pragma unroll
    for (int n = 0; n < 8; n++) {
        int c = hh * 64 + n * 8 + mycol0;
        uint32_t h, l;
        split2(o[n][0] * inv_lo, o[n][1] * inv_lo, h, l);
        *(uint32_t*)(atth + (size_t)tok_lo * N_EMBD + c) = h;
        *(uint32_t*)(attl + (size_t)tok_lo * N_EMBD + c) = l;
        split2(o[n][2] * inv_hi, o[n][3] * inv_hi, h, l);
        *(uint32_t*)(atth + (size_t)tok_hi * N_EMBD + c) = h;
        *(uint32_t*)(attl + (size_t)tok_hi * N_EMBD + c) = l;
    }
}

// ---------------------------------------------------------------------------
extern "C" void kernel_launch(void* const* d_in, const int* in_sizes, int n_in,
                              void* d_out, int out_size)
{
    const float* x      = (const float*)d_in[0];
    const float* W_attn = (const float*)d_in[1];
    const float* b_attn = (const float*)d_in[2];
    const float* W_proj = (const float*)d_in[3];
    const float* b_proj = (const float*)d_in[4];
    float* out = (float*)d_out;

    __nv_bfloat16 *xhi, *xlo, *qkvh, *qkvl, *atth, *attl, *wahi, *walo, *wphi, *wplo;
    cudaGetSymbolAddress((void**)&xhi, g_xhi);
    cudaGetSymbolAddress((void**)&xlo, g_xlo);
    cudaGetSymbolAddress((void**)&qkvh, g_qkvh);
    cudaGetSymbolAddress((void**)&qkvl, g_qkvl);
    cudaGetSymbolAddress((void**)&atth, g_atth);
    cudaGetSymbolAddress((void**)&attl, g_attl);
    cudaGetSymbolAddress((void**)&wahi, g_wahi);
    cudaGetSymbolAddress((void**)&walo, g_walo);
    cudaGetSymbolAddress((void**)&wphi, g_wphi);
    cudaGetSymbolAddress((void**)&wplo, g_wplo);

    cudaFuncSetAttribute(gemm_mma<true>,
                         cudaFuncAttributeMaxDynamicSharedMemorySize, GSMEM);
    cudaFuncSetAttribute(gemm_mma<false>,
                         cudaFuncAttributeMaxDynamicSharedMemorySize, GSMEM);
    cudaFuncSetAttribute(flash_mma,
                         cudaFuncAttributeMaxDynamicSharedMemorySize, FSMEM);

    cvt_hilo<<<(M_ROWS * N_EMBD / 4 + 255) / 256, 256>>>(x, xhi, xlo, M_ROWS * N_EMBD / 4);
    cvt_t_hilo<<<dim3(E3 / 32, N_EMBD / 32), dim3(32, 8)>>>(W_attn, wahi, walo, N_EMBD, E3);
    cvt_t_hilo<<<dim3(N_EMBD / 32, N_EMBD / 32), dim3(32, 8)>>>(W_proj, wphi, wplo, N_EMBD, N_EMBD);

    gemm_mma<true><<<dim3(E3 / 128, M_ROWS / 128), 256, GSMEM>>>(
        xhi, xlo, wahi, walo, b_attn, nullptr, qkvh, qkvl, M_ROWS, E3, N_EMBD);

    flash_mma<<<dim3(2 * N_HEADS, S_LEN / 128), 256, FSMEM>>>(qkvh, qkvl, atth, attl);

    gemm_mma<false><<<dim3(N_EMBD / 128, M_ROWS / 128), 256, GSMEM>>>(
        atth, attl, wphi, wplo, b_proj, out, nullptr, nullptr, M_ROWS, N_EMBD, N_EMBD);
}

// round 8
// speedup vs baseline: 3.6943x; 1.0520x over previous
#include <cuda_runtime.h>
#include <cuda_bf16.h>
#include <math_constants.h>
#include <cstdint>

// ---------------------------------------------------------------------------
// MultiHeadAttention, B=2,S=2048,H=16,D=64,E=1024. HMMA everywhere with
// bf16 hi/lo 3-term split precision.
//   1) qkv(hi,lo) = split( x @ W_attn + b_attn )
//   2) att(hi,lo) = split( flash(qkv) )   [128-row Q tiles, 8 warps]
//   3) out        = att @ W_proj + b_proj
// GEMM: BK=32, XOR-swizzled smem, 96KB/CTA, 2 CTAs/SM (round 7).
// Flash: XOR-swizzled smem (no pad) -> 96KB/CTA -> 2 CTAs/SM; ql fragments
// reloaded from smem to fit the 128-reg budget (round 8).
// ---------------------------------------------------------------------------

#define S_LEN   2048
#define N_EMBD  1024
#define E3      3072
#define N_HEADS 16
#define M_ROWS  4096

__device__ __nv_bfloat16 g_xhi[(size_t)M_ROWS * N_EMBD];
__device__ __nv_bfloat16 g_xlo[(size_t)M_ROWS * N_EMBD];
__device__ __nv_bfloat16 g_qkvh[(size_t)M_ROWS * E3];
__device__ __nv_bfloat16 g_qkvl[(size_t)M_ROWS * E3];
__device__ __nv_bfloat16 g_atth[(size_t)M_ROWS * N_EMBD];
__device__ __nv_bfloat16 g_attl[(size_t)M_ROWS * N_EMBD];
__device__ __nv_bfloat16 g_wahi[(size_t)E3 * N_EMBD];
__device__ __nv_bfloat16 g_walo[(size_t)E3 * N_EMBD];
__device__ __nv_bfloat16 g_wphi[(size_t)N_EMBD * N_EMBD];
__device__ __nv_bfloat16 g_wplo[(size_t)N_EMBD * N_EMBD];

// ------------------------- helpers ------------------------------------------
__device__ __forceinline__ uint32_t smem_u32(const void* p) {
    uint32_t a;
    asm("{ .reg .u64 t; cvta.to.shared.u64 t, %1; cvt.u32.u64 %0, t; }"
        : "=r"(a) : "l"(p));
    return a;
}
__device__ __forceinline__ void cp16(uint32_t dst, const void* src) {
    asm volatile("cp.async.cg.shared.global [%0], [%1], 16;" :: "r"(dst), "l"(src));
}
#define CP_COMMIT() asm volatile("cp.async.commit_group;" ::: "memory")
#define CP_WAIT1()  asm volatile("cp.async.wait_group 1;"  ::: "memory")

__device__ __forceinline__ void ldsm4(uint32_t* r, uint32_t addr) {
    asm volatile("ldmatrix.sync.aligned.m8n8.x4.shared.b16 {%0,%1,%2,%3}, [%4];"
                 : "=r"(r[0]), "=r"(r[1]), "=r"(r[2]), "=r"(r[3]) : "r"(addr));
}
__device__ __forceinline__ void ldsm4t(uint32_t* r, uint32_t addr) {
    asm volatile("ldmatrix.sync.aligned.m8n8.x4.trans.shared.b16 {%0,%1,%2,%3}, [%4];"
                 : "=r"(r[0]), "=r"(r[1]), "=r"(r[2]), "=r"(r[3]) : "r"(addr));
}
__device__ __forceinline__ void mma16816(float* d, const uint32_t* a, const uint32_t* b) {
    asm volatile(
        "mma.sync.aligned.m16n8k16.row.col.f32.bf16.bf16.f32 "
        "{%0,%1,%2,%3}, {%4,%5,%6,%7}, {%8,%9}, {%0,%1,%2,%3};"
        : "+f"(d[0]), "+f"(d[1]), "+f"(d[2]), "+f"(d[3])
        : "r"(a[0]), "r"(a[1]), "r"(a[2]), "r"(a[3]), "r"(b[0]), "r"(b[1]));
}
// fast split: truncation hi + exact residual lo
__device__ __forceinline__ void split2(float a, float b, uint32_t& hi, uint32_t& lo) {
    uint32_t ua = __float_as_uint(a) & 0xFFFF0000u;
    uint32_t ub = __float_as_uint(b) & 0xFFFF0000u;
    hi = __byte_perm(ua, ub, 0x7632);
    float la = a - __uint_as_float(ua);
    float lb = b - __uint_as_float(ub);
    asm("cvt.rn.bf16x2.f32 %0, %1, %2;" : "=r"(lo) : "f"(lb), "f"(la));
}

// ---------------------------------------------------------------------------
__global__ void cvt_hilo(const float* __restrict__ in, __nv_bfloat16* __restrict__ hi,
                         __nv_bfloat16* __restrict__ lo, int n4)
{
    int i = blockIdx.x * blockDim.x + threadIdx.x;
    if (i >= n4) return;
    float4 v = ((const float4*)in)[i];
    uint32_t h0, l0, h1, l1;
    split2(v.x, v.y, h0, l0);
    split2(v.z, v.w, h1, l1);
    uint2 hv = {h0, h1}, lv = {l0, l1};
    ((uint2*)hi)[i] = hv;
    ((uint2*)lo)[i] = lv;
}

__global__ void cvt_t_hilo(const float* __restrict__ W, __nv_bfloat16* __restrict__ Thi,
                           __nv_bfloat16* __restrict__ Tlo, int K, int N)
{
    __shared__ float tile[32][33];
    int k0 = blockIdx.y * 32, n0 = blockIdx.x * 32;
    int tx = threadIdx.x, ty = threadIdx.y;
#pragma unroll
    for (int i = ty; i < 32; i += 8)
        tile[i][tx] = W[(size_t)(k0 + i) * N + n0 + tx];
    __syncthreads();
#pragma unroll
    for (int i = ty; i < 32; i += 8) {
        float v = tile[tx][i];
        uint32_t uh = __float_as_uint(v) & 0xFFFF0000u;
        float l = v - __uint_as_float(uh);
        size_t o = (size_t)(n0 + i) * K + k0 + tx;
        Thi[o] = __ushort_as_bfloat16((unsigned short)(uh >> 16));
        Tlo[o] = __float2bfloat16(l);
    }
}

// ---------------------------------------------------------------------------
// HMMA bf16x3 GEMM: 128x128 CTA, BK=32, 8 warps (64x32), 3 stages,
// XOR-swizzled 64B rows, 1 barrier/ktile, 2 CTAs/SM. (unchanged round 7)
// ---------------------------------------------------------------------------
#define MATB   8192
#define STAGEB (4 * MATB)
#define GSMEM  (3 * STAGEB)      // 98304

template <bool HILO>
__global__ __launch_bounds__(256, 2)
void gemm_mma(const __nv_bfloat16* __restrict__ Ahi, const __nv_bfloat16* __restrict__ Alo,
              const __nv_bfloat16* __restrict__ Bhi, const __nv_bfloat16* __restrict__ Blo,
              const float* __restrict__ bias, float* __restrict__ Cf,
              __nv_bfloat16* __restrict__ Ch, __nv_bfloat16* __restrict__ Cl,
              int M, int N, int K)
{
    extern __shared__ char smem[];
    uint32_t sb = smem_u32(smem);
    int t = threadIdx.x, wid = t >> 5, lid = t & 31;
    int m0 = blockIdx.y * 128, n0 = blockIdx.x * 128;
    int wm = wid & 1, wn = wid >> 1;

    const __nv_bfloat16* gp[4] = {
        Ahi + (size_t)m0 * K, Alo + (size_t)m0 * K,
        Bhi + (size_t)n0 * K, Blo + (size_t)n0 * K };

    const int lc = t & 3;
    const int lr = t >> 2;
    const uint32_t wofs0 = lr * 64 + ((lc ^ ((lr >> 1) & 3)) << 4);
    const uint32_t wofs1 = (lr + 64) * 64 + ((lc ^ (((lr + 64) >> 1) & 3)) << 4);

    float acc[4][4][4];
#pragma unroll
    for (int i = 0; i < 4; i++)
#pragma unroll
        for (int j = 0; j < 4; j++)
#pragma unroll
            for (int v = 0; v < 4; v++) acc[i][j][v] = 0.f;

    int nkt = K / 32;

#pragma unroll
    for (int s = 0; s < 2; s++) {
        uint32_t st = sb + s * STAGEB;
        int koff = s * 32;
#pragma unroll
        for (int mat = 0; mat < 4; mat++) {
            cp16(st + mat * MATB + wofs0, gp[mat] + (size_t)lr * K + koff + lc * 8);
            cp16(st + mat * MATB + wofs1, gp[mat] + (size_t)(lr + 64) * K + koff + lc * 8);
        }
        CP_COMMIT();
    }

    const int arow = lid & 15, asel = lid >> 4;
    const int axor = (arow >> 1) & 3;
    const int browl = ((lid >> 4) & 1) * 8 + (lid & 7);
    const int bsel = (lid >> 3) & 1;
    const int bxor = (browl >> 1) & 3;

    int rd = 0, wr = 2;
    for (int kt = 0; kt < nkt; kt++) {
        CP_WAIT1();
        __syncthreads();

        uint32_t st = sb + rd * STAGEB;

#pragma unroll
        for (int kb = 0; kb < 2; kb++) {
            uint32_t ah[4][4], al[4][4];
#pragma unroll
            for (int mt = 0; mt < 4; mt++) {
                uint32_t ad = st + (uint32_t)(wm * 64 + mt * 16 + arow) * 64
                              + (uint32_t)(((kb * 2 + asel) ^ axor) << 4);
                ldsm4(ah[mt], ad);
                ldsm4(al[mt], ad + MATB);
            }
#pragma unroll
            for (int p = 0; p < 2; p++) {
                uint32_t bd = st + 2 * MATB
                              + (uint32_t)(wn * 32 + p * 16 + browl) * 64
                              + (uint32_t)(((kb * 2 + bsel) ^ bxor) << 4);
                uint32_t bh[4], bl[4];
                ldsm4(bh, bd);
                ldsm4(bl, bd + MATB);
#pragma unroll
                for (int mt = 0; mt < 4; mt++) {
                    mma16816(acc[mt][2 * p],     ah[mt], &bh[0]);
                    mma16816(acc[mt][2 * p + 1], ah[mt], &bh[2]);
                }
#pragma unroll
                for (int mt = 0; mt < 4; mt++) {
                    mma16816(acc[mt][2 * p],     ah[mt], &bl[0]);
                    mma16816(acc[mt][2 * p + 1], ah[mt], &bl[2]);
                }
#pragma unroll
                for (int mt = 0; mt < 4; mt++) {
                    mma16816(acc[mt][2 * p],     al[mt], &bh[0]);
                    mma16816(acc[mt][2 * p + 1], al[mt], &bh[2]);
                }
            }
        }

        if (kt + 2 < nkt) {
            uint32_t st2 = sb + wr * STAGEB;
            int koff = (kt + 2) * 32;
#pragma unroll
            for (int mat = 0; mat < 4; mat++) {
                cp16(st2 + mat * MATB + wofs0, gp[mat] + (size_t)lr * K + koff + lc * 8);
                cp16(st2 + mat * MATB + wofs1, gp[mat] + (size_t)(lr + 64) * K + koff + lc * 8);
            }
        }
        CP_COMMIT();
        rd = (rd == 2) ? 0 : rd + 1;
        wr = (wr == 2) ? 0 : wr + 1;
    }

    int rA = m0 + wm * 64 + (lid >> 2);
    int cA = n0 + wn * 32 + 2 * (lid & 3);
#pragma unroll
    for (int mt = 0; mt < 4; mt++) {
        int r = rA + mt * 16;
#pragma unroll
        for (int nt = 0; nt < 4; nt++) {
            int c = cA + nt * 8;
            float b0 = bias[c], b1 = bias[c + 1];
            float v00 = acc[mt][nt][0] + b0, v01 = acc[mt][nt][1] + b1;
            float v10 = acc[mt][nt][2] + b0, v11 = acc[mt][nt][3] + b1;
            if (HILO) {
                uint32_t h, l;
                split2(v00, v01, h, l);
                *(uint32_t*)(Ch + (size_t)r * N + c) = h;
                *(uint32_t*)(Cl + (size_t)r * N + c) = l;
                split2(v10, v11, h, l);
                *(uint32_t*)(Ch + (size_t)(r + 8) * N + c) = h;
                *(uint32_t*)(Cl + (size_t)(r + 8) * N + c) = l;
            } else {
                float2 w0 = {v00, v01}, w1 = {v10, v11};
                *(float2*)(Cf + (size_t)r * N + c)       = w0;
                *(float2*)(Cf + (size_t)(r + 8) * N + c) = w1;
            }
        }
    }
}

// ---------------------------------------------------------------------------
// Tensor-core causal flash attention. Per CTA: one (b,h), 128 q-rows,
// 8 warps x 16 rows, 64-token K tiles, 2-stage KV pipeline.
// XOR-swizzled 128B rows (chunk ^= row&7), 96KB smem -> 2 CTAs/SM.
// ql fragments reloaded from smem (reg budget 128).
// ---------------------------------------------------------------------------
#define QMATB   16384            // 128 rows * 128B
#define FMATB   8192             // 64 rows * 128B
#define FSTAGE  (4 * FMATB)      // 32768
#define FSMEM   (2 * QMATB + 2 * FSTAGE)  // 98304
#define SCALE_L2E 0.18033688011112042f

__global__ __launch_bounds__(256, 2)
void flash_mma(const __nv_bfloat16* __restrict__ qkvh,
               const __nv_bfloat16* __restrict__ qkvl,
               __nv_bfloat16* __restrict__ atth,
               __nv_bfloat16* __restrict__ attl)
{
    extern __shared__ char smem[];
    uint32_t sb = smem_u32(smem);
    int t = threadIdx.x, wid = t >> 5, lid = t & 31;
    int bh = blockIdx.x;
    int b = bh >> 4, hh = bh & 15;
    int qt = (int)gridDim.y - 1 - blockIdx.y;   // heavy tiles first
    int qbase = qt * 128;
    int tok0 = b * S_LEN;

    const uint32_t QH = sb, QL = sb + QMATB;
    const uint32_t KV0 = sb + 2 * QMATB;

    // Q loaders: 2 threads/row, 4 chunks each
    const int qlrow  = t >> 1;
    const int qlcol0 = (t & 1) * 4;
    // KV loaders: 4 threads/row, 2 chunks each
    const int klrow  = t >> 2;
    const int klcol0 = (t & 3) * 2;
    const int klx = klrow & 7;

    // prologue: Q tile + KV stage 0
    {
        size_t rq = (size_t)(tok0 + qbase + qlrow) * E3 + hh * 64;
        int qx = qlrow & 7;
#pragma unroll
        for (int u = 0; u < 4; u++) {
            int ch = qlcol0 + u;
            uint32_t d = qlrow * 128 + ((ch ^ qx) << 4);
            cp16(QH + d, qkvh + rq + ch * 8);
            cp16(QL + d, qkvl + rq + ch * 8);
        }
        size_t rk = (size_t)(tok0 + klrow) * E3 + 1024 + hh * 64;
#pragma unroll
        for (int u = 0; u < 2; u++) {
            int ch = klcol0 + u;
            uint32_t d = klrow * 128 + ((ch ^ klx) << 4);
            cp16(KV0 + d,             qkvh + rk + ch * 8);
            cp16(KV0 + FMATB + d,     qkvl + rk + ch * 8);
            cp16(KV0 + 2 * FMATB + d, qkvh + rk + 1024 + ch * 8);
            cp16(KV0 + 3 * FMATB + d, qkvl + rk + 1024 + ch * 8);
        }
    }
    CP_COMMIT();

    // fragment lane constants
    const int arow = lid & 15, asel = lid >> 4;
    const int qrow = wid * 16 + arow;          // Q row for A-fragments
    const int qx = qrow & 7;
    const int browf = ((lid >> 4) & 1) * 8 + (lid & 7);
    const int bsel = (lid >> 3) & 1;
    const int vrowf = ((lid >> 3) & 1) * 8 + (lid & 7);
    const int vsel = (lid >> 4) & 1;

    uint32_t qh[4][4];
    float o[8][4];
#pragma unroll
    for (int n = 0; n < 8; n++)
#pragma unroll
        for (int v = 0; v < 4; v++) o[n][v] = 0.f;
    float m_lo = -CUDART_INF_F, m_hi = -CUDART_INF_F, l_lo = 0.f, l_hi = 0.f;

    const int rlo = lid >> 2;
    const int rloc = 16 * (wid & 3) + rlo;
    const int mycol0 = 2 * (lid & 3);
    const int kt_d = 2 * qt + (wid >> 2);
    const int ntiles = 2 * qt + 2;

    for (int kt = 0; kt < ntiles; kt++) {
        if (kt + 1 < ntiles) {
            uint32_t st = KV0 + ((kt + 1) & 1) * FSTAGE;
            size_t rk = (size_t)(tok0 + (kt + 1) * 64 + klrow) * E3 + 1024 + hh * 64;
#pragma unroll
            for (int u = 0; u < 2; u++) {
                int ch = klcol0 + u;
                uint32_t d = klrow * 128 + ((ch ^ klx) << 4);
                cp16(st + d,             qkvh + rk + ch * 8);
                cp16(st + FMATB + d,     qkvl + rk + ch * 8);
                cp16(st + 2 * FMATB + d, qkvh + rk + 1024 + ch * 8);
                cp16(st + 3 * FMATB + d, qkvl + rk + 1024 + ch * 8);
            }
        }
        CP_COMMIT();
        CP_WAIT1();
        __syncthreads();

        if (kt == 0) {   // persistent Q-hi fragments
#pragma unroll
            for (int ks = 0; ks < 4; ks++) {
                uint32_t ad = QH + qrow * 128 + (((ks * 2 + asel) ^ qx) << 4);
                ldsm4(qh[ks], ad);
            }
        }

        if (kt <= kt_d) {
            uint32_t st = KV0 + (kt & 1) * FSTAGE;

            // ---- S = Q K^T ----
            float s[8][4];
#pragma unroll
            for (int n = 0; n < 8; n++)
#pragma unroll
                for (int v = 0; v < 4; v++) s[n][v] = 0.f;

#pragma unroll
            for (int ks = 0; ks < 4; ks++) {
                uint32_t qlt[4];
                ldsm4(qlt, QL + qrow * 128 + (((ks * 2 + asel) ^ qx) << 4));
#pragma unroll
                for (int pp = 0; pp < 2; pp++) {
                    int p0 = pp * 2;
                    int rk0 = p0 * 16 + browf, rk1 = rk0 + 16;
                    uint32_t ka0 = st + rk0 * 128 + (((ks * 2 + bsel) ^ (rk0 & 7)) << 4);
                    uint32_t ka1 = st + rk1 * 128 + (((ks * 2 + bsel) ^ (rk1 & 7)) << 4);
                    uint32_t kh0[4], kl0[4], kh1[4], kl1[4];
                    ldsm4(kh0, ka0);
                    ldsm4(kl0, ka0 + FMATB);
                    ldsm4(kh1, ka1);
                    ldsm4(kl1, ka1 + FMATB);
                    mma16816(s[2 * p0],     qh[ks], &kh0[0]);
                    mma16816(s[2 * p0 + 1], qh[ks], &kh0[2]);
                    mma16816(s[2 * p0 + 2], qh[ks], &kh1[0]);
                    mma16816(s[2 * p0 + 3], qh[ks], &kh1[2]);
                    mma16816(s[2 * p0],     qh[ks], &kl0[0]);
                    mma16816(s[2 * p0 + 1], qh[ks], &kl0[2]);
                    mma16816(s[2 * p0 + 2], qh[ks], &kl1[0]);
                    mma16816(s[2 * p0 + 3], qh[ks], &kl1[2]);
                    mma16816(s[2 * p0],     qlt, &kh0[0]);
                    mma16816(s[2 * p0 + 1], qlt, &kh0[2]);
                    mma16816(s[2 * p0 + 2], qlt, &kh1[0]);
                    mma16816(s[2 * p0 + 3], qlt, &kh1[2]);
                }
            }

#pragma unroll
            for (int n = 0; n < 8; n++)
#pragma unroll
                for (int v = 0; v < 4; v++) s[n][v] *= SCALE_L2E;

            if (kt == kt_d) {
#pragma unroll
                for (int n = 0; n < 8; n++) {
                    int c0 = n * 8 + mycol0;
                    if (c0 > rloc)     s[n][0] = -CUDART_INF_F;
                    if (c0 + 1 > rloc) s[n][1] = -CUDART_INF_F;
                    if (c0 > rloc + 8)     s[n][2] = -CUDART_INF_F;
                    if (c0 + 1 > rloc + 8) s[n][3] = -CUDART_INF_F;
                }
            }

            // ---- online softmax ----
            float mt_lo = -CUDART_INF_F, mt_hi = -CUDART_INF_F;
#pragma unroll
            for (int n = 0; n < 8; n++) {
                mt_lo = fmaxf(mt_lo, fmaxf(s[n][0], s[n][1]));
                mt_hi = fmaxf(mt_hi, fmaxf(s[n][2], s[n][3]));
            }
            mt_lo = fmaxf(mt_lo, __shfl_xor_sync(0xffffffffu, mt_lo, 1));
            mt_lo = fmaxf(mt_lo, __shfl_xor_sync(0xffffffffu, mt_lo, 2));
            mt_hi = fmaxf(mt_hi, __shfl_xor_sync(0xffffffffu, mt_hi, 1));
            mt_hi = fmaxf(mt_hi, __shfl_xor_sync(0xffffffffu, mt_hi, 2));

            float mn_lo = fmaxf(m_lo, mt_lo), mn_hi = fmaxf(m_hi, mt_hi);
            float a_lo = exp2f(m_lo - mn_lo), a_hi = exp2f(m_hi - mn_hi);
            m_lo = mn_lo; m_hi = mn_hi;

            float rs_lo = 0.f, rs_hi = 0.f;
#pragma unroll
            for (int n = 0; n < 8; n++) {
                s[n][0] = exp2f(s[n][0] - mn_lo);
                s[n][1] = exp2f(s[n][1] - mn_lo);
                s[n][2] = exp2f(s[n][2] - mn_hi);
                s[n][3] = exp2f(s[n][3] - mn_hi);
                rs_lo += s[n][0] + s[n][1];
                rs_hi += s[n][2] + s[n][3];
            }
            rs_lo += __shfl_xor_sync(0xffffffffu, rs_lo, 1);
            rs_lo += __shfl_xor_sync(0xffffffffu, rs_lo, 2);
            rs_hi += __shfl_xor_sync(0xffffffffu, rs_hi, 1);
            rs_hi += __shfl_xor_sync(0xffffffffu, rs_hi, 2);
            l_lo = a_lo * l_lo + rs_lo;
            l_hi = a_hi * l_hi + rs_hi;
#pragma unroll
            for (int n = 0; n < 8; n++) {
                o[n][0] *= a_lo; o[n][1] *= a_lo;
                o[n][2] *= a_hi; o[n][3] *= a_hi;
            }

            // ---- O += P V ----
            uint32_t vbase = st + 2 * FMATB;
#pragma unroll
            for (int ks = 0; ks < 4; ks++) {
                uint32_t ph[4], pl[4];
                split2(s[2 * ks][0],     s[2 * ks][1],     ph[0], pl[0]);
                split2(s[2 * ks][2],     s[2 * ks][3],     ph[1], pl[1]);
                split2(s[2 * ks + 1][0], s[2 * ks + 1][1], ph[2], pl[2]);
                split2(s[2 * ks + 1][2], s[2 * ks + 1][3], ph[3], pl[3]);
                int rv = ks * 16 + vrowf;
                int vx = rv & 7;
#pragma unroll
                for (int pp = 0; pp < 2; pp++) {
                    int p0 = pp * 2;
                    uint32_t va0 = vbase + rv * 128 + (((p0 * 2 + vsel) ^ vx) << 4);
                    uint32_t va1 = vbase + rv * 128 + ((((p0 + 1) * 2 + vsel) ^ vx) << 4);
                    uint32_t vh0[4], vl0[4], vh1[4], vl1[4];
                    ldsm4t(vh0, va0);
                    ldsm4t(vl0, va0 + FMATB);
                    ldsm4t(vh1, va1);
                    ldsm4t(vl1, va1 + FMATB);
                    mma16816(o[2 * p0],     ph, &vh0[0]);
                    mma16816(o[2 * p0 + 1], ph, &vh0[2]);
                    mma16816(o[2 * p0 + 2], ph, &vh1[0]);
                    mma16816(o[2 * p0 + 3], ph, &vh1[2]);
                    mma16816(o[2 * p0],     ph, &vl0[0]);
                    mma16816(o[2 * p0 + 1], ph, &vl0[2]);
                    mma16816(o[2 * p0 + 2], ph, &vl1[0]);
                    mma16816(o[2 * p0 + 3], ph, &vl1[2]);
                    mma16816(o[2 * p0],     pl, &vh0[0]);
                    mma16816(o[2 * p0 + 1], pl, &vh0[2]);
                    mma16816(o[2 * p0 + 2], pl, &vh1[0]);
                    mma16816(o[2 * p0 + 3], pl, &vh1[2]);
                }
            }
        }
        __syncthreads();
    }

    // ---- epilogue ----
    float inv_lo = 1.f / l_lo, inv_hi = 1.f / l_hi;
    int tok_lo = tok0 + qbase + wid * 16 + rlo;
    int tok_hi = tok_lo + 8;
#pragma unroll
    for (int n = 0; n < 8; n++) {
        int c = hh * 64 + n * 8 + mycol0;
        uint32_t h, l;
        split2(o[n][0] * inv_lo, o[n][1] * inv_lo, h, l);
        *(uint32_t*)(atth + (size_t)tok_lo * N_EMBD + c) = h;
        *(uint32_t*)(attl + (size_t)tok_lo * N_EMBD + c) = l;
        split2(o[n][2] * inv_hi, o[n][3] * inv_hi, h, l);
        *(uint32_t*)(atth + (size_t)tok_hi * N_EMBD + c) = h;
        *(uint32_t*)(attl + (size_t)tok_hi * N_EMBD + c) = l;
    }
}

// ---------------------------------------------------------------------------
extern "C" void kernel_launch(void* const* d_in, const int* in_sizes, int n_in,
                              void* d_out, int out_size)
{
    const float* x      = (const float*)d_in[0];
    const float* W_attn = (const float*)d_in[1];
    const float* b_attn = (const float*)d_in[2];
    const float* W_proj = (const float*)d_in[3];
    const float* b_proj = (const float*)d_in[4];
    float* out = (float*)d_out;

    __nv_bfloat16 *xhi, *xlo, *qkvh, *qkvl, *atth, *attl, *wahi, *walo, *wphi, *wplo;
    cudaGetSymbolAddress((void**)&xhi, g_xhi);
    cudaGetSymbolAddress((void**)&xlo, g_xlo);
    cudaGetSymbolAddress((void**)&qkvh, g_qkvh);
    cudaGetSymbolAddress((void**)&qkvl, g_qkvl);
    cudaGetSymbolAddress((void**)&atth, g_atth);
    cudaGetSymbolAddress((void**)&attl, g_attl);
    cudaGetSymbolAddress((void**)&wahi, g_wahi);
    cudaGetSymbolAddress((void**)&walo, g_walo);
    cudaGetSymbolAddress((void**)&wphi, g_wphi);
    cudaGetSymbolAddress((void**)&wplo, g_wplo);

    cudaFuncSetAttribute(gemm_mma<true>,
                         cudaFuncAttributeMaxDynamicSharedMemorySize, GSMEM);
    cudaFuncSetAttribute(gemm_mma<false>,
                         cudaFuncAttributeMaxDynamicSharedMemorySize, GSMEM);
    cudaFuncSetAttribute(flash_mma,
                         cudaFuncAttributeMaxDynamicSharedMemorySize, FSMEM);

    cvt_hilo<<<(M_ROWS * N_EMBD / 4 + 255) / 256, 256>>>(x, xhi, xlo, M_ROWS * N_EMBD / 4);
    cvt_t_hilo<<<dim3(E3 / 32, N_EMBD / 32), dim3(32, 8)>>>(W_attn, wahi, walo, N_EMBD, E3);
    cvt_t_hilo<<<dim3(N_EMBD / 32, N_EMBD / 32), dim3(32, 8)>>>(W_proj, wphi, wplo, N_EMBD, N_EMBD);

    gemm_mma<true><<<dim3(E3 / 128, M_ROWS / 128), 256, GSMEM>>>(
        xhi, xlo, wahi, walo, b_attn, nullptr, qkvh, qkvl, M_ROWS, E3, N_EMBD);

    flash_mma<<<dim3(2 * N_HEADS, S_LEN / 128), 256, FSMEM>>>(qkvh, qkvl, atth, attl);

    gemm_mma<false><<<dim3(N_EMBD / 128, M_ROWS / 128), 256, GSMEM>>>(
        atth, attl, wphi, wplo, b_proj, out, nullptr, nullptr, M_ROWS, N_EMBD, N_EMBD);
}

// round 9
// speedup vs baseline: 3.8423x; 1.0401x over previous
#include <cuda_runtime.h>
#include <cuda_bf16.h>
#include <math_constants.h>
#include <cstdint>

// ---------------------------------------------------------------------------
// MultiHeadAttention, B=2,S=2048,H=16,D=64,E=1024. HMMA everywhere with
// bf16 hi/lo 3-term split precision.
//   1) qkv(hi,lo) = split( x @ W_attn + b_attn )
//   2) att(hi,lo) = split( flash(qkv) )   [128-row Q tiles, 8 warps, 2 CTA/SM]
//   3) out        = att @ W_proj + b_proj
// GEMM (round 9): 128 threads, 4 warps of 64x64 tiles, 2 CTAs/SM. LDSM:MMA
// ratio 1:6 per warp + 6 independent acc chains -> single-warp tensor
// saturation (round-8 limiter was LDSM/barrier latency exposure).
// ---------------------------------------------------------------------------

#define S_LEN   2048
#define N_EMBD  1024
#define E3      3072
#define N_HEADS 16
#define M_ROWS  4096

__device__ __nv_bfloat16 g_xhi[(size_t)M_ROWS * N_EMBD];
__device__ __nv_bfloat16 g_xlo[(size_t)M_ROWS * N_EMBD];
__device__ __nv_bfloat16 g_qkvh[(size_t)M_ROWS * E3];
__device__ __nv_bfloat16 g_qkvl[(size_t)M_ROWS * E3];
__device__ __nv_bfloat16 g_atth[(size_t)M_ROWS * N_EMBD];
__device__ __nv_bfloat16 g_attl[(size_t)M_ROWS * N_EMBD];
__device__ __nv_bfloat16 g_wahi[(size_t)E3 * N_EMBD];
__device__ __nv_bfloat16 g_walo[(size_t)E3 * N_EMBD];
__device__ __nv_bfloat16 g_wphi[(size_t)N_EMBD * N_EMBD];
__device__ __nv_bfloat16 g_wplo[(size_t)N_EMBD * N_EMBD];

// ------------------------- helpers ------------------------------------------
__device__ __forceinline__ uint32_t smem_u32(const void* p) {
    uint32_t a;
    asm("{ .reg .u64 t; cvta.to.shared.u64 t, %1; cvt.u32.u64 %0, t; }"
        : "=r"(a) : "l"(p));
    return a;
}
__device__ __forceinline__ void cp16(uint32_t dst, const void* src) {
    asm volatile("cp.async.cg.shared.global [%0], [%1], 16;" :: "r"(dst), "l"(src));
}
#define CP_COMMIT() asm volatile("cp.async.commit_group;" ::: "memory")
#define CP_WAIT1()  asm volatile("cp.async.wait_group 1;"  ::: "memory")

__device__ __forceinline__ void ldsm4(uint32_t* r, uint32_t addr) {
    asm volatile("ldmatrix.sync.aligned.m8n8.x4.shared.b16 {%0,%1,%2,%3}, [%4];"
                 : "=r"(r[0]), "=r"(r[1]), "=r"(r[2]), "=r"(r[3]) : "r"(addr));
}
__device__ __forceinline__ void ldsm4t(uint32_t* r, uint32_t addr) {
    asm volatile("ldmatrix.sync.aligned.m8n8.x4.trans.shared.b16 {%0,%1,%2,%3}, [%4];"
                 : "=r"(r[0]), "=r"(r[1]), "=r"(r[2]), "=r"(r[3]) : "r"(addr));
}
__device__ __forceinline__ void mma16816(float* d, const uint32_t* a, const uint32_t* b) {
    asm volatile(
        "mma.sync.aligned.m16n8k16.row.col.f32.bf16.bf16.f32 "
        "{%0,%1,%2,%3}, {%4,%5,%6,%7}, {%8,%9}, {%0,%1,%2,%3};"
        : "+f"(d[0]), "+f"(d[1]), "+f"(d[2]), "+f"(d[3])
        : "r"(a[0]), "r"(a[1]), "r"(a[2]), "r"(a[3]), "r"(b[0]), "r"(b[1]));
}
// fast split: truncation hi + exact residual lo
__device__ __forceinline__ void split2(float a, float b, uint32_t& hi, uint32_t& lo) {
    uint32_t ua = __float_as_uint(a) & 0xFFFF0000u;
    uint32_t ub = __float_as_uint(b) & 0xFFFF0000u;
    hi = __byte_perm(ua, ub, 0x7632);
    float la = a - __uint_as_float(ua);
    float lb = b - __uint_as_float(ub);
    asm("cvt.rn.bf16x2.f32 %0, %1, %2;" : "=r"(lo) : "f"(lb), "f"(la));
}

// ---------------------------------------------------------------------------
__global__ void cvt_hilo(const float* __restrict__ in, __nv_bfloat16* __restrict__ hi,
                         __nv_bfloat16* __restrict__ lo, int n4)
{
    int i = blockIdx.x * blockDim.x + threadIdx.x;
    if (i >= n4) return;
    float4 v = ((const float4*)in)[i];
    uint32_t h0, l0, h1, l1;
    split2(v.x, v.y, h0, l0);
    split2(v.z, v.w, h1, l1);
    uint2 hv = {h0, h1}, lv = {l0, l1};
    ((uint2*)hi)[i] = hv;
    ((uint2*)lo)[i] = lv;
}

__global__ void cvt_t_hilo(const float* __restrict__ W, __nv_bfloat16* __restrict__ Thi,
                           __nv_bfloat16* __restrict__ Tlo, int K, int N)
{
    __shared__ float tile[32][33];
    int k0 = blockIdx.y * 32, n0 = blockIdx.x * 32;
    int tx = threadIdx.x, ty = threadIdx.y;
#pragma unroll
    for (int i = ty; i < 32; i += 8)
        tile[i][tx] = W[(size_t)(k0 + i) * N + n0 + tx];
    __syncthreads();
#pragma unroll
    for (int i = ty; i < 32; i += 8) {
        float v = tile[tx][i];
        uint32_t uh = __float_as_uint(v) & 0xFFFF0000u;
        float l = v - __uint_as_float(uh);
        size_t o = (size_t)(n0 + i) * K + k0 + tx;
        Thi[o] = __ushort_as_bfloat16((unsigned short)(uh >> 16));
        Tlo[o] = __float2bfloat16(l);
    }
}

// ---------------------------------------------------------------------------
// HMMA bf16x3 GEMM: 128x128 CTA, BK=32, 4 warps (64x64 each), 3 stages,
// XOR-swizzled 64B rows, 1 barrier/ktile, 2 CTAs/SM, 128 threads.
// ---------------------------------------------------------------------------
#define MATB   8192
#define STAGEB (4 * MATB)
#define GSMEM  (3 * STAGEB)      // 98304

template <bool HILO>
__global__ __launch_bounds__(128, 2)
void gemm_mma(const __nv_bfloat16* __restrict__ Ahi, const __nv_bfloat16* __restrict__ Alo,
              const __nv_bfloat16* __restrict__ Bhi, const __nv_bfloat16* __restrict__ Blo,
              const float* __restrict__ bias, float* __restrict__ Cf,
              __nv_bfloat16* __restrict__ Ch, __nv_bfloat16* __restrict__ Cl,
              int M, int N, int K)
{
    extern __shared__ char smem[];
    uint32_t sb = smem_u32(smem);
    int t = threadIdx.x, wid = t >> 5, lid = t & 31;
    int m0 = blockIdx.y * 128, n0 = blockIdx.x * 128;
    int wm = wid & 1, wn = wid >> 1;   // 2x2 warp grid, 64x64 tiles

    const __nv_bfloat16* gp[4] = {
        Ahi + (size_t)m0 * K, Alo + (size_t)m0 * K,
        Bhi + (size_t)n0 * K, Blo + (size_t)n0 * K };

    // loader lanes: 128 threads; chunk lc (16B) in 64B row, rows lr+32*r4
    const int lc = t & 3;
    const int lr = t >> 2;                  // 0..31
    const int lx = (lr >> 1) & 3;           // xor invariant under +32
    const uint32_t wbase = (uint32_t)((lc ^ lx) << 4) + lr * 64;

    float acc[4][8][4];   // [mt][n8][4] = 128 regs
#pragma unroll
    for (int i = 0; i < 4; i++)
#pragma unroll
        for (int j = 0; j < 8; j++)
#pragma unroll
            for (int v = 0; v < 4; v++) acc[i][j][v] = 0.f;

    int nkt = K / 32;

    // prologue: stages 0,1
#pragma unroll
    for (int s = 0; s < 2; s++) {
        uint32_t st = sb + s * STAGEB;
        int koff = s * 32;
#pragma unroll
        for (int mat = 0; mat < 4; mat++)
#pragma unroll
            for (int r4 = 0; r4 < 4; r4++)
                cp16(st + mat * MATB + wbase + r4 * 32 * 64,
                     gp[mat] + (size_t)(lr + r4 * 32) * K + koff + lc * 8);
        CP_COMMIT();
    }

    // fragment lane constants
    const int arow = lid & 15, asel = lid >> 4;
    const int axor = (arow >> 1) & 3;
    const int browl = ((lid >> 4) & 1) * 8 + (lid & 7);
    const int bsel = (lid >> 3) & 1;
    const int bxor = (browl >> 1) & 3;

    int rd = 0, wr = 2;
    for (int kt = 0; kt < nkt; kt++) {
        CP_WAIT1();
        __syncthreads();

        uint32_t st = sb + rd * STAGEB;

#pragma unroll
        for (int kb = 0; kb < 2; kb++) {
            uint32_t ah[4][4], al[4][4];
#pragma unroll
            for (int mt = 0; mt < 4; mt++) {
                uint32_t ad = st + (uint32_t)(wm * 64 + mt * 16 + arow) * 64
                              + (uint32_t)(((kb * 2 + asel) ^ axor) << 4);
                ldsm4(ah[mt], ad);
                ldsm4(al[mt], ad + MATB);
            }
#pragma unroll
            for (int p = 0; p < 4; p++) {
                uint32_t bd = st + 2 * MATB
                              + (uint32_t)(wn * 64 + p * 16 + browl) * 64
                              + (uint32_t)(((kb * 2 + bsel) ^ bxor) << 4);
                uint32_t bh[4], bl[4];
                ldsm4(bh, bd);
                ldsm4(bl, bd + MATB);
#pragma unroll
                for (int mt = 0; mt < 4; mt++) {
                    mma16816(acc[mt][2 * p],     ah[mt], &bh[0]);
                    mma16816(acc[mt][2 * p + 1], ah[mt], &bh[2]);
                }
#pragma unroll
                for (int mt = 0; mt < 4; mt++) {
                    mma16816(acc[mt][2 * p],     ah[mt], &bl[0]);
                    mma16816(acc[mt][2 * p + 1], ah[mt], &bl[2]);
                }
#pragma unroll
                for (int mt = 0; mt < 4; mt++) {
                    mma16816(acc[mt][2 * p],     al[mt], &bh[0]);
                    mma16816(acc[mt][2 * p + 1], al[mt], &bh[2]);
                }
            }
        }

        if (kt + 2 < nkt) {
            uint32_t st2 = sb + wr * STAGEB;
            int koff = (kt + 2) * 32;
#pragma unroll
            for (int mat = 0; mat < 4; mat++)
#pragma unroll
                for (int r4 = 0; r4 < 4; r4++)
                    cp16(st2 + mat * MATB + wbase + r4 * 32 * 64,
                         gp[mat] + (size_t)(lr + r4 * 32) * K + koff + lc * 8);
        }
        CP_COMMIT();
        rd = (rd == 2) ? 0 : rd + 1;
        wr = (wr == 2) ? 0 : wr + 1;
    }

    int rA = m0 + wm * 64 + (lid >> 2);
    int cA = n0 + wn * 64 + 2 * (lid & 3);
#pragma unroll
    for (int mt = 0; mt < 4; mt++) {
        int r = rA + mt * 16;
#pragma unroll
        for (int nt = 0; nt < 8; nt++) {
            int c = cA + nt * 8;
            float b0 = bias[c], b1 = bias[c + 1];
            float v00 = acc[mt][nt][0] + b0, v01 = acc[mt][nt][1] + b1;
            float v10 = acc[mt][nt][2] + b0, v11 = acc[mt][nt][3] + b1;
            if (HILO) {
                uint32_t h, l;
                split2(v00, v01, h, l);
                *(uint32_t*)(Ch + (size_t)r * N + c) = h;
                *(uint32_t*)(Cl + (size_t)r * N + c) = l;
                split2(v10, v11, h, l);
                *(uint32_t*)(Ch + (size_t)(r + 8) * N + c) = h;
                *(uint32_t*)(Cl + (size_t)(r + 8) * N + c) = l;
            } else {
                float2 w0 = {v00, v01}, w1 = {v10, v11};
                *(float2*)(Cf + (size_t)r * N + c)       = w0;
                *(float2*)(Cf + (size_t)(r + 8) * N + c) = w1;
            }
        }
    }
}

// ---------------------------------------------------------------------------
// Tensor-core causal flash attention (unchanged from round 8).
// Per CTA: one (b,h), 128 q-rows, 8 warps x 16 rows, 64-token K tiles,
// XOR-swizzled 128B rows, 96KB smem -> 2 CTAs/SM.
// ---------------------------------------------------------------------------
#define QMATB   16384
#define FMATB   8192
#define FSTAGE  (4 * FMATB)
#define FSMEM   (2 * QMATB + 2 * FSTAGE)  // 98304
#define SCALE_L2E 0.18033688011112042f

__global__ __launch_bounds__(256, 2)
void flash_mma(const __nv_bfloat16* __restrict__ qkvh,
               const __nv_bfloat16* __restrict__ qkvl,
               __nv_bfloat16* __restrict__ atth,
               __nv_bfloat16* __restrict__ attl)
{
    extern __shared__ char smem[];
    uint32_t sb = smem_u32(smem);
    int t = threadIdx.x, wid = t >> 5, lid = t & 31;
    int bh = blockIdx.x;
    int b = bh >> 4, hh = bh & 15;
    int qt = (int)gridDim.y - 1 - blockIdx.y;
    int qbase = qt * 128;
    int tok0 = b * S_LEN;

    const uint32_t QH = sb, QL = sb + QMATB;
    const uint32_t KV0 = sb + 2 * QMATB;

    const int qlrow  = t >> 1;
    const int qlcol0 = (t & 1) * 4;
    const int klrow  = t >> 2;
    const int klcol0 = (t & 3) * 2;
    const int klx = klrow & 7;

    {
        size_t rq = (size_t)(tok0 + qbase + qlrow) * E3 + hh * 64;
        int qx = qlrow & 7;
#pragma unroll
        for (int u = 0; u < 4; u++) {
            int ch = qlcol0 + u;
            uint32_t d = qlrow * 128 + ((ch ^ qx) << 4);
            cp16(QH + d, qkvh + rq + ch * 8);
            cp16(QL + d, qkvl + rq + ch * 8);
        }
        size_t rk = (size_t)(tok0 + klrow) * E3 + 1024 + hh * 64;
#pragma unroll
        for (int u = 0; u < 2; u++) {
            int ch = klcol0 + u;
            uint32_t d = klrow * 128 + ((ch ^ klx) << 4);
            cp16(KV0 + d,             qkvh + rk + ch * 8);
            cp16(KV0 + FMATB + d,     qkvl + rk + ch * 8);
            cp16(KV0 + 2 * FMATB + d, qkvh + rk + 1024 + ch * 8);
            cp16(KV0 + 3 * FMATB + d, qkvl + rk + 1024 + ch * 8);
        }
    }
    CP_COMMIT();

    const int arow = lid & 15, asel = lid >> 4;
    const int qrow = wid * 16 + arow;
    const int qx = qrow & 7;
    const int browf = ((lid >> 4) & 1) * 8 + (lid & 7);
    const int bsel = (lid >> 3) & 1;
    const int vrowf = ((lid >> 3) & 1) * 8 + (lid & 7);
    const int vsel = (lid >> 4) & 1;

    uint32_t qh[4][4];
    float o[8][4];
#pragma unroll
    for (int n = 0; n < 8; n++)
#pragma unroll
        for (int v = 0; v < 4; v++) o[n][v] = 0.f;
    float m_lo = -CUDART_INF_F, m_hi = -CUDART_INF_F, l_lo = 0.f, l_hi = 0.f;

    const int rlo = lid >> 2;
    const int rloc = 16 * (wid & 3) + rlo;
    const int mycol0 = 2 * (lid & 3);
    const int kt_d = 2 * qt + (wid >> 2);
    const int ntiles = 2 * qt + 2;

    for (int kt = 0; kt < ntiles; kt++) {
        if (kt + 1 < ntiles) {
            uint32_t st = KV0 + ((kt + 1) & 1) * FSTAGE;
            size_t rk = (size_t)(tok0 + (kt + 1) * 64 + klrow) * E3 + 1024 + hh * 64;
#pragma unroll
            for (int u = 0; u < 2; u++) {
                int ch = klcol0 + u;
                uint32_t d = klrow * 128 + ((ch ^ klx) << 4);
                cp16(st + d,             qkvh + rk + ch * 8);
                cp16(st + FMATB + d,     qkvl + rk + ch * 8);
                cp16(st + 2 * FMATB + d, qkvh + rk + 1024 + ch * 8);
                cp16(st + 3 * FMATB + d, qkvl + rk + 1024 + ch * 8);
            }
        }
        CP_COMMIT();
        CP_WAIT1();
        __syncthreads();

        if (kt == 0) {
#pragma unroll
            for (int ks = 0; ks < 4; ks++) {
                uint32_t ad = QH + qrow * 128 + (((ks * 2 + asel) ^ qx) << 4);
                ldsm4(qh[ks], ad);
            }
        }

        if (kt <= kt_d) {
            uint32_t st = KV0 + (kt & 1) * FSTAGE;

            float s[8][4];
#pragma unroll
            for (int n = 0; n < 8; n++)
#pragma unroll
                for (int v = 0; v < 4; v++) s[n][v] = 0.f;

#pragma unroll
            for (int ks = 0; ks < 4; ks++) {
                uint32_t qlt[4];
                ldsm4(qlt, QL + qrow * 128 + (((ks * 2 + asel) ^ qx) << 4));
#pragma unroll
                for (int pp = 0; pp < 2; pp++) {
                    int p0 = pp * 2;
                    int rk0 = p0 * 16 + browf, rk1 = rk0 + 16;
                    uint32_t ka0 = st + rk0 * 128 + (((ks * 2 + bsel) ^ (rk0 & 7)) << 4);
                    uint32_t ka1 = st + rk1 * 128 + (((ks * 2 + bsel) ^ (rk1 & 7)) << 4);
                    uint32_t kh0[4], kl0[4], kh1[4], kl1[4];
                    ldsm4(kh0, ka0);
                    ldsm4(kl0, ka0 + FMATB);
                    ldsm4(kh1, ka1);
                    ldsm4(kl1, ka1 + FMATB);
                    mma16816(s[2 * p0],     qh[ks], &kh0[0]);
                    mma16816(s[2 * p0 + 1], qh[ks], &kh0[2]);
                    mma16816(s[2 * p0 + 2], qh[ks], &kh1[0]);
                    mma16816(s[2 * p0 + 3], qh[ks], &kh1[2]);
                    mma16816(s[2 * p0],     qh[ks], &kl0[0]);
                    mma16816(s[2 * p0 + 1], qh[ks], &kl0[2]);
                    mma16816(s[2 * p0 + 2], qh[ks], &kl1[0]);
                    mma16816(s[2 * p0 + 3], qh[ks], &kl1[2]);
                    mma16816(s[2 * p0],     qlt, &kh0[0]);
                    mma16816(s[2 * p0 + 1], qlt, &kh0[2]);
                    mma16816(s[2 * p0 + 2], qlt, &kh1[0]);
                    mma16816(s[2 * p0 + 3], qlt, &kh1[2]);
                }
            }

#pragma unroll
            for (int n = 0; n < 8; n++)
#pragma unroll
                for (int v = 0; v < 4; v++) s[n][v] *= SCALE_L2E;

            if (kt == kt_d) {
#pragma unroll
                for (int n = 0; n < 8; n++) {
                    int c0 = n * 8 + mycol0;
                    if (c0 > rloc)     s[n][0] = -CUDART_INF_F;
                    if (c0 + 1 > rloc) s[n][1] = -CUDART_INF_F;
                    if (c0 > rloc + 8)     s[n][2] = -CUDART_INF_F;
                    if (c0 + 1 > rloc + 8) s[n][3] = -CUDART_INF_F;
                }
            }

            float mt_lo = -CUDART_INF_F, mt_hi = -CUDART_INF_F;
#pragma unroll
            for (int n = 0; n < 8; n++) {
                mt_lo = fmaxf(mt_lo, fmaxf(s[n][0], s[n][1]));
                mt_hi = fmaxf(mt_hi, fmaxf(s[n][2], s[n][3]));
            }
            mt_lo = fmaxf(mt_lo, __shfl_xor_sync(0xffffffffu, mt_lo, 1));
            mt_lo = fmaxf(mt_lo, __shfl_xor_sync(0xffffffffu, mt_lo, 2));
            mt_hi = fmaxf(mt_hi, __shfl_xor_sync(0xffffffffu, mt_hi, 1));
            mt_hi = fmaxf(mt_hi, __shfl_xor_sync(0xffffffffu, mt_hi, 2));

            float mn_lo = fmaxf(m_lo, mt_lo), mn_hi = fmaxf(m_hi, mt_hi);
            float a_lo = exp2f(m_lo - mn_lo), a_hi = exp2f(m_hi - mn_hi);
            m_lo = mn_lo; m_hi = mn_hi;

            float rs_lo = 0.f, rs_hi = 0.f;
#pragma unroll
            for (int n = 0; n < 8; n++) {
                s[n][0] = exp2f(s[n][0] - mn_lo);
                s[n][1] = exp2f(s[n][1] - mn_lo);
                s[n][2] = exp2f(s[n][2] - mn_hi);
                s[n][3] = exp2f(s[n][3] - mn_hi);
                rs_lo += s[n][0] + s[n][1];
                rs_hi += s[n][2] + s[n][3];
            }
            rs_lo += __shfl_xor_sync(0xffffffffu, rs_lo, 1);
            rs_lo += __shfl_xor_sync(0xffffffffu, rs_lo, 2);
            rs_hi += __shfl_xor_sync(0xffffffffu, rs_hi, 1);
            rs_hi += __shfl_xor_sync(0xffffffffu, rs_hi, 2);
            l_lo = a_lo * l_lo + rs_lo;
            l_hi = a_hi * l_hi + rs_hi;
#pragma unroll
            for (int n = 0; n < 8; n++) {
                o[n][0] *= a_lo; o[n][1] *= a_lo;
                o[n][2] *= a_hi; o[n][3] *= a_hi;
            }

            uint32_t vbase = st + 2 * FMATB;
#pragma unroll
            for (int ks = 0; ks < 4; ks++) {
                uint32_t ph[4], pl[4];
                split2(s[2 * ks][0],     s[2 * ks][1],     ph[0], pl[0]);
                split2(s[2 * ks][2],     s[2 * ks][3],     ph[1], pl[1]);
                split2(s[2 * ks + 1][0], s[2 * ks + 1][1], ph[2], pl[2]);
                split2(s[2 * ks + 1][2], s[2 * ks + 1][3], ph[3], pl[3]);
                int rv = ks * 16 + vrowf;
                int vx = rv & 7;
#pragma unroll
                for (int pp = 0; pp < 2; pp++) {
                    int p0 = pp * 2;
                    uint32_t va0 = vbase + rv * 128 + (((p0 * 2 + vsel) ^ vx) << 4);
                    uint32_t va1 = vbase + rv * 128 + ((((p0 + 1) * 2 + vsel) ^ vx) << 4);
                    uint32_t vh0[4], vl0[4], vh1[4], vl1[4];
                    ldsm4t(vh0, va0);
                    ldsm4t(vl0, va0 + FMATB);
                    ldsm4t(vh1, va1);
                    ldsm4t(vl1, va1 + FMATB);
                    mma16816(o[2 * p0],     ph, &vh0[0]);
                    mma16816(o[2 * p0 + 1], ph, &vh0[2]);
                    mma16816(o[2 * p0 + 2], ph, &vh1[0]);
                    mma16816(o[2 * p0 + 3], ph, &vh1[2]);
                    mma16816(o[2 * p0],     ph, &vl0[0]);
                    mma16816(o[2 * p0 + 1], ph, &vl0[2]);
                    mma16816(o[2 * p0 + 2], ph, &vl1[0]);
                    mma16816(o[2 * p0 + 3], ph, &vl1[2]);
                    mma16816(o[2 * p0],     pl, &vh0[0]);
                    mma16816(o[2 * p0 + 1], pl, &vh0[2]);
                    mma16816(o[2 * p0 + 2], pl, &vh1[0]);
                    mma16816(o[2 * p0 + 3], pl, &vh1[2]);
                }
            }
        }
        __syncthreads();
    }

    float inv_lo = 1.f / l_lo, inv_hi = 1.f / l_hi;
    int tok_lo = tok0 + qbase + wid * 16 + rlo;
    int tok_hi = tok_lo + 8;
#pragma unroll
    for (int n = 0; n < 8; n++) {
        int c = hh * 64 + n * 8 + mycol0;
        uint32_t h, l;
        split2(o[n][0] * inv_lo, o[n][1] * inv_lo, h, l);
        *(uint32_t*)(atth + (size_t)tok_lo * N_EMBD + c) = h;
        *(uint32_t*)(attl + (size_t)tok_lo * N_EMBD + c) = l;
        split2(o[n][2] * inv_hi, o[n][3] * inv_hi, h, l);
        *(uint32_t*)(atth + (size_t)tok_hi * N_EMBD + c) = h;
        *(uint32_t*)(attl + (size_t)tok_hi * N_EMBD + c) = l;
    }
}

// ---------------------------------------------------------------------------
extern "C" void kernel_launch(void* const* d_in, const int* in_sizes, int n_in,
                              void* d_out, int out_size)
{
    const float* x      = (const float*)d_in[0];
    const float* W_attn = (const float*)d_in[1];
    const float* b_attn = (const float*)d_in[2];
    const float* W_proj = (const float*)d_in[3];
    const float* b_proj = (const float*)d_in[4];
    float* out = (float*)d_out;

    __nv_bfloat16 *xhi, *xlo, *qkvh, *qkvl, *atth, *attl, *wahi, *walo, *wphi, *wplo;
    cudaGetSymbolAddress((void**)&xhi, g_xhi);
    cudaGetSymbolAddress((void**)&xlo, g_xlo);
    cudaGetSymbolAddress((void**)&qkvh, g_qkvh);
    cudaGetSymbolAddress((void**)&qkvl, g_qkvl);
    cudaGetSymbolAddress((void**)&atth, g_atth);
    cudaGetSymbolAddress((void**)&attl, g_attl);
    cudaGetSymbolAddress((void**)&wahi, g_wahi);
    cudaGetSymbolAddress((void**)&walo, g_walo);
    cudaGetSymbolAddress((void**)&wphi, g_wphi);
    cudaGetSymbolAddress((void**)&wplo, g_wplo);

    cudaFuncSetAttribute(gemm_mma<true>,
                         cudaFuncAttributeMaxDynamicSharedMemorySize, GSMEM);
    cudaFuncSetAttribute(gemm_mma<false>,
                         cudaFuncAttributeMaxDynamicSharedMemorySize, GSMEM);
    cudaFuncSetAttribute(flash_mma,
                         cudaFuncAttributeMaxDynamicSharedMemorySize, FSMEM);

    cvt_hilo<<<(M_ROWS * N_EMBD / 4 + 255) / 256, 256>>>(x, xhi, xlo, M_ROWS * N_EMBD / 4);
    cvt_t_hilo<<<dim3(E3 / 32, N_EMBD / 32), dim3(32, 8)>>>(W_attn, wahi, walo, N_EMBD, E3);
    cvt_t_hilo<<<dim3(N_EMBD / 32, N_EMBD / 32), dim3(32, 8)>>>(W_proj, wphi, wplo, N_EMBD, N_EMBD);

    gemm_mma<true><<<dim3(E3 / 128, M_ROWS / 128), 128, GSMEM>>>(
        xhi, xlo, wahi, walo, b_attn, nullptr, qkvh, qkvl, M_ROWS, E3, N_EMBD);

    flash_mma<<<dim3(2 * N_HEADS, S_LEN / 128), 256, FSMEM>>>(qkvh, qkvl, atth, attl);

    gemm_mma<false><<<dim3(N_EMBD / 128, M_ROWS / 128), 128, GSMEM>>>(
        atth, attl, wphi, wplo, b_proj, out, nullptr, nullptr, M_ROWS, N_EMBD, N_EMBD);
}

// round 10
// speedup vs baseline: 4.6299x; 1.2050x over previous
#include <cuda_runtime.h>
#include <cuda_bf16.h>
#include <cuda_fp16.h>
#include <math_constants.h>
#include <cstdint>

// ---------------------------------------------------------------------------
// MultiHeadAttention, B=2,S=2048,H=16,D=64,E=1024.
// GEMMs (round 10): fp16 one-sided split — C = Ah*(Bh+Bl), A rounded to
// single fp16 (11 mantissa bits), B split hi/lo fp16. 2 MMA passes instead
// of bf16-3-term's 3. Error ~2^-12 rel per GEMM (~1.4e-4), total ~3e-4.
// Flash: unchanged bf16 hi/lo 3-term (logit precision), 2 CTAs/SM.
//   1) qkv(bf16 hi,lo) = split( x_f16 @ Wattn_f16(hi+lo) + b )
//   2) att(fp16)       = flash(qkv)
//   3) out(fp32)       = att_f16 @ Wproj_f16(hi+lo) + b
// ---------------------------------------------------------------------------

#define S_LEN   2048
#define N_EMBD  1024
#define E3      3072
#define N_HEADS 16
#define M_ROWS  4096

__device__ __half         g_xf[(size_t)M_ROWS * N_EMBD];
__device__ __half         g_attf[(size_t)M_ROWS * N_EMBD];
__device__ __nv_bfloat16  g_qkvh[(size_t)M_ROWS * E3];
__device__ __nv_bfloat16  g_qkvl[(size_t)M_ROWS * E3];
__device__ __half         g_wahi[(size_t)E3 * N_EMBD];     // W_attn^T fp16 hi
__device__ __half         g_walo[(size_t)E3 * N_EMBD];     // W_attn^T fp16 lo
__device__ __half         g_wphi[(size_t)N_EMBD * N_EMBD];
__device__ __half         g_wplo[(size_t)N_EMBD * N_EMBD];

// ------------------------- helpers ------------------------------------------
__device__ __forceinline__ uint32_t smem_u32(const void* p) {
    uint32_t a;
    asm("{ .reg .u64 t; cvta.to.shared.u64 t, %1; cvt.u32.u64 %0, t; }"
        : "=r"(a) : "l"(p));
    return a;
}
__device__ __forceinline__ void cp16(uint32_t dst, const void* src) {
    asm volatile("cp.async.cg.shared.global [%0], [%1], 16;" :: "r"(dst), "l"(src));
}
#define CP_COMMIT() asm volatile("cp.async.commit_group;" ::: "memory")
#define CP_WAIT1()  asm volatile("cp.async.wait_group 1;"  ::: "memory")

__device__ __forceinline__ void ldsm4(uint32_t* r, uint32_t addr) {
    asm volatile("ldmatrix.sync.aligned.m8n8.x4.shared.b16 {%0,%1,%2,%3}, [%4];"
                 : "=r"(r[0]), "=r"(r[1]), "=r"(r[2]), "=r"(r[3]) : "r"(addr));
}
__device__ __forceinline__ void ldsm4t(uint32_t* r, uint32_t addr) {
    asm volatile("ldmatrix.sync.aligned.m8n8.x4.trans.shared.b16 {%0,%1,%2,%3}, [%4];"
                 : "=r"(r[0]), "=r"(r[1]), "=r"(r[2]), "=r"(r[3]) : "r"(addr));
}
// bf16 MMA (flash)
__device__ __forceinline__ void mma16816(float* d, const uint32_t* a, const uint32_t* b) {
    asm volatile(
        "mma.sync.aligned.m16n8k16.row.col.f32.bf16.bf16.f32 "
        "{%0,%1,%2,%3}, {%4,%5,%6,%7}, {%8,%9}, {%0,%1,%2,%3};"
        : "+f"(d[0]), "+f"(d[1]), "+f"(d[2]), "+f"(d[3])
        : "r"(a[0]), "r"(a[1]), "r"(a[2]), "r"(a[3]), "r"(b[0]), "r"(b[1]));
}
// fp16 MMA (GEMMs)
__device__ __forceinline__ void mma16816h(float* d, const uint32_t* a, const uint32_t* b) {
    asm volatile(
        "mma.sync.aligned.m16n8k16.row.col.f32.f16.f16.f32 "
        "{%0,%1,%2,%3}, {%4,%5,%6,%7}, {%8,%9}, {%0,%1,%2,%3};"
        : "+f"(d[0]), "+f"(d[1]), "+f"(d[2]), "+f"(d[3])
        : "r"(a[0]), "r"(a[1]), "r"(a[2]), "r"(a[3]), "r"(b[0]), "r"(b[1]));
}
// bf16 split: truncation hi + exact residual lo (flash path)
__device__ __forceinline__ void split2(float a, float b, uint32_t& hi, uint32_t& lo) {
    uint32_t ua = __float_as_uint(a) & 0xFFFF0000u;
    uint32_t ub = __float_as_uint(b) & 0xFFFF0000u;
    hi = __byte_perm(ua, ub, 0x7632);
    float la = a - __uint_as_float(ua);
    float lb = b - __uint_as_float(ub);
    asm("cvt.rn.bf16x2.f32 %0, %1, %2;" : "=r"(lo) : "f"(lb), "f"(la));
}

// ---------------------------------------------------------------------------
// fp32 -> fp16 cast (x)
__global__ void cvt_f16(const float* __restrict__ in, __half* __restrict__ out, int n4)
{
    int i = blockIdx.x * blockDim.x + threadIdx.x;
    if (i >= n4) return;
    float4 v = ((const float4*)in)[i];
    __half2 a = __floats2half2_rn(v.x, v.y);
    __half2 b = __floats2half2_rn(v.z, v.w);
    uint2 o = { *(uint32_t*)&a, *(uint32_t*)&b };
    ((uint2*)out)[i] = o;
}

// transpose W[K][N] -> T[N][K] with fp16 hi/lo split
__global__ void cvt_t_hilo16(const float* __restrict__ W, __half* __restrict__ Thi,
                             __half* __restrict__ Tlo, int K, int N)
{
    __shared__ float tile[32][33];
    int k0 = blockIdx.y * 32, n0 = blockIdx.x * 32;
    int tx = threadIdx.x, ty = threadIdx.y;
#pragma unroll
    for (int i = ty; i < 32; i += 8)
        tile[i][tx] = W[(size_t)(k0 + i) * N + n0 + tx];
    __syncthreads();
#pragma unroll
    for (int i = ty; i < 32; i += 8) {
        float v = tile[tx][i];
        __half h = __float2half_rn(v);
        __half l = __float2half_rn(v - __half2float(h));
        size_t o = (size_t)(n0 + i) * K + k0 + tx;
        Thi[o] = h; Tlo[o] = l;
    }
}

// ---------------------------------------------------------------------------
// fp16 GEMM: C[M,N] = A[M,K] @ (Bh+Bl)[N,K]^T + bias. A single fp16, B hi/lo.
// 128x128 CTA, BK=32, 4 warps (64x64), 3 stages of [A|Bh|Bl] (24KB),
// XOR-swizzled 64B rows, 1 barrier/ktile, 2 CTAs/SM, 128 threads.
// HILO=true: bf16 hi/lo outputs (for flash); else fp32 + bias.
// ---------------------------------------------------------------------------
#define MATB   8192
#define STAGEB (3 * MATB)        // 24576
#define GSMEM  (3 * STAGEB)      // 73728

template <bool HILO>
__global__ __launch_bounds__(128, 2)
void gemm_mma(const __half* __restrict__ A,
              const __half* __restrict__ Bhi, const __half* __restrict__ Blo,
              const float* __restrict__ bias, float* __restrict__ Cf,
              __nv_bfloat16* __restrict__ Ch, __nv_bfloat16* __restrict__ Cl,
              int M, int N, int K)
{
    extern __shared__ char smem[];
    uint32_t sb = smem_u32(smem);
    int t = threadIdx.x, wid = t >> 5, lid = t & 31;
    int m0 = blockIdx.y * 128, n0 = blockIdx.x * 128;
    int wm = wid & 1, wn = wid >> 1;   // 2x2 warp grid, 64x64 tiles

    const __half* gp[3] = {
        A + (size_t)m0 * K, Bhi + (size_t)n0 * K, Blo + (size_t)n0 * K };

    const int lc = t & 3;
    const int lr = t >> 2;                  // 0..31
    const int lx = (lr >> 1) & 3;           // xor invariant under +32
    const uint32_t wbase = (uint32_t)((lc ^ lx) << 4) + lr * 64;

    float acc[4][8][4];   // 128 regs
#pragma unroll
    for (int i = 0; i < 4; i++)
#pragma unroll
        for (int j = 0; j < 8; j++)
#pragma unroll
            for (int v = 0; v < 4; v++) acc[i][j][v] = 0.f;

    int nkt = K / 32;

    // prologue: stages 0,1
#pragma unroll
    for (int s = 0; s < 2; s++) {
        uint32_t st = sb + s * STAGEB;
        int koff = s * 32;
#pragma unroll
        for (int mat = 0; mat < 3; mat++)
#pragma unroll
            for (int r4 = 0; r4 < 4; r4++)
                cp16(st + mat * MATB + wbase + r4 * 32 * 64,
                     gp[mat] + (size_t)(lr + r4 * 32) * K + koff + lc * 8);
        CP_COMMIT();
    }

    const int arow = lid & 15, asel = lid >> 4;
    const int axor = (arow >> 1) & 3;
    const int browl = ((lid >> 4) & 1) * 8 + (lid & 7);
    const int bsel = (lid >> 3) & 1;
    const int bxor = (browl >> 1) & 3;

    int rd = 0, wr = 2;
    for (int kt = 0; kt < nkt; kt++) {
        CP_WAIT1();
        __syncthreads();

        uint32_t st = sb + rd * STAGEB;

#pragma unroll
        for (int kb = 0; kb < 2; kb++) {
            uint32_t ah[4][4];
#pragma unroll
            for (int mt = 0; mt < 4; mt++) {
                uint32_t ad = st + (uint32_t)(wm * 64 + mt * 16 + arow) * 64
                              + (uint32_t)(((kb * 2 + asel) ^ axor) << 4);
                ldsm4(ah[mt], ad);
            }
#pragma unroll
            for (int p = 0; p < 4; p++) {
                uint32_t bd = st + MATB
                              + (uint32_t)(wn * 64 + p * 16 + browl) * 64
                              + (uint32_t)(((kb * 2 + bsel) ^ bxor) << 4);
                uint32_t bh[4], bl[4];
                ldsm4(bh, bd);
                ldsm4(bl, bd + MATB);
#pragma unroll
                for (int mt = 0; mt < 4; mt++) {
                    mma16816h(acc[mt][2 * p],     ah[mt], &bh[0]);
                    mma16816h(acc[mt][2 * p + 1], ah[mt], &bh[2]);
                }
#pragma unroll
                for (int mt = 0; mt < 4; mt++) {
                    mma16816h(acc[mt][2 * p],     ah[mt], &bl[0]);
                    mma16816h(acc[mt][2 * p + 1], ah[mt], &bl[2]);
                }
            }
        }

        if (kt + 2 < nkt) {
            uint32_t st2 = sb + wr * STAGEB;
            int koff = (kt + 2) * 32;
#pragma unroll
            for (int mat = 0; mat < 3; mat++)
#pragma unroll
                for (int r4 = 0; r4 < 4; r4++)
                    cp16(st2 + mat * MATB + wbase + r4 * 32 * 64,
                         gp[mat] + (size_t)(lr + r4 * 32) * K + koff + lc * 8);
        }
        CP_COMMIT();
        rd = (rd == 2) ? 0 : rd + 1;
        wr = (wr == 2) ? 0 : wr + 1;
    }

    int rA = m0 + wm * 64 + (lid >> 2);
    int cA = n0 + wn * 64 + 2 * (lid & 3);
#pragma unroll
    for (int mt = 0; mt < 4; mt++) {
        int r = rA + mt * 16;
#pragma unroll
        for (int nt = 0; nt < 8; nt++) {
            int c = cA + nt * 8;
            float b0 = bias[c], b1 = bias[c + 1];
            float v00 = acc[mt][nt][0] + b0, v01 = acc[mt][nt][1] + b1;
            float v10 = acc[mt][nt][2] + b0, v11 = acc[mt][nt][3] + b1;
            if (HILO) {
                uint32_t h, l;
                split2(v00, v01, h, l);
                *(uint32_t*)(Ch + (size_t)r * N + c) = h;
                *(uint32_t*)(Cl + (size_t)r * N + c) = l;
                split2(v10, v11, h, l);
                *(uint32_t*)(Ch + (size_t)(r + 8) * N + c) = h;
                *(uint32_t*)(Cl + (size_t)(r + 8) * N + c) = l;
            } else {
                float2 w0 = {v00, v01}, w1 = {v10, v11};
                *(float2*)(Cf + (size_t)r * N + c)       = w0;
                *(float2*)(Cf + (size_t)(r + 8) * N + c) = w1;
            }
        }
    }
}

// ---------------------------------------------------------------------------
// Tensor-core causal flash attention (bf16 hi/lo 3-term; unchanged except
// epilogue now emits single fp16). 128 q-rows, 8 warps, 2 CTAs/SM.
// ---------------------------------------------------------------------------
#define QMATB   16384
#define FMATB   8192
#define FSTAGE  (4 * FMATB)
#define FSMEM   (2 * QMATB + 2 * FSTAGE)  // 98304
#define SCALE_L2E 0.18033688011112042f

__global__ __launch_bounds__(256, 2)
void flash_mma(const __nv_bfloat16* __restrict__ qkvh,
               const __nv_bfloat16* __restrict__ qkvl,
               __half* __restrict__ attf)
{
    extern __shared__ char smem[];
    uint32_t sb = smem_u32(smem);
    int t = threadIdx.x, wid = t >> 5, lid = t & 31;
    int bh = blockIdx.x;
    int b = bh >> 4, hh = bh & 15;
    int qt = (int)gridDim.y - 1 - blockIdx.y;
    int qbase = qt * 128;
    int tok0 = b * S_LEN;

    const uint32_t QH = sb, QL = sb + QMATB;
    const uint32_t KV0 = sb + 2 * QMATB;

    const int qlrow  = t >> 1;
    const int qlcol0 = (t & 1) * 4;
    const int klrow  = t >> 2;
    const int klcol0 = (t & 3) * 2;
    const int klx = klrow & 7;

    {
        size_t rq = (size_t)(tok0 + qbase + qlrow) * E3 + hh * 64;
        int qx = qlrow & 7;
#pragma unroll
        for (int u = 0; u < 4; u++) {
            int ch = qlcol0 + u;
            uint32_t d = qlrow * 128 + ((ch ^ qx) << 4);
            cp16(QH + d, qkvh + rq + ch * 8);
            cp16(QL + d, qkvl + rq + ch * 8);
        }
        size_t rk = (size_t)(tok0 + klrow) * E3 + 1024 + hh * 64;
#pragma unroll
        for (int u = 0; u < 2; u++) {
            int ch = klcol0 + u;
            uint32_t d = klrow * 128 + ((ch ^ klx) << 4);
            cp16(KV0 + d,             qkvh + rk + ch * 8);
            cp16(KV0 + FMATB + d,     qkvl + rk + ch * 8);
            cp16(KV0 + 2 * FMATB + d, qkvh + rk + 1024 + ch * 8);
            cp16(KV0 + 3 * FMATB + d, qkvl + rk + 1024 + ch * 8);
        }
    }
    CP_COMMIT();

    const int arow = lid & 15, asel = lid >> 4;
    const int qrow = wid * 16 + arow;
    const int qx = qrow & 7;
    const int browf = ((lid >> 4) & 1) * 8 + (lid & 7);
    const int bsel = (lid >> 3) & 1;
    const int vrowf = ((lid >> 3) & 1) * 8 + (lid & 7);
    const int vsel = (lid >> 4) & 1;

    uint32_t qh[4][4];
    float o[8][4];
#pragma unroll
    for (int n = 0; n < 8; n++)
#pragma unroll
        for (int v = 0; v < 4; v++) o[n][v] = 0.f;
    float m_lo = -CUDART_INF_F, m_hi = -CUDART_INF_F, l_lo = 0.f, l_hi = 0.f;

    const int rlo = lid >> 2;
    const int rloc = 16 * (wid & 3) + rlo;
    const int mycol0 = 2 * (lid & 3);
    const int kt_d = 2 * qt + (wid >> 2);
    const int ntiles = 2 * qt + 2;

    for (int kt = 0; kt < ntiles; kt++) {
        if (kt + 1 < ntiles) {
            uint32_t st = KV0 + ((kt + 1) & 1) * FSTAGE;
            size_t rk = (size_t)(tok0 + (kt + 1) * 64 + klrow) * E3 + 1024 + hh * 64;
#pragma unroll
            for (int u = 0; u < 2; u++) {
                int ch = klcol0 + u;
                uint32_t d = klrow * 128 + ((ch ^ klx) << 4);
                cp16(st + d,             qkvh + rk + ch * 8);
                cp16(st + FMATB + d,     qkvl + rk + ch * 8);
                cp16(st + 2 * FMATB + d, qkvh + rk + 1024 + ch * 8);
                cp16(st + 3 * FMATB + d, qkvl + rk + 1024 + ch * 8);
            }
        }
        CP_COMMIT();
        CP_WAIT1();
        __syncthreads();

        if (kt == 0) {
#pragma unroll
            for (int ks = 0; ks < 4; ks++) {
                uint32_t ad = QH + qrow * 128 + (((ks * 2 + asel) ^ qx) << 4);
                ldsm4(qh[ks], ad);
            }
        }

        if (kt <= kt_d) {
            uint32_t st = KV0 + (kt & 1) * FSTAGE;

            float s[8][4];
#pragma unroll
            for (int n = 0; n < 8; n++)
#pragma unroll
                for (int v = 0; v < 4; v++) s[n][v] = 0.f;

#pragma unroll
            for (int ks = 0; ks < 4; ks++) {
                uint32_t qlt[4];
                ldsm4(qlt, QL + qrow * 128 + (((ks * 2 + asel) ^ qx) << 4));
#pragma unroll
                for (int pp = 0; pp < 2; pp++) {
                    int p0 = pp * 2;
                    int rk0 = p0 * 16 + browf, rk1 = rk0 + 16;
                    uint32_t ka0 = st + rk0 * 128 + (((ks * 2 + bsel) ^ (rk0 & 7)) << 4);
                    uint32_t ka1 = st + rk1 * 128 + (((ks * 2 + bsel) ^ (rk1 & 7)) << 4);
                    uint32_t kh0[4], kl0[4], kh1[4], kl1[4];
                    ldsm4(kh0, ka0);
                    ldsm4(kl0, ka0 + FMATB);
                    ldsm4(kh1, ka1);
                    ldsm4(kl1, ka1 + FMATB);
                    mma16816(s[2 * p0],     qh[ks], &kh0[0]);
                    mma16816(s[2 * p0 + 1], qh[ks], &kh0[2]);
                    mma16816(s[2 * p0 + 2], qh[ks], &kh1[0]);
                    mma16816(s[2 * p0 + 3], qh[ks], &kh1[2]);
                    mma16816(s[2 * p0],     qh[ks], &kl0[0]);
                    mma16816(s[2 * p0 + 1], qh[ks], &kl0[2]);
                    mma16816(s[2 * p0 + 2], qh[ks], &kl1[0]);
                    mma16816(s[2 * p0 + 3], qh[ks], &kl1[2]);
                    mma16816(s[2 * p0],     qlt, &kh0[0]);
                    mma16816(s[2 * p0 + 1], qlt, &kh0[2]);
                    mma16816(s[2 * p0 + 2], qlt, &kh1[0]);
                    mma16816(s[2 * p0 + 3], qlt, &kh1[2]);
                }
            }

#pragma unroll
            for (int n = 0; n < 8; n++)
#pragma unroll
                for (int v = 0; v < 4; v++) s[n][v] *= SCALE_L2E;

            if (kt == kt_d) {
#pragma unroll
                for (int n = 0; n < 8; n++) {
                    int c0 = n * 8 + mycol0;
                    if (c0 > rloc)     s[n][0] = -CUDART_INF_F;
                    if (c0 + 1 > rloc) s[n][1] = -CUDART_INF_F;
                    if (c0 > rloc + 8)     s[n][2] = -CUDART_INF_F;
                    if (c0 + 1 > rloc + 8) s[n][3] = -CUDART_INF_F;
                }
            }

            float mt_lo = -CUDART_INF_F, mt_hi = -CUDART_INF_F;
#pragma unroll
            for (int n = 0; n < 8; n++) {
                mt_lo = fmaxf(mt_lo, fmaxf(s[n][0], s[n][1]));
                mt_hi = fmaxf(mt_hi, fmaxf(s[n][2], s[n][3]));
            }
            mt_lo = fmaxf(mt_lo, __shfl_xor_sync(0xffffffffu, mt_lo, 1));
            mt_lo = fmaxf(mt_lo, __shfl_xor_sync(0xffffffffu, mt_lo, 2));
            mt_hi = fmaxf(mt_hi, __shfl_xor_sync(0xffffffffu, mt_hi, 1));
            mt_hi = fmaxf(mt_hi, __shfl_xor_sync(0xffffffffu, mt_hi, 2));

            float mn_lo = fmaxf(m_lo, mt_lo), mn_hi = fmaxf(m_hi, mt_hi);
            float a_lo = exp2f(m_lo - mn_lo), a_hi = exp2f(m_hi - mn_hi);
            m_lo = mn_lo; m_hi = mn_hi;

            float rs_lo = 0.f, rs_hi = 0.f;
#pragma unroll
            for (int n = 0; n < 8; n++) {
                s[n][0] = exp2f(s[n][0] - mn_lo);
                s[n][1] = exp2f(s[n][1] - mn_lo);
                s[n][2] = exp2f(s[n][2] - mn_hi);
                s[n][3] = exp2f(s[n][3] - mn_hi);
                rs_lo += s[n][0] + s[n][1];
                rs_hi += s[n][2] + s[n][3];
            }
            rs_lo += __shfl_xor_sync(0xffffffffu, rs_lo, 1);
            rs_lo += __shfl_xor_sync(0xffffffffu, rs_lo, 2);
            rs_hi += __shfl_xor_sync(0xffffffffu, rs_hi, 1);
            rs_hi += __shfl_xor_sync(0xffffffffu, rs_hi, 2);
            l_lo = a_lo * l_lo + rs_lo;
            l_hi = a_hi * l_hi + rs_hi;
#pragma unroll
            for (int n = 0; n < 8; n++) {
                o[n][0] *= a_lo; o[n][1] *= a_lo;
                o[n][2] *= a_hi; o[n][3] *= a_hi;
            }

            uint32_t vbase = st + 2 * FMATB;
#pragma unroll
            for (int ks = 0; ks < 4; ks++) {
                uint32_t ph[4], pl[4];
                split2(s[2 * ks][0],     s[2 * ks][1],     ph[0], pl[0]);
                split2(s[2 * ks][2],     s[2 * ks][3],     ph[1], pl[1]);
                split2(s[2 * ks + 1][0], s[2 * ks + 1][1], ph[2], pl[2]);
                split2(s[2 * ks + 1][2], s[2 * ks + 1][3], ph[3], pl[3]);
                int rv = ks * 16 + vrowf;
                int vx = rv & 7;
#pragma unroll
                for (int pp = 0; pp < 2; pp++) {
                    int p0 = pp * 2;
                    uint32_t va0 = vbase + rv * 128 + (((p0 * 2 + vsel) ^ vx) << 4);
                    uint32_t va1 = vbase + rv * 128 + ((((p0 + 1) * 2 + vsel) ^ vx) << 4);
                    uint32_t vh0[4], vl0[4], vh1[4], vl1[4];
                    ldsm4t(vh0, va0);
                    ldsm4t(vl0, va0 + FMATB);
                    ldsm4t(vh1, va1);
                    ldsm4t(vl1, va1 + FMATB);
                    mma16816(o[2 * p0],     ph, &vh0[0]);
                    mma16816(o[2 * p0 + 1], ph, &vh0[2]);
                    mma16816(o[2 * p0 + 2], ph, &vh1[0]);
                    mma16816(o[2 * p0 + 3], ph, &vh1[2]);
                    mma16816(o[2 * p0],     ph, &vl0[0]);
                    mma16816(o[2 * p0 + 1], ph, &vl0[2]);
                    mma16816(o[2 * p0 + 2], ph, &vl1[0]);
                    mma16816(o[2 * p0 + 3], ph, &vl1[2]);
                    mma16816(o[2 * p0],     pl, &vh0[0]);
                    mma16816(o[2 * p0 + 1], pl, &vh0[2]);
                    mma16816(o[2 * p0 + 2], pl, &vh1[0]);
                    mma16816(o[2 * p0 + 3], pl, &vh1[2]);
                }
            }
        }
        __syncthreads();
    }

    // ---- epilogue: normalize, cast to single fp16 ----
    float inv_lo = 1.f / l_lo, inv_hi = 1.f / l_hi;
    int tok_lo = tok0 + qbase + wid * 16 + rlo;
    int tok_hi = tok_lo + 8;
#pragma unroll
    for (int n = 0; n < 8; n++) {
        int c = hh * 64 + n * 8 + mycol0;
        __half2 h0 = __floats2half2_rn(o[n][0] * inv_lo, o[n][1] * inv_lo);
        __half2 h1 = __floats2half2_rn(o[n][2] * inv_hi, o[n][3] * inv_hi);
        *(__half2*)(attf + (size_t)tok_lo * N_EMBD + c) = h0;
        *(__half2*)(attf + (size_t)tok_hi * N_EMBD + c) = h1;
    }
}

// ---------------------------------------------------------------------------
extern "C" void kernel_launch(void* const* d_in, const int* in_sizes, int n_in,
                              void* d_out, int out_size)
{
    const float* x      = (const float*)d_in[0];
    const float* W_attn = (const float*)d_in[1];
    const float* b_attn = (const float*)d_in[2];
    const float* W_proj = (const float*)d_in[3];
    const float* b_proj = (const float*)d_in[4];
    float* out = (float*)d_out;

    __half *xf, *attf, *wahi, *walo, *wphi, *wplo;
    __nv_bfloat16 *qkvh, *qkvl;
    cudaGetSymbolAddress((void**)&xf, g_xf);
    cudaGetSymbolAddress((void**)&attf, g_attf);
    cudaGetSymbolAddress((void**)&qkvh, g_qkvh);
    cudaGetSymbolAddress((void**)&qkvl, g_qkvl);
    cudaGetSymbolAddress((void**)&wahi, g_wahi);
    cudaGetSymbolAddress((void**)&walo, g_walo);
    cudaGetSymbolAddress((void**)&wphi, g_wphi);
    cudaGetSymbolAddress((void**)&wplo, g_wplo);

    cudaFuncSetAttribute(gemm_mma<true>,
                         cudaFuncAttributeMaxDynamicSharedMemorySize, GSMEM);
    cudaFuncSetAttribute(gemm_mma<false>,
                         cudaFuncAttributeMaxDynamicSharedMemorySize, GSMEM);
    cudaFuncSetAttribute(flash_mma,
                         cudaFuncAttributeMaxDynamicSharedMemorySize, FSMEM);

    // operand preparation
    cvt_f16<<<(M_ROWS * N_EMBD / 4 + 255) / 256, 256>>>(x, xf, M_ROWS * N_EMBD / 4);
    cvt_t_hilo16<<<dim3(E3 / 32, N_EMBD / 32), dim3(32, 8)>>>(W_attn, wahi, walo, N_EMBD, E3);
    cvt_t_hilo16<<<dim3(N_EMBD / 32, N_EMBD / 32), dim3(32, 8)>>>(W_proj, wphi, wplo, N_EMBD, N_EMBD);

    // 1) QKV projection (fp16 2-term) -> bf16 hi/lo for flash
    gemm_mma<true><<<dim3(E3 / 128, M_ROWS / 128), 128, GSMEM>>>(
        xf, wahi, walo, b_attn, nullptr, qkvh, qkvl, M_ROWS, E3, N_EMBD);

    // 2) causal flash attention (bf16 3-term) -> fp16
    flash_mma<<<dim3(2 * N_HEADS, S_LEN / 128), 256, FSMEM>>>(qkvh, qkvl, attf);

    // 3) output projection (fp16 2-term) -> fp32
    gemm_mma<false><<<dim3(N_EMBD / 128, M_ROWS / 128), 128, GSMEM>>>(
        attf, wphi, wplo, b_proj, out, nullptr, nullptr, M_ROWS, N_EMBD, N_EMBD);
}

// round 11
// speedup vs baseline: 5.1130x; 1.1043x over previous
#include <cuda_runtime.h>
#include <cuda_bf16.h>
#include <cuda_fp16.h>
#include <math_constants.h>
#include <cstdint>

// ---------------------------------------------------------------------------
// MultiHeadAttention, B=2,S=2048,H=16,D=64,E=1024. All-fp16 HMMA pipeline
// with one-sided hi/lo split precision (11+11 mantissa bits on one operand).
//   1) qkv = x_f16 @ Wattn(hi+lo) + b :  Q -> single fp16, K/V -> fp16 hi/lo
//   2) att(fp16) = flash(qkv):  S = Qh*(Kh+Kl),  O = Ph*(Vh+Vl)  [4 passes]
//   3) out(fp32) = att @ Wproj(hi+lo) + b
// Round-10 result: fp16 2-term GEMM gave rel_err 3.1e-4 (3x margin); this
// round applies the same scheme to flash (was bf16 3-term, 6 passes).
// ---------------------------------------------------------------------------

#define S_LEN   2048
#define N_EMBD  1024
#define E3      3072
#define N_HEADS 16
#define M_ROWS  4096

__device__ __half g_xf[(size_t)M_ROWS * N_EMBD];
__device__ __half g_attf[(size_t)M_ROWS * N_EMBD];
__device__ __half g_qkvh[(size_t)M_ROWS * E3];   // Q single | K hi | V hi
__device__ __half g_qkvl[(size_t)M_ROWS * E3];   // (unused) | K lo | V lo
__device__ __half g_wahi[(size_t)E3 * N_EMBD];
__device__ __half g_walo[(size_t)E3 * N_EMBD];
__device__ __half g_wphi[(size_t)N_EMBD * N_EMBD];
__device__ __half g_wplo[(size_t)N_EMBD * N_EMBD];

// ------------------------- helpers ------------------------------------------
__device__ __forceinline__ uint32_t smem_u32(const void* p) {
    uint32_t a;
    asm("{ .reg .u64 t; cvta.to.shared.u64 t, %1; cvt.u32.u64 %0, t; }"
        : "=r"(a) : "l"(p));
    return a;
}
__device__ __forceinline__ void cp16(uint32_t dst, const void* src) {
    asm volatile("cp.async.cg.shared.global [%0], [%1], 16;" :: "r"(dst), "l"(src));
}
#define CP_COMMIT() asm volatile("cp.async.commit_group;" ::: "memory")
#define CP_WAIT1()  asm volatile("cp.async.wait_group 1;"  ::: "memory")

__device__ __forceinline__ void ldsm4(uint32_t* r, uint32_t addr) {
    asm volatile("ldmatrix.sync.aligned.m8n8.x4.shared.b16 {%0,%1,%2,%3}, [%4];"
                 : "=r"(r[0]), "=r"(r[1]), "=r"(r[2]), "=r"(r[3]) : "r"(addr));
}
__device__ __forceinline__ void ldsm4t(uint32_t* r, uint32_t addr) {
    asm volatile("ldmatrix.sync.aligned.m8n8.x4.trans.shared.b16 {%0,%1,%2,%3}, [%4];"
                 : "=r"(r[0]), "=r"(r[1]), "=r"(r[2]), "=r"(r[3]) : "r"(addr));
}
// fp16 MMA
__device__ __forceinline__ void mma16816h(float* d, const uint32_t* a, const uint32_t* b) {
    asm volatile(
        "mma.sync.aligned.m16n8k16.row.col.f32.f16.f16.f32 "
        "{%0,%1,%2,%3}, {%4,%5,%6,%7}, {%8,%9}, {%0,%1,%2,%3};"
        : "+f"(d[0]), "+f"(d[1]), "+f"(d[2]), "+f"(d[3])
        : "r"(a[0]), "r"(a[1]), "r"(a[2]), "r"(a[3]), "r"(b[0]), "r"(b[1]));
}
// pack two fp32 -> fp16x2 (a in low half, b in high half)
__device__ __forceinline__ uint32_t pack2h(float a, float b) {
    uint32_t r;
    asm("cvt.rn.f16x2.f32 %0, %1, %2;" : "=r"(r) : "f"(b), "f"(a));
    return r;
}
// fp16 split: hi = rn(v) packed pair, lo = exact residual packed pair
__device__ __forceinline__ void split2h(float a, float b, uint32_t& hi, uint32_t& lo) {
    __half ha = __float2half_rn(a), hb = __float2half_rn(b);
    hi = (uint32_t)__half_as_ushort(ha) | ((uint32_t)__half_as_ushort(hb) << 16);
    lo = pack2h(a - __half2float(ha), b - __half2float(hb));
}

// ---------------------------------------------------------------------------
// fp32 -> fp16 cast (x)
__global__ void cvt_f16(const float* __restrict__ in, __half* __restrict__ out, int n4)
{
    int i = blockIdx.x * blockDim.x + threadIdx.x;
    if (i >= n4) return;
    float4 v = ((const float4*)in)[i];
    uint2 o = { pack2h(v.x, v.y), pack2h(v.z, v.w) };
    ((uint2*)out)[i] = o;
}

// transpose W[K][N] -> T[N][K] with fp16 hi/lo split
__global__ void cvt_t_hilo16(const float* __restrict__ W, __half* __restrict__ Thi,
                             __half* __restrict__ Tlo, int K, int N)
{
    __shared__ float tile[32][33];
    int k0 = blockIdx.y * 32, n0 = blockIdx.x * 32;
    int tx = threadIdx.x, ty = threadIdx.y;
#pragma unroll
    for (int i = ty; i < 32; i += 8)
        tile[i][tx] = W[(size_t)(k0 + i) * N + n0 + tx];
    __syncthreads();
#pragma unroll
    for (int i = ty; i < 32; i += 8) {
        float v = tile[tx][i];
        __half h = __float2half_rn(v);
        __half l = __float2half_rn(v - __half2float(h));
        size_t o = (size_t)(n0 + i) * K + k0 + tx;
        Thi[o] = h; Tlo[o] = l;
    }
}

// ---------------------------------------------------------------------------
// fp16 GEMM: C[M,N] = A[M,K] @ (Bh+Bl)[N,K]^T + bias. A single fp16, B hi/lo.
// 128x128 CTA, BK=32, 4 warps (64x64), 3 stages of [A|Bh|Bl], XOR swizzle,
// 1 barrier/ktile, 2 CTAs/SM, 128 threads.
// HILO=true: fp16 outputs for flash — Q block (n0<1024) single fp16 (hi only),
// K/V blocks hi/lo. HILO=false: fp32 + bias.
// ---------------------------------------------------------------------------
#define MATB   8192
#define STAGEB (3 * MATB)        // 24576
#define GSMEM  (3 * STAGEB)      // 73728

template <bool HILO>
__global__ __launch_bounds__(128, 2)
void gemm_mma(const __half* __restrict__ A,
              const __half* __restrict__ Bhi, const __half* __restrict__ Blo,
              const float* __restrict__ bias, float* __restrict__ Cf,
              __half* __restrict__ Ch, __half* __restrict__ Cl,
              int M, int N, int K)
{
    extern __shared__ char smem[];
    uint32_t sb = smem_u32(smem);
    int t = threadIdx.x, wid = t >> 5, lid = t & 31;
    int m0 = blockIdx.y * 128, n0 = blockIdx.x * 128;
    int wm = wid & 1, wn = wid >> 1;

    const __half* gp[3] = {
        A + (size_t)m0 * K, Bhi + (size_t)n0 * K, Blo + (size_t)n0 * K };

    const int lc = t & 3;
    const int lr = t >> 2;
    const int lx = (lr >> 1) & 3;
    const uint32_t wbase = (uint32_t)((lc ^ lx) << 4) + lr * 64;

    float acc[4][8][4];
#pragma unroll
    for (int i = 0; i < 4; i++)
#pragma unroll
        for (int j = 0; j < 8; j++)
#pragma unroll
            for (int v = 0; v < 4; v++) acc[i][j][v] = 0.f;

    int nkt = K / 32;

#pragma unroll
    for (int s = 0; s < 2; s++) {
        uint32_t st = sb + s * STAGEB;
        int koff = s * 32;
#pragma unroll
        for (int mat = 0; mat < 3; mat++)
#pragma unroll
            for (int r4 = 0; r4 < 4; r4++)
                cp16(st + mat * MATB + wbase + r4 * 32 * 64,
                     gp[mat] + (size_t)(lr + r4 * 32) * K + koff + lc * 8);
        CP_COMMIT();
    }

    const int arow = lid & 15, asel = lid >> 4;
    const int axor = (arow >> 1) & 3;
    const int browl = ((lid >> 4) & 1) * 8 + (lid & 7);
    const int bsel = (lid >> 3) & 1;
    const int bxor = (browl >> 1) & 3;

    int rd = 0, wr = 2;
    for (int kt = 0; kt < nkt; kt++) {
        CP_WAIT1();
        __syncthreads();

        uint32_t st = sb + rd * STAGEB;

#pragma unroll
        for (int kb = 0; kb < 2; kb++) {
            uint32_t ah[4][4];
#pragma unroll
            for (int mt = 0; mt < 4; mt++) {
                uint32_t ad = st + (uint32_t)(wm * 64 + mt * 16 + arow) * 64
                              + (uint32_t)(((kb * 2 + asel) ^ axor) << 4);
                ldsm4(ah[mt], ad);
            }
#pragma unroll
            for (int p = 0; p < 4; p++) {
                uint32_t bd = st + MATB
                              + (uint32_t)(wn * 64 + p * 16 + browl) * 64
                              + (uint32_t)(((kb * 2 + bsel) ^ bxor) << 4);
                uint32_t bh[4], bl[4];
                ldsm4(bh, bd);
                ldsm4(bl, bd + MATB);
#pragma unroll
                for (int mt = 0; mt < 4; mt++) {
                    mma16816h(acc[mt][2 * p],     ah[mt], &bh[0]);
                    mma16816h(acc[mt][2 * p + 1], ah[mt], &bh[2]);
                }
#pragma unroll
                for (int mt = 0; mt < 4; mt++) {
                    mma16816h(acc[mt][2 * p],     ah[mt], &bl[0]);
                    mma16816h(acc[mt][2 * p + 1], ah[mt], &bl[2]);
                }
            }
        }

        if (kt + 2 < nkt) {
            uint32_t st2 = sb + wr * STAGEB;
            int koff = (kt + 2) * 32;
#pragma unroll
            for (int mat = 0; mat < 3; mat++)
#pragma unroll
                for (int r4 = 0; r4 < 4; r4++)
                    cp16(st2 + mat * MATB + wbase + r4 * 32 * 64,
                         gp[mat] + (size_t)(lr + r4 * 32) * K + koff + lc * 8);
        }
        CP_COMMIT();
        rd = (rd == 2) ? 0 : rd + 1;
        wr = (wr == 2) ? 0 : wr + 1;
    }

    int rA = m0 + wm * 64 + (lid >> 2);
    int cA = n0 + wn * 64 + 2 * (lid & 3);
    const bool qreg = HILO && (n0 < 1024);   // Q block: single fp16
#pragma unroll
    for (int mt = 0; mt < 4; mt++) {
        int r = rA + mt * 16;
#pragma unroll
        for (int nt = 0; nt < 8; nt++) {
            int c = cA + nt * 8;
            float b0 = bias[c], b1 = bias[c + 1];
            float v00 = acc[mt][nt][0] + b0, v01 = acc[mt][nt][1] + b1;
            float v10 = acc[mt][nt][2] + b0, v11 = acc[mt][nt][3] + b1;
            if (HILO) {
                uint32_t h, l;
                split2h(v00, v01, h, l);
                *(uint32_t*)(Ch + (size_t)r * N + c) = h;
                if (!qreg) *(uint32_t*)(Cl + (size_t)r * N + c) = l;
                split2h(v10, v11, h, l);
                *(uint32_t*)(Ch + (size_t)(r + 8) * N + c) = h;
                if (!qreg) *(uint32_t*)(Cl + (size_t)(r + 8) * N + c) = l;
            } else {
                float2 w0 = {v00, v01}, w1 = {v10, v11};
                *(float2*)(Cf + (size_t)r * N + c)       = w0;
                *(float2*)(Cf + (size_t)(r + 8) * N + c) = w1;
            }
        }
    }
}

// ---------------------------------------------------------------------------
// fp16 2-term causal flash attention. Per CTA: one (b,h), 128 q-rows,
// 8 warps x 16 rows, 64-token K tiles, 2-stage KV pipeline.
// S = Qh*(Kh+Kl), O = Ph*(Vh+Vl). XOR-swizzled 128B rows.
// SMEM: Q 16KB + 2 stages x 32KB = 80KB -> 2 CTAs/SM.
// ---------------------------------------------------------------------------
#define QMATB   16384
#define FMATB   8192
#define FSTAGE  (4 * FMATB)      // 32768 (Kh,Kl,Vh,Vl)
#define FSMEM   (QMATB + 2 * FSTAGE)  // 81920
#define SCALE_L2E 0.18033688011112042f

__global__ __launch_bounds__(256, 2)
void flash_mma(const __half* __restrict__ qkvh,
               const __half* __restrict__ qkvl,
               __half* __restrict__ attf)
{
    extern __shared__ char smem[];
    uint32_t sb = smem_u32(smem);
    int t = threadIdx.x, wid = t >> 5, lid = t & 31;
    int bh = blockIdx.x;
    int b = bh >> 4, hh = bh & 15;
    int qt = (int)gridDim.y - 1 - blockIdx.y;
    int qbase = qt * 128;
    int tok0 = b * S_LEN;

    const uint32_t QH = sb;
    const uint32_t KV0 = sb + QMATB;

    const int qlrow  = t >> 1;
    const int qlcol0 = (t & 1) * 4;
    const int klrow  = t >> 2;
    const int klcol0 = (t & 3) * 2;
    const int klx = klrow & 7;

    // prologue: Q tile + KV stage 0
    {
        size_t rq = (size_t)(tok0 + qbase + qlrow) * E3 + hh * 64;
        int qx = qlrow & 7;
#pragma unroll
        for (int u = 0; u < 4; u++) {
            int ch = qlcol0 + u;
            cp16(QH + qlrow * 128 + ((ch ^ qx) << 4), qkvh + rq + ch * 8);
        }
        size_t rk = (size_t)(tok0 + klrow) * E3 + 1024 + hh * 64;
#pragma unroll
        for (int u = 0; u < 2; u++) {
            int ch = klcol0 + u;
            uint32_t d = klrow * 128 + ((ch ^ klx) << 4);
            cp16(KV0 + d,             qkvh + rk + ch * 8);          // Kh
            cp16(KV0 + FMATB + d,     qkvl + rk + ch * 8);          // Kl
            cp16(KV0 + 2 * FMATB + d, qkvh + rk + 1024 + ch * 8);   // Vh
            cp16(KV0 + 3 * FMATB + d, qkvl + rk + 1024 + ch * 8);   // Vl
        }
    }
    CP_COMMIT();

    const int arow = lid & 15, asel = lid >> 4;
    const int qrow = wid * 16 + arow;
    const int qx = qrow & 7;
    const int browf = ((lid >> 4) & 1) * 8 + (lid & 7);
    const int bsel = (lid >> 3) & 1;
    const int vrowf = ((lid >> 3) & 1) * 8 + (lid & 7);
    const int vsel = (lid >> 4) & 1;

    uint32_t qh[4][4];
    float o[8][4];
#pragma unroll
    for (int n = 0; n < 8; n++)
#pragma unroll
        for (int v = 0; v < 4; v++) o[n][v] = 0.f;
    float m_lo = -CUDART_INF_F, m_hi = -CUDART_INF_F, l_lo = 0.f, l_hi = 0.f;

    const int rlo = lid >> 2;
    const int rloc = 16 * (wid & 3) + rlo;
    const int mycol0 = 2 * (lid & 3);
    const int kt_d = 2 * qt + (wid >> 2);
    const int ntiles = 2 * qt + 2;

    for (int kt = 0; kt < ntiles; kt++) {
        if (kt + 1 < ntiles) {
            uint32_t st = KV0 + ((kt + 1) & 1) * FSTAGE;
            size_t rk = (size_t)(tok0 + (kt + 1) * 64 + klrow) * E3 + 1024 + hh * 64;
#pragma unroll
            for (int u = 0; u < 2; u++) {
                int ch = klcol0 + u;
                uint32_t d = klrow * 128 + ((ch ^ klx) << 4);
                cp16(st + d,             qkvh + rk + ch * 8);
                cp16(st + FMATB + d,     qkvl + rk + ch * 8);
                cp16(st + 2 * FMATB + d, qkvh + rk + 1024 + ch * 8);
                cp16(st + 3 * FMATB + d, qkvl + rk + 1024 + ch * 8);
            }
        }
        CP_COMMIT();
        CP_WAIT1();
        __syncthreads();

        if (kt == 0) {   // persistent Q fragments
#pragma unroll
            for (int ks = 0; ks < 4; ks++)
                ldsm4(qh[ks], QH + qrow * 128 + (((ks * 2 + asel) ^ qx) << 4));
        }

        if (kt <= kt_d) {
            uint32_t st = KV0 + (kt & 1) * FSTAGE;

            // ---- S = Qh * (Kh + Kl) ----
            float s[8][4];
#pragma unroll
            for (int n = 0; n < 8; n++)
#pragma unroll
                for (int v = 0; v < 4; v++) s[n][v] = 0.f;

#pragma unroll
            for (int ks = 0; ks < 4; ks++) {
#pragma unroll
                for (int pp = 0; pp < 2; pp++) {
                    int p0 = pp * 2;
                    int rk0 = p0 * 16 + browf, rk1 = rk0 + 16;
                    uint32_t ka0 = st + rk0 * 128 + (((ks * 2 + bsel) ^ (rk0 & 7)) << 4);
                    uint32_t ka1 = st + rk1 * 128 + (((ks * 2 + bsel) ^ (rk1 & 7)) << 4);
                    uint32_t kh0[4], kl0[4], kh1[4], kl1[4];
                    ldsm4(kh0, ka0);
                    ldsm4(kl0, ka0 + FMATB);
                    ldsm4(kh1, ka1);
                    ldsm4(kl1, ka1 + FMATB);
                    mma16816h(s[2 * p0],     qh[ks], &kh0[0]);
                    mma16816h(s[2 * p0 + 1], qh[ks], &kh0[2]);
                    mma16816h(s[2 * p0 + 2], qh[ks], &kh1[0]);
                    mma16816h(s[2 * p0 + 3], qh[ks], &kh1[2]);
                    mma16816h(s[2 * p0],     qh[ks], &kl0[0]);
                    mma16816h(s[2 * p0 + 1], qh[ks], &kl0[2]);
                    mma16816h(s[2 * p0 + 2], qh[ks], &kl1[0]);
                    mma16816h(s[2 * p0 + 3], qh[ks], &kl1[2]);
                }
            }

#pragma unroll
            for (int n = 0; n < 8; n++)
#pragma unroll
                for (int v = 0; v < 4; v++) s[n][v] *= SCALE_L2E;

            if (kt == kt_d) {
#pragma unroll
                for (int n = 0; n < 8; n++) {
                    int c0 = n * 8 + mycol0;
                    if (c0 > rloc)     s[n][0] = -CUDART_INF_F;
                    if (c0 + 1 > rloc) s[n][1] = -CUDART_INF_F;
                    if (c0 > rloc + 8)     s[n][2] = -CUDART_INF_F;
                    if (c0 + 1 > rloc + 8) s[n][3] = -CUDART_INF_F;
                }
            }

            // ---- online softmax ----
            float mt_lo = -CUDART_INF_F, mt_hi = -CUDART_INF_F;
#pragma unroll
            for (int n = 0; n < 8; n++) {
                mt_lo = fmaxf(mt_lo, fmaxf(s[n][0], s[n][1]));
                mt_hi = fmaxf(mt_hi, fmaxf(s[n][2], s[n][3]));
            }
            mt_lo = fmaxf(mt_lo, __shfl_xor_sync(0xffffffffu, mt_lo, 1));
            mt_lo = fmaxf(mt_lo, __shfl_xor_sync(0xffffffffu, mt_lo, 2));
            mt_hi = fmaxf(mt_hi, __shfl_xor_sync(0xffffffffu, mt_hi, 1));
            mt_hi = fmaxf(mt_hi, __shfl_xor_sync(0xffffffffu, mt_hi, 2));

            float mn_lo = fmaxf(m_lo, mt_lo), mn_hi = fmaxf(m_hi, mt_hi);
            float a_lo = exp2f(m_lo - mn_lo), a_hi = exp2f(m_hi - mn_hi);
            m_lo = mn_lo; m_hi = mn_hi;

            float rs_lo = 0.f, rs_hi = 0.f;
#pragma unroll
            for (int n = 0; n < 8; n++) {
                s[n][0] = exp2f(s[n][0] - mn_lo);
                s[n][1] = exp2f(s[n][1] - mn_lo);
                s[n][2] = exp2f(s[n][2] - mn_hi);
                s[n][3] = exp2f(s[n][3] - mn_hi);
                rs_lo += s[n][0] + s[n][1];
                rs_hi += s[n][2] + s[n][3];
            }
            rs_lo += __shfl_xor_sync(0xffffffffu, rs_lo, 1);
            rs_lo += __shfl_xor_sync(0xffffffffu, rs_lo, 2);
            rs_hi += __shfl_xor_sync(0xffffffffu, rs_hi, 1);
            rs_hi += __shfl_xor_sync(0xffffffffu, rs_hi, 2);
            l_lo = a_lo * l_lo + rs_lo;
            l_hi = a_hi * l_hi + rs_hi;
#pragma unroll
            for (int n = 0; n < 8; n++) {
                o[n][0] *= a_lo; o[n][1] *= a_lo;
                o[n][2] *= a_hi; o[n][3] *= a_hi;
            }

            // ---- O += Ph * (Vh + Vl) ----
            uint32_t vbase = st + 2 * FMATB;
#pragma unroll
            for (int ks = 0; ks < 4; ks++) {
                uint32_t ph[4];
                ph[0] = pack2h(s[2 * ks][0],     s[2 * ks][1]);
                ph[1] = pack2h(s[2 * ks][2],     s[2 * ks][3]);
                ph[2] = pack2h(s[2 * ks + 1][0], s[2 * ks + 1][1]);
                ph[3] = pack2h(s[2 * ks + 1][2], s[2 * ks + 1][3]);
                int rv = ks * 16 + vrowf;
                int vx = rv & 7;
#pragma unroll
                for (int pp = 0; pp < 2; pp++) {
                    int p0 = pp * 2;
                    uint32_t va0 = vbase + rv * 128 + (((p0 * 2 + vsel) ^ vx) << 4);
                    uint32_t va1 = vbase + rv * 128 + ((((p0 + 1) * 2 + vsel) ^ vx) << 4);
                    uint32_t vh0[4], vl0[4], vh1[4], vl1[4];
                    ldsm4t(vh0, va0);
                    ldsm4t(vl0, va0 + FMATB);
                    ldsm4t(vh1, va1);
                    ldsm4t(vl1, va1 + FMATB);
                    mma16816h(o[2 * p0],     ph, &vh0[0]);
                    mma16816h(o[2 * p0 + 1], ph, &vh0[2]);
                    mma16816h(o[2 * p0 + 2], ph, &vh1[0]);
                    mma16816h(o[2 * p0 + 3], ph, &vh1[2]);
                    mma16816h(o[2 * p0],     ph, &vl0[0]);
                    mma16816h(o[2 * p0 + 1], ph, &vl0[2]);
                    mma16816h(o[2 * p0 + 2], ph, &vl1[0]);
                    mma16816h(o[2 * p0 + 3], ph, &vl1[2]);
                }
            }
        }
        __syncthreads();
    }

    // ---- epilogue: normalize, cast to fp16 ----
    float inv_lo = 1.f / l_lo, inv_hi = 1.f / l_hi;
    int tok_lo = tok0 + qbase + wid * 16 + rlo;
    int tok_hi = tok_lo + 8;
#pragma unroll
    for (int n = 0; n < 8; n++) {
        int c = hh * 64 + n * 8 + mycol0;
        *(uint32_t*)(attf + (size_t)tok_lo * N_EMBD + c) =
            pack2h(o[n][0] * inv_lo, o[n][1] * inv_lo);
        *(uint32_t*)(attf + (size_t)tok_hi * N_EMBD + c) =
            pack2h(o[n][2] * inv_hi, o[n][3] * inv_hi);
    }
}

// ---------------------------------------------------------------------------
extern "C" void kernel_launch(void* const* d_in, const int* in_sizes, int n_in,
                              void* d_out, int out_size)
{
    const float* x      = (const float*)d_in[0];
    const float* W_attn = (const float*)d_in[1];
    const float* b_attn = (const float*)d_in[2];
    const float* W_proj = (const float*)d_in[3];
    const float* b_proj = (const float*)d_in[4];
    float* out = (float*)d_out;

    __half *xf, *attf, *qkvh, *qkvl, *wahi, *walo, *wphi, *wplo;
    cudaGetSymbolAddress((void**)&xf, g_xf);
    cudaGetSymbolAddress((void**)&attf, g_attf);
    cudaGetSymbolAddress((void**)&qkvh, g_qkvh);
    cudaGetSymbolAddress((void**)&qkvl, g_qkvl);
    cudaGetSymbolAddress((void**)&wahi, g_wahi);
    cudaGetSymbolAddress((void**)&walo, g_walo);
    cudaGetSymbolAddress((void**)&wphi, g_wphi);
    cudaGetSymbolAddress((void**)&wplo, g_wplo);

    cudaFuncSetAttribute(gemm_mma<true>,
                         cudaFuncAttributeMaxDynamicSharedMemorySize, GSMEM);
    cudaFuncSetAttribute(gemm_mma<false>,
                         cudaFuncAttributeMaxDynamicSharedMemorySize, GSMEM);
    cudaFuncSetAttribute(flash_mma,
                         cudaFuncAttributeMaxDynamicSharedMemorySize, FSMEM);

    // operand preparation
    cvt_f16<<<(M_ROWS * N_EMBD / 4 + 255) / 256, 256>>>(x, xf, M_ROWS * N_EMBD / 4);
    cvt_t_hilo16<<<dim3(E3 / 32, N_EMBD / 32), dim3(32, 8)>>>(W_attn, wahi, walo, N_EMBD, E3);
    cvt_t_hilo16<<<dim3(N_EMBD / 32, N_EMBD / 32), dim3(32, 8)>>>(W_proj, wphi, wplo, N_EMBD, N_EMBD);

    // 1) QKV projection -> Q single fp16, K/V fp16 hi/lo
    gemm_mma<true><<<dim3(E3 / 128, M_ROWS / 128), 128, GSMEM>>>(
        xf, wahi, walo, b_attn, nullptr, qkvh, qkvl, M_ROWS, E3, N_EMBD);

    // 2) fp16 2-term causal flash attention -> fp16
    flash_mma<<<dim3(2 * N_HEADS, S_LEN / 128), 256, FSMEM>>>(qkvh, qkvl, attf);

    // 3) output projection -> fp32
    gemm_mma<false><<<dim3(N_EMBD / 128, M_ROWS / 128), 128, GSMEM>>>(
        attf, wphi, wplo, b_proj, out, nullptr, nullptr, M_ROWS, N_EMBD, N_EMBD);
}

// round 12
// speedup vs baseline: 6.7086x; 1.3121x over previous
#include <cuda_runtime.h>
#include <cuda_bf16.h>
#include <cuda_fp16.h>
#include <math_constants.h>
#include <cstdint>

// ---------------------------------------------------------------------------
// MultiHeadAttention, B=2,S=2048,H=16,D=64,E=1024. All-fp16 HMMA pipeline.
//   1) qkv = x_f16 @ Wattn_f16 + b : single-pass fp16 GEMM (BK=64);
//      epilogue: Q -> single fp16, K/V -> fp16 hi/lo (exact residual)
//   2) att(fp16) = flash(qkv):  S = Qh*(Kh+Kl),  O = Ph*(Vh+Vl)
//   3) out(fp32) = att_f16 @ Wproj_f16 + b : single-pass fp16 GEMM
// Error model (validated r10/r11): each one-sided fp16 rounding adds
// ~1.4e-4 rms; predicted total ~4.2e-4 vs 1e-3 threshold.
// ---------------------------------------------------------------------------

#define S_LEN   2048
#define N_EMBD  1024
#define E3      3072
#define N_HEADS 16
#define M_ROWS  4096

__device__ __half g_xf[(size_t)M_ROWS * N_EMBD];
__device__ __half g_attf[(size_t)M_ROWS * N_EMBD];
__device__ __half g_qkvh[(size_t)M_ROWS * E3];   // Q single | K hi | V hi
__device__ __half g_qkvl[(size_t)M_ROWS * E3];   // (unused) | K lo | V lo
__device__ __half g_wa[(size_t)E3 * N_EMBD];     // W_attn^T fp16
__device__ __half g_wp[(size_t)N_EMBD * N_EMBD]; // W_proj^T fp16

// ------------------------- helpers ------------------------------------------
__device__ __forceinline__ uint32_t smem_u32(const void* p) {
    uint32_t a;
    asm("{ .reg .u64 t; cvta.to.shared.u64 t, %1; cvt.u32.u64 %0, t; }"
        : "=r"(a) : "l"(p));
    return a;
}
__device__ __forceinline__ void cp16(uint32_t dst, const void* src) {
    asm volatile("cp.async.cg.shared.global [%0], [%1], 16;" :: "r"(dst), "l"(src));
}
#define CP_COMMIT() asm volatile("cp.async.commit_group;" ::: "memory")
#define CP_WAIT1()  asm volatile("cp.async.wait_group 1;"  ::: "memory")

__device__ __forceinline__ void ldsm4(uint32_t* r, uint32_t addr) {
    asm volatile("ldmatrix.sync.aligned.m8n8.x4.shared.b16 {%0,%1,%2,%3}, [%4];"
                 : "=r"(r[0]), "=r"(r[1]), "=r"(r[2]), "=r"(r[3]) : "r"(addr));
}
__device__ __forceinline__ void ldsm4t(uint32_t* r, uint32_t addr) {
    asm volatile("ldmatrix.sync.aligned.m8n8.x4.trans.shared.b16 {%0,%1,%2,%3}, [%4];"
                 : "=r"(r[0]), "=r"(r[1]), "=r"(r[2]), "=r"(r[3]) : "r"(addr));
}
__device__ __forceinline__ void mma16816h(float* d, const uint32_t* a, const uint32_t* b) {
    asm volatile(
        "mma.sync.aligned.m16n8k16.row.col.f32.f16.f16.f32 "
        "{%0,%1,%2,%3}, {%4,%5,%6,%7}, {%8,%9}, {%0,%1,%2,%3};"
        : "+f"(d[0]), "+f"(d[1]), "+f"(d[2]), "+f"(d[3])
        : "r"(a[0]), "r"(a[1]), "r"(a[2]), "r"(a[3]), "r"(b[0]), "r"(b[1]));
}
__device__ __forceinline__ uint32_t pack2h(float a, float b) {
    uint32_t r;
    asm("cvt.rn.f16x2.f32 %0, %1, %2;" : "=r"(r) : "f"(b), "f"(a));
    return r;
}
__device__ __forceinline__ void split2h(float a, float b, uint32_t& hi, uint32_t& lo) {
    __half ha = __float2half_rn(a), hb = __float2half_rn(b);
    hi = (uint32_t)__half_as_ushort(ha) | ((uint32_t)__half_as_ushort(hb) << 16);
    lo = pack2h(a - __half2float(ha), b - __half2float(hb));
}

// ---------------------------------------------------------------------------
__global__ void cvt_f16(const float* __restrict__ in, __half* __restrict__ out, int n4)
{
    int i = blockIdx.x * blockDim.x + threadIdx.x;
    if (i >= n4) return;
    float4 v = ((const float4*)in)[i];
    uint2 o = { pack2h(v.x, v.y), pack2h(v.z, v.w) };
    ((uint2*)out)[i] = o;
}

// transpose W[K][N] -> T[N][K], fp16 single
__global__ void cvt_t_16(const float* __restrict__ W, __half* __restrict__ T, int K, int N)
{
    __shared__ float tile[32][33];
    int k0 = blockIdx.y * 32, n0 = blockIdx.x * 32;
    int tx = threadIdx.x, ty = threadIdx.y;
#pragma unroll
    for (int i = ty; i < 32; i += 8)
        tile[i][tx] = W[(size_t)(k0 + i) * N + n0 + tx];
    __syncthreads();
#pragma unroll
    for (int i = ty; i < 32; i += 8)
        T[(size_t)(n0 + i) * K + k0 + tx] = __float2half_rn(tile[tx][i]);
}

// ---------------------------------------------------------------------------
// fp16 single-pass GEMM: C[M,N] = A[M,K] @ B[N,K]^T + bias.
// 128x128 CTA, BK=64 (128B rows, 8-chunk XOR swizzle), 4 warps (64x64),
// 3 stages x 32KB, 1 barrier/ktile (16 iters), 2 CTAs/SM, 128 threads.
// HILO=true: fp16 out — Q block (n0<1024) single, K/V blocks hi/lo.
// ---------------------------------------------------------------------------
#define GMATB  16384             // 128 rows * 128B
#define STAGEB (2 * GMATB)       // 32768 (A | B)
#define GSMEM  (3 * STAGEB)      // 98304

template <bool HILO>
__global__ __launch_bounds__(128, 2)
void gemm_mma(const __half* __restrict__ A, const __half* __restrict__ B,
              const float* __restrict__ bias, float* __restrict__ Cf,
              __half* __restrict__ Ch, __half* __restrict__ Cl,
              int M, int N, int K)
{
    extern __shared__ char smem[];
    uint32_t sb = smem_u32(smem);
    int t = threadIdx.x, wid = t >> 5, lid = t & 31;
    int m0 = blockIdx.y * 128, n0 = blockIdx.x * 128;
    int wm = wid & 1, wn = wid >> 1;   // 2x2 warp grid, 64x64 tiles

    const __half* gp[2] = { A + (size_t)m0 * K, B + (size_t)n0 * K };

    // loader lanes: chunk lc (16B of 8) in 128B row, rows lr + 16*r8
    const int lc = t & 7;
    const int lr = t >> 3;                  // 0..15
    const uint32_t wbase = (uint32_t)((lc ^ (lr & 7)) << 4) + lr * 128;

    float acc[4][8][4];
#pragma unroll
    for (int i = 0; i < 4; i++)
#pragma unroll
        for (int j = 0; j < 8; j++)
#pragma unroll
            for (int v = 0; v < 4; v++) acc[i][j][v] = 0.f;

    int nkt = K / 64;   // 16

    // prologue: stages 0,1
#pragma unroll
    for (int s = 0; s < 2; s++) {
        uint32_t st = sb + s * STAGEB;
        int koff = s * 64;
#pragma unroll
        for (int mat = 0; mat < 2; mat++)
#pragma unroll
            for (int r8 = 0; r8 < 8; r8++)
                cp16(st + mat * GMATB + wbase + r8 * 16 * 128,
                     gp[mat] + (size_t)(lr + r8 * 16) * K + koff + lc * 8);
        CP_COMMIT();
    }

    // fragment lane constants (3-bit xor: chunk ^ (row & 7))
    const int arow = lid & 15, asel = lid >> 4;
    const int axor = arow & 7;
    const int browl = ((lid >> 4) & 1) * 8 + (lid & 7);
    const int bsel = (lid >> 3) & 1;
    const int bxor = browl & 7;

    int rd = 0, wr = 2;
    for (int kt = 0; kt < nkt; kt++) {
        CP_WAIT1();
        __syncthreads();

        uint32_t st = sb + rd * STAGEB;
        uint32_t aRow = st + (uint32_t)(wm * 64) * 128;
        uint32_t bRow = st + GMATB + (uint32_t)(wn * 64) * 128;

#pragma unroll
        for (int kb = 0; kb < 4; kb++) {
            uint32_t ah[4][4];
#pragma unroll
            for (int mt = 0; mt < 4; mt++)
                ldsm4(ah[mt], aRow + (uint32_t)(mt * 16 + arow) * 128
                              + (uint32_t)(((kb * 2 + asel) ^ axor) << 4));
#pragma unroll
            for (int p = 0; p < 4; p++) {
                uint32_t bh[4];
                ldsm4(bh, bRow + (uint32_t)(p * 16 + browl) * 128
                          + (uint32_t)(((kb * 2 + bsel) ^ bxor) << 4));
#pragma unroll
                for (int mt = 0; mt < 4; mt++) {
                    mma16816h(acc[mt][2 * p],     ah[mt], &bh[0]);
                    mma16816h(acc[mt][2 * p + 1], ah[mt], &bh[2]);
                }
            }
        }

        // issue loads for ktile kt+2 (stage wr == (kt-1)%3, drained by this
        // iteration's barrier)
        if (kt + 2 < nkt) {
            uint32_t st2 = sb + wr * STAGEB;
            int koff = (kt + 2) * 64;
#pragma unroll
            for (int mat = 0; mat < 2; mat++)
#pragma unroll
                for (int r8 = 0; r8 < 8; r8++)
                    cp16(st2 + mat * GMATB + wbase + r8 * 16 * 128,
                         gp[mat] + (size_t)(lr + r8 * 16) * K + koff + lc * 8);
        }
        CP_COMMIT();
        rd = (rd == 2) ? 0 : rd + 1;
        wr = (wr == 2) ? 0 : wr + 1;
    }

    int rA = m0 + wm * 64 + (lid >> 2);
    int cA = n0 + wn * 64 + 2 * (lid & 3);
    const bool qreg = HILO && (n0 < 1024);   // Q block: single fp16
#pragma unroll
    for (int mt = 0; mt < 4; mt++) {
        int r = rA + mt * 16;
#pragma unroll
        for (int nt = 0; nt < 8; nt++) {
            int c = cA + nt * 8;
            float b0 = bias[c], b1 = bias[c + 1];
            float v00 = acc[mt][nt][0] + b0, v01 = acc[mt][nt][1] + b1;
            float v10 = acc[mt][nt][2] + b0, v11 = acc[mt][nt][3] + b1;
            if (HILO) {
                uint32_t h, l;
                split2h(v00, v01, h, l);
                *(uint32_t*)(Ch + (size_t)r * N + c) = h;
                if (!qreg) *(uint32_t*)(Cl + (size_t)r * N + c) = l;
                split2h(v10, v11, h, l);
                *(uint32_t*)(Ch + (size_t)(r + 8) * N + c) = h;
                if (!qreg) *(uint32_t*)(Cl + (size_t)(r + 8) * N + c) = l;
            } else {
                float2 w0 = {v00, v01}, w1 = {v10, v11};
                *(float2*)(Cf + (size_t)r * N + c)       = w0;
                *(float2*)(Cf + (size_t)(r + 8) * N + c) = w1;
            }
        }
    }
}

// ---------------------------------------------------------------------------
// fp16 2-term causal flash attention (unchanged from round 11).
// S = Qh*(Kh+Kl), O = Ph*(Vh+Vl). 128 q-rows, 8 warps, 2 CTAs/SM.
// ---------------------------------------------------------------------------
#define QMATB   16384
#define FMATB   8192
#define FSTAGE  (4 * FMATB)      // 32768 (Kh,Kl,Vh,Vl)
#define FSMEM   (QMATB + 2 * FSTAGE)  // 81920
#define SCALE_L2E 0.18033688011112042f

__global__ __launch_bounds__(256, 2)
void flash_mma(const __half* __restrict__ qkvh,
               const __half* __restrict__ qkvl,
               __half* __restrict__ attf)
{
    extern __shared__ char smem[];
    uint32_t sb = smem_u32(smem);
    int t = threadIdx.x, wid = t >> 5, lid = t & 31;
    int bh = blockIdx.x;
    int b = bh >> 4, hh = bh & 15;
    int qt = (int)gridDim.y - 1 - blockIdx.y;
    int qbase = qt * 128;
    int tok0 = b * S_LEN;

    const uint32_t QH = sb;
    const uint32_t KV0 = sb + QMATB;

    const int qlrow  = t >> 1;
    const int qlcol0 = (t & 1) * 4;
    const int klrow  = t >> 2;
    const int klcol0 = (t & 3) * 2;
    const int klx = klrow & 7;

    {
        size_t rq = (size_t)(tok0 + qbase + qlrow) * E3 + hh * 64;
        int qx = qlrow & 7;
#pragma unroll
        for (int u = 0; u < 4; u++) {
            int ch = qlcol0 + u;
            cp16(QH + qlrow * 128 + ((ch ^ qx) << 4), qkvh + rq + ch * 8);
        }
        size_t rk = (size_t)(tok0 + klrow) * E3 + 1024 + hh * 64;
#pragma unroll
        for (int u = 0; u < 2; u++) {
            int ch = klcol0 + u;
            uint32_t d = klrow * 128 + ((ch ^ klx) << 4);
            cp16(KV0 + d,             qkvh + rk + ch * 8);
            cp16(KV0 + FMATB + d,     qkvl + rk + ch * 8);
            cp16(KV0 + 2 * FMATB + d, qkvh + rk + 1024 + ch * 8);
            cp16(KV0 + 3 * FMATB + d, qkvl + rk + 1024 + ch * 8);
        }
    }
    CP_COMMIT();

    const int arow = lid & 15, asel = lid >> 4;
    const int qrow = wid * 16 + arow;
    const int qx = qrow & 7;
    const int browf = ((lid >> 4) & 1) * 8 + (lid & 7);
    const int bsel = (lid >> 3) & 1;
    const int vrowf = ((lid >> 3) & 1) * 8 + (lid & 7);
    const int vsel = (lid >> 4) & 1;

    uint32_t qh[4][4];
    float o[8][4];
#pragma unroll
    for (int n = 0; n < 8; n++)
#pragma unroll
        for (int v = 0; v < 4; v++) o[n][v] = 0.f;
    float m_lo = -CUDART_INF_F, m_hi = -CUDART_INF_F, l_lo = 0.f, l_hi = 0.f;

    const int rlo = lid >> 2;
    const int rloc = 16 * (wid & 3) + rlo;
    const int mycol0 = 2 * (lid & 3);
    const int kt_d = 2 * qt + (wid >> 2);
    const int ntiles = 2 * qt + 2;

    for (int kt = 0; kt < ntiles; kt++) {
        if (kt + 1 < ntiles) {
            uint32_t st = KV0 + ((kt + 1) & 1) * FSTAGE;
            size_t rk = (size_t)(tok0 + (kt + 1) * 64 + klrow) * E3 + 1024 + hh * 64;
#pragma unroll
            for (int u = 0; u < 2; u++) {
                int ch = klcol0 + u;
                uint32_t d = klrow * 128 + ((ch ^ klx) << 4);
                cp16(st + d,             qkvh + rk + ch * 8);
                cp16(st + FMATB + d,     qkvl + rk + ch * 8);
                cp16(st + 2 * FMATB + d, qkvh + rk + 1024 + ch * 8);
                cp16(st + 3 * FMATB + d, qkvl + rk + 1024 + ch * 8);
            }
        }
        CP_COMMIT();
        CP_WAIT1();
        __syncthreads();

        if (kt == 0) {
#pragma unroll
            for (int ks = 0; ks < 4; ks++)
                ldsm4(qh[ks], QH + qrow * 128 + (((ks * 2 + asel) ^ qx) << 4));
        }

        if (kt <= kt_d) {
            uint32_t st = KV0 + (kt & 1) * FSTAGE;

            float s[8][4];
#pragma unroll
            for (int n = 0; n < 8; n++)
#pragma unroll
                for (int v = 0; v < 4; v++) s[n][v] = 0.f;

#pragma unroll
            for (int ks = 0; ks < 4; ks++) {
#pragma unroll
                for (int pp = 0; pp < 2; pp++) {
                    int p0 = pp * 2;
                    int rk0 = p0 * 16 + browf, rk1 = rk0 + 16;
                    uint32_t ka0 = st + rk0 * 128 + (((ks * 2 + bsel) ^ (rk0 & 7)) << 4);
                    uint32_t ka1 = st + rk1 * 128 + (((ks * 2 + bsel) ^ (rk1 & 7)) << 4);
                    uint32_t kh0[4], kl0[4], kh1[4], kl1[4];
                    ldsm4(kh0, ka0);
                    ldsm4(kl0, ka0 + FMATB);
                    ldsm4(kh1, ka1);
                    ldsm4(kl1, ka1 + FMATB);
                    mma16816h(s[2 * p0],     qh[ks], &kh0[0]);
                    mma16816h(s[2 * p0 + 1], qh[ks], &kh0[2]);
                    mma16816h(s[2 * p0 + 2], qh[ks], &kh1[0]);
                    mma16816h(s[2 * p0 + 3], qh[ks], &kh1[2]);
                    mma16816h(s[2 * p0],     qh[ks], &kl0[0]);
                    mma16816h(s[2 * p0 + 1], qh[ks], &kl0[2]);
                    mma16816h(s[2 * p0 + 2], qh[ks], &kl1[0]);
                    mma16816h(s[2 * p0 + 3], qh[ks], &kl1[2]);
                }
            }

#pragma unroll
            for (int n = 0; n < 8; n++)
#pragma unroll
                for (int v = 0; v < 4; v++) s[n][v] *= SCALE_L2E;

            if (kt == kt_d) {
#pragma unroll
                for (int n = 0; n < 8; n++) {
                    int c0 = n * 8 + mycol0;
                    if (c0 > rloc)     s[n][0] = -CUDART_INF_F;
                    if (c0 + 1 > rloc) s[n][1] = -CUDART_INF_F;
                    if (c0 > rloc + 8)     s[n][2] = -CUDART_INF_F;
                    if (c0 + 1 > rloc + 8) s[n][3] = -CUDART_INF_F;
                }
            }

            float mt_lo = -CUDART_INF_F, mt_hi = -CUDART_INF_F;
#pragma unroll
            for (int n = 0; n < 8; n++) {
                mt_lo = fmaxf(mt_lo, fmaxf(s[n][0], s[n][1]));
                mt_hi = fmaxf(mt_hi, fmaxf(s[n][2], s[n][3]));
            }
            mt_lo = fmaxf(mt_lo, __shfl_xor_sync(0xffffffffu, mt_lo, 1));
            mt_lo = fmaxf(mt_lo, __shfl_xor_sync(0xffffffffu, mt_lo, 2));
            mt_hi = fmaxf(mt_hi, __shfl_xor_sync(0xffffffffu, mt_hi, 1));
            mt_hi = fmaxf(mt_hi, __shfl_xor_sync(0xffffffffu, mt_hi, 2));

            float mn_lo = fmaxf(m_lo, mt_lo), mn_hi = fmaxf(m_hi, mt_hi);
            float a_lo = exp2f(m_lo - mn_lo), a_hi = exp2f(m_hi - mn_hi);
            m_lo = mn_lo; m_hi = mn_hi;

            float rs_lo = 0.f, rs_hi = 0.f;
#pragma unroll
            for (int n = 0; n < 8; n++) {
                s[n][0] = exp2f(s[n][0] - mn_lo);
                s[n][1] = exp2f(s[n][1] - mn_lo);
                s[n][2] = exp2f(s[n][2] - mn_hi);
                s[n][3] = exp2f(s[n][3] - mn_hi);
                rs_lo += s[n][0] + s[n][1];
                rs_hi += s[n][2] + s[n][3];
            }
            rs_lo += __shfl_xor_sync(0xffffffffu, rs_lo, 1);
            rs_lo += __shfl_xor_sync(0xffffffffu, rs_lo, 2);
            rs_hi += __shfl_xor_sync(0xffffffffu, rs_hi, 1);
            rs_hi += __shfl_xor_sync(0xffffffffu, rs_hi, 2);
            l_lo = a_lo * l_lo + rs_lo;
            l_hi = a_hi * l_hi + rs_hi;
#pragma unroll
            for (int n = 0; n < 8; n++) {
                o[n][0] *= a_lo; o[n][1] *= a_lo;
                o[n][2] *= a_hi; o[n][3] *= a_hi;
            }

            uint32_t vbase = st + 2 * FMATB;
#pragma unroll
            for (int ks = 0; ks < 4; ks++) {
                uint32_t ph[4];
                ph[0] = pack2h(s[2 * ks][0],     s[2 * ks][1]);
                ph[1] = pack2h(s[2 * ks][2],     s[2 * ks][3]);
                ph[2] = pack2h(s[2 * ks + 1][0], s[2 * ks + 1][1]);
                ph[3] = pack2h(s[2 * ks + 1][2], s[2 * ks + 1][3]);
                int rv = ks * 16 + vrowf;
                int vx = rv & 7;
#pragma unroll
                for (int pp = 0; pp < 2; pp++) {
                    int p0 = pp * 2;
                    uint32_t va0 = vbase + rv * 128 + (((p0 * 2 + vsel) ^ vx) << 4);
                    uint32_t va1 = vbase + rv * 128 + ((((p0 + 1) * 2 + vsel) ^ vx) << 4);
                    uint32_t vh0[4], vl0[4], vh1[4], vl1[4];
                    ldsm4t(vh0, va0);
                    ldsm4t(vl0, va0 + FMATB);
                    ldsm4t(vh1, va1);
                    ldsm4t(vl1, va1 + FMATB);
                    mma16816h(o[2 * p0],     ph, &vh0[0]);
                    mma16816h(o[2 * p0 + 1], ph, &vh0[2]);
                    mma16816h(o[2 * p0 + 2], ph, &vh1[0]);
                    mma16816h(o[2 * p0 + 3], ph, &vh1[2]);
                    mma16816h(o[2 * p0],     ph, &vl0[0]);
                    mma16816h(o[2 * p0 + 1], ph, &vl0[2]);
                    mma16816h(o[2 * p0 + 2], ph, &vl1[0]);
                    mma16816h(o[2 * p0 + 3], ph, &vl1[2]);
                }
            }
        }
        __syncthreads();
    }

    float inv_lo = 1.f / l_lo, inv_hi = 1.f / l_hi;
    int tok_lo = tok0 + qbase + wid * 16 + rlo;
    int tok_hi = tok_lo + 8;
#pragma unroll
    for (int n = 0; n < 8; n++) {
        int c = hh * 64 + n * 8 + mycol0;
        *(uint32_t*)(attf + (size_t)tok_lo * N_EMBD + c) =
            pack2h(o[n][0] * inv_lo, o[n][1] * inv_lo);
        *(uint32_t*)(attf + (size_t)tok_hi * N_EMBD + c) =
            pack2h(o[n][2] * inv_hi, o[n][3] * inv_hi);
    }
}

// ---------------------------------------------------------------------------
extern "C" void kernel_launch(void* const* d_in, const int* in_sizes, int n_in,
                              void* d_out, int out_size)
{
    const float* x      = (const float*)d_in[0];
    const float* W_attn = (const float*)d_in[1];
    const float* b_attn = (const float*)d_in[2];
    const float* W_proj = (const float*)d_in[3];
    const float* b_proj = (const float*)d_in[4];
    float* out = (float*)d_out;

    __half *xf, *attf, *qkvh, *qkvl, *wa, *wp;
    cudaGetSymbolAddress((void**)&xf, g_xf);
    cudaGetSymbolAddress((void**)&attf, g_attf);
    cudaGetSymbolAddress((void**)&qkvh, g_qkvh);
    cudaGetSymbolAddress((void**)&qkvl, g_qkvl);
    cudaGetSymbolAddress((void**)&wa, g_wa);
    cudaGetSymbolAddress((void**)&wp, g_wp);

    cudaFuncSetAttribute(gemm_mma<true>,
                         cudaFuncAttributeMaxDynamicSharedMemorySize, GSMEM);
    cudaFuncSetAttribute(gemm_mma<false>,
                         cudaFuncAttributeMaxDynamicSharedMemorySize, GSMEM);
    cudaFuncSetAttribute(flash_mma,
                         cudaFuncAttributeMaxDynamicSharedMemorySize, FSMEM);

    // operand preparation
    cvt_f16<<<(M_ROWS * N_EMBD / 4 + 255) / 256, 256>>>(x, xf, M_ROWS * N_EMBD / 4);
    cvt_t_16<<<dim3(E3 / 32, N_EMBD / 32), dim3(32, 8)>>>(W_attn, wa, N_EMBD, E3);
    cvt_t_16<<<dim3(N_EMBD / 32, N_EMBD / 32), dim3(32, 8)>>>(W_proj, wp, N_EMBD, N_EMBD);

    // 1) QKV projection (single-pass fp16) -> Q single, K/V hi/lo
    gemm_mma<true><<<dim3(E3 / 128, M_ROWS / 128), 128, GSMEM>>>(
        xf, wa, b_attn, nullptr, qkvh, qkvl, M_ROWS, E3, N_EMBD);

    // 2) fp16 2-term causal flash attention -> fp16
    flash_mma<<<dim3(2 * N_HEADS, S_LEN / 128), 256, FSMEM>>>(qkvh, qkvl, attf);

    // 3) output projection (single-pass fp16) -> fp32
    gemm_mma<false><<<dim3(N_EMBD / 128, M_ROWS / 128), 128, GSMEM>>>(
        attf, wp, b_proj, out, nullptr, nullptr, M_ROWS, N_EMBD, N_EMBD);
}

// round 13
// speedup vs baseline: 8.4814x; 1.2643x over previous
#include <cuda_runtime.h>
#include <cuda_bf16.h>
#include <cuda_fp16.h>
#include <math_constants.h>
#include <cstdint>

// ---------------------------------------------------------------------------
// MultiHeadAttention, B=2,S=2048,H=16,D=64,E=1024. All-fp16 HMMA pipeline,
// single-pass everywhere (validated error model: each one-sided fp16
// rounding ~1.4-3e-4 rms; predicted total ~6e-4 vs 1e-3 threshold).
//   1) qkv(fp16) = x_f16 @ Wattn_f16 + b      [single-pass GEMM, BK=64]
//   2) att(fp16) = flash(qkv)                  [S=Qh*Kh, O=Ph*Vh]
//   3) out(fp32) = att @ Wproj_f16 + b         [single-pass GEMM]
// ---------------------------------------------------------------------------

#define S_LEN   2048
#define N_EMBD  1024
#define E3      3072
#define N_HEADS 16
#define M_ROWS  4096

__device__ __half g_xf[(size_t)M_ROWS * N_EMBD];
__device__ __half g_attf[(size_t)M_ROWS * N_EMBD];
__device__ __half g_qkv[(size_t)M_ROWS * E3];
__device__ __half g_wa[(size_t)E3 * N_EMBD];     // W_attn^T fp16
__device__ __half g_wp[(size_t)N_EMBD * N_EMBD]; // W_proj^T fp16

// ------------------------- helpers ------------------------------------------
__device__ __forceinline__ uint32_t smem_u32(const void* p) {
    uint32_t a;
    asm("{ .reg .u64 t; cvta.to.shared.u64 t, %1; cvt.u32.u64 %0, t; }"
        : "=r"(a) : "l"(p));
    return a;
}
__device__ __forceinline__ void cp16(uint32_t dst, const void* src) {
    asm volatile("cp.async.cg.shared.global [%0], [%1], 16;" :: "r"(dst), "l"(src));
}
#define CP_COMMIT() asm volatile("cp.async.commit_group;" ::: "memory")
#define CP_WAIT1()  asm volatile("cp.async.wait_group 1;"  ::: "memory")

__device__ __forceinline__ void ldsm4(uint32_t* r, uint32_t addr) {
    asm volatile("ldmatrix.sync.aligned.m8n8.x4.shared.b16 {%0,%1,%2,%3}, [%4];"
                 : "=r"(r[0]), "=r"(r[1]), "=r"(r[2]), "=r"(r[3]) : "r"(addr));
}
__device__ __forceinline__ void ldsm4t(uint32_t* r, uint32_t addr) {
    asm volatile("ldmatrix.sync.aligned.m8n8.x4.trans.shared.b16 {%0,%1,%2,%3}, [%4];"
                 : "=r"(r[0]), "=r"(r[1]), "=r"(r[2]), "=r"(r[3]) : "r"(addr));
}
__device__ __forceinline__ void mma16816h(float* d, const uint32_t* a, const uint32_t* b) {
    asm volatile(
        "mma.sync.aligned.m16n8k16.row.col.f32.f16.f16.f32 "
        "{%0,%1,%2,%3}, {%4,%5,%6,%7}, {%8,%9}, {%0,%1,%2,%3};"
        : "+f"(d[0]), "+f"(d[1]), "+f"(d[2]), "+f"(d[3])
        : "r"(a[0]), "r"(a[1]), "r"(a[2]), "r"(a[3]), "r"(b[0]), "r"(b[1]));
}
__device__ __forceinline__ uint32_t pack2h(float a, float b) {
    uint32_t r;
    asm("cvt.rn.f16x2.f32 %0, %1, %2;" : "=r"(r) : "f"(b), "f"(a));
    return r;
}

// ---------------------------------------------------------------------------
__global__ void cvt_f16(const float* __restrict__ in, __half* __restrict__ out, int n4)
{
    int i = blockIdx.x * blockDim.x + threadIdx.x;
    if (i >= n4) return;
    float4 v = ((const float4*)in)[i];
    uint2 o = { pack2h(v.x, v.y), pack2h(v.z, v.w) };
    ((uint2*)out)[i] = o;
}

// transpose W[K][N] -> T[N][K], fp16
__global__ void cvt_t_16(const float* __restrict__ W, __half* __restrict__ T, int K, int N)
{
    __shared__ float tile[32][33];
    int k0 = blockIdx.y * 32, n0 = blockIdx.x * 32;
    int tx = threadIdx.x, ty = threadIdx.y;
#pragma unroll
    for (int i = ty; i < 32; i += 8)
        tile[i][tx] = W[(size_t)(k0 + i) * N + n0 + tx];
    __syncthreads();
#pragma unroll
    for (int i = ty; i < 32; i += 8)
        T[(size_t)(n0 + i) * K + k0 + tx] = __float2half_rn(tile[tx][i]);
}

// ---------------------------------------------------------------------------
// fp16 single-pass GEMM: C[M,N] = A[M,K] @ B[N,K]^T + bias.
// 128x128 CTA, BK=64 (128B rows, 8-chunk XOR swizzle), 4 warps (64x64),
// 3 stages x 32KB, 1 barrier/ktile, 2 CTAs/SM, 128 threads.
// F16OUT=true: fp16 output (no bias-free case here; bias always added).
// ---------------------------------------------------------------------------
#define GMATB  16384             // 128 rows * 128B
#define STAGEB (2 * GMATB)       // 32768 (A | B)
#define GSMEM  (3 * STAGEB)      // 98304

template <bool F16OUT>
__global__ __launch_bounds__(128, 2)
void gemm_mma(const __half* __restrict__ A, const __half* __restrict__ B,
              const float* __restrict__ bias, float* __restrict__ Cf,
              __half* __restrict__ Ch, int M, int N, int K)
{
    extern __shared__ char smem[];
    uint32_t sb = smem_u32(smem);
    int t = threadIdx.x, wid = t >> 5, lid = t & 31;
    int m0 = blockIdx.y * 128, n0 = blockIdx.x * 128;
    int wm = wid & 1, wn = wid >> 1;

    const __half* gp[2] = { A + (size_t)m0 * K, B + (size_t)n0 * K };

    const int lc = t & 7;
    const int lr = t >> 3;                  // 0..15
    const uint32_t wbase = (uint32_t)((lc ^ (lr & 7)) << 4) + lr * 128;

    float acc[4][8][4];
#pragma unroll
    for (int i = 0; i < 4; i++)
#pragma unroll
        for (int j = 0; j < 8; j++)
#pragma unroll
            for (int v = 0; v < 4; v++) acc[i][j][v] = 0.f;

    int nkt = K / 64;

#pragma unroll
    for (int s = 0; s < 2; s++) {
        uint32_t st = sb + s * STAGEB;
        int koff = s * 64;
#pragma unroll
        for (int mat = 0; mat < 2; mat++)
#pragma unroll
            for (int r8 = 0; r8 < 8; r8++)
                cp16(st + mat * GMATB + wbase + r8 * 16 * 128,
                     gp[mat] + (size_t)(lr + r8 * 16) * K + koff + lc * 8);
        CP_COMMIT();
    }

    const int arow = lid & 15, asel = lid >> 4;
    const int axor = arow & 7;
    const int browl = ((lid >> 4) & 1) * 8 + (lid & 7);
    const int bsel = (lid >> 3) & 1;
    const int bxor = browl & 7;

    int rd = 0, wr = 2;
    for (int kt = 0; kt < nkt; kt++) {
        CP_WAIT1();
        __syncthreads();

        uint32_t st = sb + rd * STAGEB;
        uint32_t aRow = st + (uint32_t)(wm * 64) * 128;
        uint32_t bRow = st + GMATB + (uint32_t)(wn * 64) * 128;

#pragma unroll
        for (int kb = 0; kb < 4; kb++) {
            uint32_t ah[4][4];
#pragma unroll
            for (int mt = 0; mt < 4; mt++)
                ldsm4(ah[mt], aRow + (uint32_t)(mt * 16 + arow) * 128
                              + (uint32_t)(((kb * 2 + asel) ^ axor) << 4));
#pragma unroll
            for (int p = 0; p < 4; p++) {
                uint32_t bh[4];
                ldsm4(bh, bRow + (uint32_t)(p * 16 + browl) * 128
                          + (uint32_t)(((kb * 2 + bsel) ^ bxor) << 4));
#pragma unroll
                for (int mt = 0; mt < 4; mt++) {
                    mma16816h(acc[mt][2 * p],     ah[mt], &bh[0]);
                    mma16816h(acc[mt][2 * p + 1], ah[mt], &bh[2]);
                }
            }
        }

        if (kt + 2 < nkt) {
            uint32_t st2 = sb + wr * STAGEB;
            int koff = (kt + 2) * 64;
#pragma unroll
            for (int mat = 0; mat < 2; mat++)
#pragma unroll
                for (int r8 = 0; r8 < 8; r8++)
                    cp16(st2 + mat * GMATB + wbase + r8 * 16 * 128,
                         gp[mat] + (size_t)(lr + r8 * 16) * K + koff + lc * 8);
        }
        CP_COMMIT();
        rd = (rd == 2) ? 0 : rd + 1;
        wr = (wr == 2) ? 0 : wr + 1;
    }

    int rA = m0 + wm * 64 + (lid >> 2);
    int cA = n0 + wn * 64 + 2 * (lid & 3);
#pragma unroll
    for (int mt = 0; mt < 4; mt++) {
        int r = rA + mt * 16;
#pragma unroll
        for (int nt = 0; nt < 8; nt++) {
            int c = cA + nt * 8;
            float b0 = bias[c], b1 = bias[c + 1];
            float v00 = acc[mt][nt][0] + b0, v01 = acc[mt][nt][1] + b1;
            float v10 = acc[mt][nt][2] + b0, v11 = acc[mt][nt][3] + b1;
            if (F16OUT) {
                *(uint32_t*)(Ch + (size_t)r * N + c)       = pack2h(v00, v01);
                *(uint32_t*)(Ch + (size_t)(r + 8) * N + c) = pack2h(v10, v11);
            } else {
                float2 w0 = {v00, v01}, w1 = {v10, v11};
                *(float2*)(Cf + (size_t)r * N + c)       = w0;
                *(float2*)(Cf + (size_t)(r + 8) * N + c) = w1;
            }
        }
    }
}

// ---------------------------------------------------------------------------
// fp16 single-pass causal flash attention. Per CTA: one (b,h), 128 q-rows,
// 8 warps x 16 rows, 64-token K tiles, 2-stage KV pipeline.
// S = Qh*Kh, O = Ph*Vh. XOR-swizzled 128B rows.
// SMEM: Q 16KB + 2 stages x 16KB = 48KB.
// ---------------------------------------------------------------------------
#define QMATB   16384
#define FMATB   8192
#define FSTAGE  (2 * FMATB)      // 16384 (K | V)
#define FSMEM   (QMATB + 2 * FSTAGE)  // 49152
#define SCALE_L2E 0.18033688011112042f

__global__ __launch_bounds__(256, 2)
void flash_mma(const __half* __restrict__ qkv, __half* __restrict__ attf)
{
    extern __shared__ char smem[];
    uint32_t sb = smem_u32(smem);
    int t = threadIdx.x, wid = t >> 5, lid = t & 31;
    int bh = blockIdx.x;
    int b = bh >> 4, hh = bh & 15;
    int qt = (int)gridDim.y - 1 - blockIdx.y;   // heavy tiles first
    int qbase = qt * 128;
    int tok0 = b * S_LEN;

    const uint32_t QH = sb;
    const uint32_t KV0 = sb + QMATB;

    const int qlrow  = t >> 1;
    const int qlcol0 = (t & 1) * 4;
    const int klrow  = t >> 2;        // 0..63
    const int klcol0 = (t & 3) * 2;
    const int klx = klrow & 7;

    // prologue: Q tile + KV stage 0
    {
        size_t rq = (size_t)(tok0 + qbase + qlrow) * E3 + hh * 64;
        int qx = qlrow & 7;
#pragma unroll
        for (int u = 0; u < 4; u++) {
            int ch = qlcol0 + u;
            cp16(QH + qlrow * 128 + ((ch ^ qx) << 4), qkv + rq + ch * 8);
        }
        size_t rk = (size_t)(tok0 + klrow) * E3 + 1024 + hh * 64;
#pragma unroll
        for (int u = 0; u < 2; u++) {
            int ch = klcol0 + u;
            uint32_t d = klrow * 128 + ((ch ^ klx) << 4);
            cp16(KV0 + d,         qkv + rk + ch * 8);          // K
            cp16(KV0 + FMATB + d, qkv + rk + 1024 + ch * 8);   // V
        }
    }
    CP_COMMIT();

    const int arow = lid & 15, asel = lid >> 4;
    const int qrow = wid * 16 + arow;
    const int qx = qrow & 7;
    const int browf = ((lid >> 4) & 1) * 8 + (lid & 7);
    const int bsel = (lid >> 3) & 1;
    const int vrowf = ((lid >> 3) & 1) * 8 + (lid & 7);
    const int vsel = (lid >> 4) & 1;

    uint32_t qh[4][4];
    float o[8][4];
#pragma unroll
    for (int n = 0; n < 8; n++)
#pragma unroll
        for (int v = 0; v < 4; v++) o[n][v] = 0.f;
    float m_lo = -CUDART_INF_F, m_hi = -CUDART_INF_F, l_lo = 0.f, l_hi = 0.f;

    const int rlo = lid >> 2;
    const int rloc = 16 * (wid & 3) + rlo;
    const int mycol0 = 2 * (lid & 3);
    const int kt_d = 2 * qt + (wid >> 2);
    const int ntiles = 2 * qt + 2;

    for (int kt = 0; kt < ntiles; kt++) {
        if (kt + 1 < ntiles) {
            uint32_t st = KV0 + ((kt + 1) & 1) * FSTAGE;
            size_t rk = (size_t)(tok0 + (kt + 1) * 64 + klrow) * E3 + 1024 + hh * 64;
#pragma unroll
            for (int u = 0; u < 2; u++) {
                int ch = klcol0 + u;
                uint32_t d = klrow * 128 + ((ch ^ klx) << 4);
                cp16(st + d,         qkv + rk + ch * 8);
                cp16(st + FMATB + d, qkv + rk + 1024 + ch * 8);
            }
        }
        CP_COMMIT();
        CP_WAIT1();
        __syncthreads();

        if (kt == 0) {   // persistent Q fragments
#pragma unroll
            for (int ks = 0; ks < 4; ks++)
                ldsm4(qh[ks], QH + qrow * 128 + (((ks * 2 + asel) ^ qx) << 4));
        }

        if (kt <= kt_d) {
            uint32_t st = KV0 + (kt & 1) * FSTAGE;

            // ---- S = Qh * Kh ----
            float s[8][4];
#pragma unroll
            for (int n = 0; n < 8; n++)
#pragma unroll
                for (int v = 0; v < 4; v++) s[n][v] = 0.f;

#pragma unroll
            for (int ks = 0; ks < 4; ks++) {
#pragma unroll
                for (int pp = 0; pp < 2; pp++) {
                    int p0 = pp * 2;
                    int rk0 = p0 * 16 + browf, rk1 = rk0 + 16;
                    uint32_t ka0 = st + rk0 * 128 + (((ks * 2 + bsel) ^ (rk0 & 7)) << 4);
                    uint32_t ka1 = st + rk1 * 128 + (((ks * 2 + bsel) ^ (rk1 & 7)) << 4);
                    uint32_t kh0[4], kh1[4];
                    ldsm4(kh0, ka0);
                    ldsm4(kh1, ka1);
                    mma16816h(s[2 * p0],     qh[ks], &kh0[0]);
                    mma16816h(s[2 * p0 + 1], qh[ks], &kh0[2]);
                    mma16816h(s[2 * p0 + 2], qh[ks], &kh1[0]);
                    mma16816h(s[2 * p0 + 3], qh[ks], &kh1[2]);
                }
            }

#pragma unroll
            for (int n = 0; n < 8; n++)
#pragma unroll
                for (int v = 0; v < 4; v++) s[n][v] *= SCALE_L2E;

            if (kt == kt_d) {
#pragma unroll
                for (int n = 0; n < 8; n++) {
                    int c0 = n * 8 + mycol0;
                    if (c0 > rloc)     s[n][0] = -CUDART_INF_F;
                    if (c0 + 1 > rloc) s[n][1] = -CUDART_INF_F;
                    if (c0 > rloc + 8)     s[n][2] = -CUDART_INF_F;
                    if (c0 + 1 > rloc + 8) s[n][3] = -CUDART_INF_F;
                }
            }

            // ---- online softmax ----
            float mt_lo = -CUDART_INF_F, mt_hi = -CUDART_INF_F;
#pragma unroll
            for (int n = 0; n < 8; n++) {
                mt_lo = fmaxf(mt_lo, fmaxf(s[n][0], s[n][1]));
                mt_hi = fmaxf(mt_hi, fmaxf(s[n][2], s[n][3]));
            }
            mt_lo = fmaxf(mt_lo, __shfl_xor_sync(0xffffffffu, mt_lo, 1));
            mt_lo = fmaxf(mt_lo, __shfl_xor_sync(0xffffffffu, mt_lo, 2));
            mt_hi = fmaxf(mt_hi, __shfl_xor_sync(0xffffffffu, mt_hi, 1));
            mt_hi = fmaxf(mt_hi, __shfl_xor_sync(0xffffffffu, mt_hi, 2));

            float mn_lo = fmaxf(m_lo, mt_lo), mn_hi = fmaxf(m_hi, mt_hi);
            float a_lo = exp2f(m_lo - mn_lo), a_hi = exp2f(m_hi - mn_hi);
            m_lo = mn_lo; m_hi = mn_hi;

            float rs_lo = 0.f, rs_hi = 0.f;
#pragma unroll
            for (int n = 0; n < 8; n++) {
                s[n][0] = exp2f(s[n][0] - mn_lo);
                s[n][1] = exp2f(s[n][1] - mn_lo);
                s[n][2] = exp2f(s[n][2] - mn_hi);
                s[n][3] = exp2f(s[n][3] - mn_hi);
                rs_lo += s[n][0] + s[n][1];
                rs_hi += s[n][2] + s[n][3];
            }
            rs_lo += __shfl_xor_sync(0xffffffffu, rs_lo, 1);
            rs_lo += __shfl_xor_sync(0xffffffffu, rs_lo, 2);
            rs_hi += __shfl_xor_sync(0xffffffffu, rs_hi, 1);
            rs_hi += __shfl_xor_sync(0xffffffffu, rs_hi, 2);
            l_lo = a_lo * l_lo + rs_lo;
            l_hi = a_hi * l_hi + rs_hi;
#pragma unroll
            for (int n = 0; n < 8; n++) {
                o[n][0] *= a_lo; o[n][1] *= a_lo;
                o[n][2] *= a_hi; o[n][3] *= a_hi;
            }

            // ---- O += Ph * Vh ----
            uint32_t vbase = st + FMATB;
#pragma unroll
            for (int ks = 0; ks < 4; ks++) {
                uint32_t ph[4];
                ph[0] = pack2h(s[2 * ks][0],     s[2 * ks][1]);
                ph[1] = pack2h(s[2 * ks][2],     s[2 * ks][3]);
                ph[2] = pack2h(s[2 * ks + 1][0], s[2 * ks + 1][1]);
                ph[3] = pack2h(s[2 * ks + 1][2], s[2 * ks + 1][3]);
                int rv = ks * 16 + vrowf;
                int vx = rv & 7;
#pragma unroll
                for (int pp = 0; pp < 2; pp++) {
                    int p0 = pp * 2;
                    uint32_t va0 = vbase + rv * 128 + (((p0 * 2 + vsel) ^ vx) << 4);
                    uint32_t va1 = vbase + rv * 128 + ((((p0 + 1) * 2 + vsel) ^ vx) << 4);
                    uint32_t vh0[4], vh1[4];
                    ldsm4t(vh0, va0);
                    ldsm4t(vh1, va1);
                    mma16816h(o[2 * p0],     ph, &vh0[0]);
                    mma16816h(o[2 * p0 + 1], ph, &vh0[2]);
                    mma16816h(o[2 * p0 + 2], ph, &vh1[0]);
                    mma16816h(o[2 * p0 + 3], ph, &vh1[2]);
                }
            }
        }
        __syncthreads();
    }

    // ---- epilogue: normalize, cast to fp16 ----
    float inv_lo = 1.f / l_lo, inv_hi = 1.f / l_hi;
    int tok_lo = tok0 + qbase + wid * 16 + rlo;
    int tok_hi = tok_lo + 8;
#pragma unroll
    for (int n = 0; n < 8; n++) {
        int c = hh * 64 + n * 8 + mycol0;
        *(uint32_t*)(attf + (size_t)tok_lo * N_EMBD + c) =
            pack2h(o[n][0] * inv_lo, o[n][1] * inv_lo);
        *(uint32_t*)(attf + (size_t)tok_hi * N_EMBD + c) =
            pack2h(o[n][2] * inv_hi, o[n][3] * inv_hi);
    }
}

// ---------------------------------------------------------------------------
extern "C" void kernel_launch(void* const* d_in, const int* in_sizes, int n_in,
                              void* d_out, int out_size)
{
    const float* x      = (const float*)d_in[0];
    const float* W_attn = (const float*)d_in[1];
    const float* b_attn = (const float*)d_in[2];
    const float* W_proj = (const float*)d_in[3];
    const float* b_proj = (const float*)d_in[4];
    float* out = (float*)d_out;

    __half *xf, *attf, *qkv, *wa, *wp;
    cudaGetSymbolAddress((void**)&xf, g_xf);
    cudaGetSymbolAddress((void**)&attf, g_attf);
    cudaGetSymbolAddress((void**)&qkv, g_qkv);
    cudaGetSymbolAddress((void**)&wa, g_wa);
    cudaGetSymbolAddress((void**)&wp, g_wp);

    cudaFuncSetAttribute(gemm_mma<true>,
                         cudaFuncAttributeMaxDynamicSharedMemorySize, GSMEM);
    cudaFuncSetAttribute(gemm_mma<false>,
                         cudaFuncAttributeMaxDynamicSharedMemorySize, GSMEM);
    cudaFuncSetAttribute(flash_mma,
                         cudaFuncAttributeMaxDynamicSharedMemorySize, FSMEM);

    // operand preparation
    cvt_f16<<<(M_ROWS * N_EMBD / 4 + 255) / 256, 256>>>(x, xf, M_ROWS * N_EMBD / 4);
    cvt_t_16<<<dim3(E3 / 32, N_EMBD / 32), dim3(32, 8)>>>(W_attn, wa, N_EMBD, E3);
    cvt_t_16<<<dim3(N_EMBD / 32, N_EMBD / 32), dim3(32, 8)>>>(W_proj, wp, N_EMBD, N_EMBD);

    // 1) QKV projection (single-pass fp16) -> fp16
    gemm_mma<true><<<dim3(E3 / 128, M_ROWS / 128), 128, GSMEM>>>(
        xf, wa, b_attn, nullptr, qkv, M_ROWS, E3, N_EMBD);

    // 2) fp16 single-pass causal flash attention -> fp16
    flash_mma<<<dim3(2 * N_HEADS, S_LEN / 128), 256, FSMEM>>>(qkv, attf);

    // 3) output projection (single-pass fp16) -> fp32
    gemm_mma<false><<<dim3(N_EMBD / 128, M_ROWS / 128), 128, GSMEM>>>(
        attf, wp, b_proj, out, nullptr, M_ROWS, N_EMBD, N_EMBD);
}